// round 12
// baseline (speedup 1.0000x reference)
#include <cuda_runtime.h>

#define TPB 256
#define T_SIG 64000
#define NSIG 64
#define NFFT 1024
#define HOP 256
#define NFRAMES 251
#define NFREQ 513
#define NMEL 80
#define CN 131072   // conv FFT length = 2^17 >= 2*T-1 (exact linear convolution)
#define CRS 144     // conv smem row stride; 144>>4=9 odd => g0 swizzle fixes transpose

// global accumulators (double):
// 0 mag, 1 cos, 2 mel, 3 dryL1, 4 rirL1, 5 sparsity, 6..9 e0..e3, 10 consist
__device__ double g_acc[12];
__device__ int    g_mel_i0[NFREQ];
__device__ float  g_mel_w0[NFREQ];
__device__ int    g_mel_i1[NFREQ];
__device__ float  g_mel_w1[NFREQ];
__device__ int4   g_mel_rng[NMEL];             // per-mel gather ranges
__device__ float2 g_tw1024[341];               // radix-4 twiddles, L=1024 (all stages)
__device__ float2 g_tw128[42];                 // radix-4 twiddles, L=128
__device__ __align__(16) float2 g_bufA[(size_t)NSIG * CN];   // 64 MB scratch
__device__ __align__(16) float2 g_bufB[(size_t)NSIG * CN];   // 64 MB scratch

// Streams/events for graph fork-join (created at program init, before the
// harness's memory checkpoints; NonBlocking so the legacy capture stream
// doesn't implicitly serialize them).
static cudaStream_t g_s1, g_s2;
static cudaEvent_t  g_eF, g_eJ1, g_eJ2;
static struct StreamInit {
    StreamInit() {
        cudaStreamCreateWithFlags(&g_s1, cudaStreamNonBlocking);
        cudaStreamCreateWithFlags(&g_s2, cudaStreamNonBlocking);
        cudaEventCreateWithFlags(&g_eF,  cudaEventDisableTiming);
        cudaEventCreateWithFlags(&g_eJ1, cudaEventDisableTiming);
        cudaEventCreateWithFlags(&g_eJ2, cudaEventDisableTiming);
    }
} g_stream_init;

// ---------------------------------------------------------------- utilities

__host__ __device__ constexpr int ilog2c(int n) { return n <= 1 ? 0 : 1 + ilog2c(n / 2); }

// Bank swizzle per buffer generation (bits [0:4) XOR-keyed from upper bits).
// g=0 fixes stage-0 write pattern (4bf+j) AND stride-144 transpose accesses;
// g=1 fixes stage-1 pattern (q | j<<2 | p<<4); g=2 identity.
__device__ __forceinline__ int swz(int a, int g) {
    if (g == 0) return a ^ ((a >> 4) & 0xF);
    if (g == 1) return a ^ ((a >> 2) & 0xC);
    return a;
}

__device__ __forceinline__ float block_reduce(float v, float* scr) {
    #pragma unroll
    for (int o = 16; o; o >>= 1) v += __shfl_down_sync(0xffffffffu, v, o);
    __syncthreads();
    if ((threadIdx.x & 31) == 0) scr[threadIdx.x >> 5] = v;
    __syncthreads();
    if (threadIdx.x < 32) {
        v = (threadIdx.x < (TPB / 32)) ? scr[threadIdx.x] : 0.f;
        #pragma unroll
        for (int o = 4; o; o >>= 1) v += __shfl_down_sync(0xffffffffu, v, o);
    }
    return v;  // valid on thread 0
}

// Mixed radix-4/2 Stockham DIF FFT over R rows of length L (power of 2) in
// shared memory, row stride RS (float2, 16-aligned). The caller writes the
// input through swz(.,GIN) and reads the natural-order result through
// swz(.,GOUT). SKIP=1: caller already performed radix-4 stage 0 (input must
// be in generation-0 layout). HALF=1: radix-2 tail stores only the low half
// (A+B) of each output pair.
template<int SIGN, int L, int R, int RS, int GIN, int GOUT, int SKIP = 0, int HALF = 0>
__device__ __forceinline__ float2* smem_fft4(float2* a, float2* b,
                                             const float2* __restrict__ tw) {
    constexpr int LOG2L = ilog2c(L);
    constexpr int NS4 = LOG2L >> 1;
    float2 *src = a, *dst = b;
    int ncur = L >> (2 * SKIP), logs = 2 * SKIP, toff = SKIP ? (L >> 2) : 0;
    #pragma unroll
    for (int s = SKIP; s < NS4; ++s) {
        const int rg = (s == 0) ? GIN : (s == 1) ? 0 : (s == 2) ? 1 : 2;
        const int wg = ((s == NS4 - 1) && !(LOG2L & 1)) ? GOUT
                       : (s == 0) ? 0 : (s == 1) ? 1 : 2;
        const int m = ncur >> 2;
        const int Ls = 1 << logs;
        constexpr int NB = R * (L >> 2);
        #pragma unroll
        for (int l = 0; l < NB / TPB; ++l) {
            const int it = threadIdx.x + TPB * l;
            const int row = it >> (LOG2L - 2);
            const int bf  = it & ((L >> 2) - 1);
            const int p = bf >> logs;
            const int q = bf - (p << logs);
            const int base = row * RS + q;
            float2 a0 = src[swz(base + p * Ls, rg)];
            float2 a1 = src[swz(base + (p + m) * Ls, rg)];
            float2 a2 = src[swz(base + (p + 2 * m) * Ls, rg)];
            float2 a3 = src[swz(base + (p + 3 * m) * Ls, rg)];
            float t0x = a0.x + a2.x, t0y = a0.y + a2.y;
            float t1x = a0.x - a2.x, t1y = a0.y - a2.y;
            float t2x = a1.x + a3.x, t2y = a1.y + a3.y;
            float t3x = a1.x - a3.x, t3y = a1.y - a3.y;
            float b0x = t0x + t2x, b0y = t0y + t2y;
            float b2x = t0x - t2x, b2y = t0y - t2y;
            float b1x, b1y, b3x, b3y;
            if (SIGN < 0) {           // b1 = t1 - i t3, b3 = t1 + i t3
                b1x = t1x + t3y; b1y = t1y - t3x;
                b3x = t1x - t3y; b3y = t1y + t3x;
            } else {                  // b1 = t1 + i t3, b3 = t1 - i t3
                b1x = t1x - t3y; b1y = t1y + t3x;
                b3x = t1x + t3y; b3y = t1y - t3x;
            }
            float2 w = __ldg(&tw[toff + p]);
            float c1 = w.x;
            float s1 = (SIGN < 0) ? -w.y : w.y;
            float c2 = c1 * c1 - s1 * s1, s2 = 2.f * c1 * s1;
            float c3 = c2 * c1 - s2 * s1, s3 = c2 * s1 + s2 * c1;
            const int ob = base + ((p << 2) << logs);
            dst[swz(ob, wg)]          = make_float2(b0x, b0y);
            dst[swz(ob + Ls, wg)]     = make_float2(b1x * c1 - b1y * s1, b1x * s1 + b1y * c1);
            dst[swz(ob + 2 * Ls, wg)] = make_float2(b2x * c2 - b2y * s2, b2x * s2 + b2y * c2);
            dst[swz(ob + 3 * Ls, wg)] = make_float2(b3x * c3 - b3y * s3, b3x * s3 + b3y * c3);
        }
        __syncthreads();
        float2* t = src; src = dst; dst = t;
        ncur >>= 2; logs += 2; toff += m;
    }
    if constexpr (LOG2L & 1) {        // final radix-2 stage (twiddle-free, p=0)
        const int rg = (NS4 == 1) ? 0 : (NS4 == 2) ? 1 : 2;
        constexpr int Ls = L >> 1;
        constexpr int NB = R * (L >> 1);
        #pragma unroll
        for (int l = 0; l < NB / TPB; ++l) {
            const int it = threadIdx.x + TPB * l;
            const int row = it >> (LOG2L - 1);
            const int q   = it & ((L >> 1) - 1);
            const int base = row * RS + q;
            float2 A = src[swz(base, rg)];
            float2 B = src[swz(base + Ls, rg)];
            dst[swz(base, GOUT)]      = make_float2(A.x + B.x, A.y + B.y);
            if constexpr (!HALF)
                dst[swz(base + Ls, GOUT)] = make_float2(A.x - B.x, A.y - B.y);
        }
        __syncthreads();
        float2* t = src; src = dst; dst = t;
    }
    return src;
}

// Hermitian unpack of two packed spectra (dry real, rir imag) + complex
// product, producing packed product pair Q1 (at p1) / Q2 (at p2=conj pos).
__device__ __forceinline__ void packprod(float2 A1, float2 A2, float2 B1, float2 B2,
                                         float2& Q1, float2& Q2) {
    float Dar = 0.5f * (A1.x + A2.x), Dai = 0.5f * (A1.y - A2.y);
    float Rar = 0.5f * (A1.y + A2.y), Rai = 0.5f * (A2.x - A1.x);
    float Par = Dar * Rar - Dai * Rai, Pai = Dar * Rai + Dai * Rar;
    float Dbr = 0.5f * (B1.x + B2.x), Dbi = 0.5f * (B1.y - B2.y);
    float Rbr = 0.5f * (B1.y + B2.y), Rbi = 0.5f * (B2.x - B1.x);
    float Pbr = Dbr * Rbr - Dbi * Rbi, Pbi = Dbr * Rbi + Dbi * Rbr;
    Q1 = make_float2(Par - Pbi, Pai + Pbr);   // Pa + i*Pb
    Q2 = make_float2(Par + Pbi, Pbr - Pai);   // conj(Pa) + i*conj(Pb)
}

// ---------------------------------------------------------------- init

__global__ void init_kernel() {
    int t = blockIdx.x * blockDim.x + threadIdx.x;
    if (t < 12) g_acc[t] = 0.0;
    if (t < 341) {                                // L=1024 twiddles (all 5 stages)
        int ncur = 1024, p = t;
        while (p >= (ncur >> 2)) { p -= (ncur >> 2); ncur >>= 2; }
        double ang = 6.283185307179586476925286766559 * (double)p / (double)ncur;
        g_tw1024[t] = make_float2((float)cos(ang), (float)sin(ang));
    }
    if (t < 42) {                                 // L=128 twiddles (3 radix-4 stages)
        int ncur = 128, p = t;
        while (p >= (ncur >> 2)) { p -= (ncur >> 2); ncur >>= 2; }
        double ang = 6.283185307179586476925286766559 * (double)p / (double)ncur;
        g_tw128[t] = make_float2((float)cos(ang), (float)sin(ang));
    }
    if (t < NFREQ) {
        double freq   = (double)t * (8000.0 / 512.0);
        double melmax = 2595.0 * log10(1.0 + 8000.0 / 700.0);
        double mstep  = melmax / 81.0;
        double mval   = 2595.0 * log10(1.0 + freq / 700.0);
        int i = (int)floor(mval / mstep);
        if (i < 0) i = 0;
        if (i > 81) i = 81;
        double f_lo = 700.0 * (pow(10.0, ((double)i * mstep) / 2595.0) - 1.0);
        double f_hi = 700.0 * (pow(10.0, ((double)(i + 1) * mstep) / 2595.0) - 1.0);
        double inv  = 1.0 / (f_hi - f_lo);
        int i0 = -1, i1 = -1; float w0 = 0.f, w1 = 0.f;
        if (i <= 79)           { i0 = i;     w0 = (float)fmax(0.0, (freq - f_lo) * inv); }
        if (i >= 1 && i <= 80) { i1 = i - 1; w1 = (float)fmax(0.0, (f_hi - freq) * inv); }
        g_mel_i0[t] = i0; g_mel_w0[t] = w0;
        g_mel_i1[t] = i1; g_mel_w1[t] = w1;
    }
}

// Second init pass: per-mel contiguous gather ranges (i0[k], i1[k] are
// monotone in k, so each mel's membership is a contiguous bin range).
__global__ void init2_kernel() {
    int m = threadIdx.x;
    if (m >= NMEL) return;
    int s0 = NFREQ, e0 = 0, s1 = NFREQ, e1 = 0;
    for (int k = 0; k < NFREQ; ++k) {
        if (g_mel_i0[k] == m) { if (k < s0) s0 = k; if (k + 1 > e0) e0 = k + 1; }
        if (g_mel_i1[k] == m) { if (k < s1) s1 = k; if (k + 1 > e1) e1 = k + 1; }
    }
    g_mel_rng[m] = make_int4(s0, e0, s1, e1);
}

// ---------------------------------------------------------------- STFT losses
// One block per (signal, frame). pred packed as real, target as imag in one
// complex FFT; Hermitian unpack recovers both spectra. Per-bin powers are
// cached in the free FFT smem buffer; mel reduction is a per-mel GATHER over
// contiguous bin ranges (no shared atomics).

__global__ __launch_bounds__(TPB, 5) void stft_loss_kernel(const float* __restrict__ pd,
                                                           const float* __restrict__ td) {
    __shared__ float2 sA[NFFT], sB[NFFT];
    __shared__ float s_mel;
    __shared__ float scr[8];
    int blk = blockIdx.x;
    int sig = blk / NFRAMES;
    int frame = blk - sig * NFRAMES;
    const float* p = pd + (size_t)sig * T_SIG;
    const float* q = td + (size_t)sig * T_SIG;
    int tid = threadIdx.x;

    for (int j = tid; j < NFFT; j += TPB) {
        int t0 = frame * HOP - 512 + j;            // reflect padding (center=True)
        if (t0 < 0) t0 = -t0;
        else if (t0 >= T_SIG) t0 = 2 * T_SIG - 2 - t0;
        float w = 0.5f - 0.5f * cospif((float)j * (1.0f / 512.0f));  // hann periodic
        sA[j] = make_float2(p[t0] * w, q[t0] * w);
    }
    if (tid == 0) s_mel = 0.f;
    __syncthreads();

    // L=1024 has 5 radix-4 stages (odd count) -> result lands in sB; sA free.
    float2* res = smem_fft4<-1, NFFT, 1, 0, 2, 2>(sA, sB, g_tw1024);

    const float SCL2 = 0.0026041666666666665f;     // 1/(sum hann^2) = 1/384
    float magacc = 0.f, cosacc = 0.f;
    for (int k = tid; k < NFREQ; k += TPB) {
        float2 Xk = res[k];
        float2 Xm = res[(NFFT - k) & (NFFT - 1)];
        float Pr = 0.5f * (Xk.x + Xm.x);
        float Pi = 0.5f * (Xk.y - Xm.y);
        float Tr = 0.5f * (Xk.y + Xm.y);
        float Ti = 0.5f * (Xm.x - Xk.x);
        float pp = (Pr * Pr + Pi * Pi) * SCL2;
        float tp = (Tr * Tr + Ti * Ti) * SCL2;
        magacc += fabsf(sqrtf(pp) - sqrtf(tp));
        float dot = (Pr * Tr + Pi * Ti) * SCL2;
        cosacc += dot * rsqrtf(fmaxf(pp * tp, 1e-36f));  // cos(dphi)
        sA[k] = make_float2(pp, tp);               // cache powers for mel gather
    }
    __syncthreads();
    if (tid < NMEL) {                              // gather: one mel per thread
        int4 r = g_mel_rng[tid];
        float mp_ = 0.f, mt_ = 0.f;
        for (int k = r.x; k < r.y; ++k) {
            float w = g_mel_w0[k]; float2 v = sA[k];
            mp_ += v.x * w; mt_ += v.y * w;
        }
        for (int k = r.z; k < r.w; ++k) {
            float w = g_mel_w1[k]; float2 v = sA[k];
            mp_ += v.x * w; mt_ += v.y * w;
        }
        float d = fabsf(logf(mp_ + 1e-8f) - logf(mt_ + 1e-8f));
        atomicAdd(&s_mel, d);
    }
    float bm = block_reduce(magacc, scr);
    float bc = block_reduce(cosacc, scr);
    if (tid == 0) {
        atomicAdd(&g_acc[0], (double)bm);
        atomicAdd(&g_acc[1], (double)bc);
        atomicAdd(&g_acc[2], (double)s_mel);
    }
}

// ---------------------------------------------------------------- time-domain

__global__ __launch_bounds__(TPB) void time_loss_kernel(const float4* __restrict__ pd,
                                                        const float4* __restrict__ pr,
                                                        const float4* __restrict__ td,
                                                        const float4* __restrict__ tr) {
    __shared__ float segsum[4];
    __shared__ float scr[8];
    if (threadIdx.x < 4) segsum[threadIdx.x] = 0.f;
    __syncthreads();
    float dry = 0.f, rir = 0.f, spa = 0.f;
    const int N4 = (NSIG * T_SIG) / 4;             // 1,024,000
    int stride = gridDim.x * TPB;
    for (int i = blockIdx.x * TPB + threadIdx.x; i < N4; i += stride) {
        float4 a = pd[i], b = td[i], c = pr[i], d = tr[i];
        dry += fabsf(a.x-b.x) + fabsf(a.y-b.y) + fabsf(a.z-b.z) + fabsf(a.w-b.w);
        rir += fabsf(c.x-d.x) + fabsf(c.y-d.y) + fabsf(c.z-d.z) + fabsf(c.w-d.w);
        spa += fabsf(c.x) + fabsf(c.y) + fabsf(c.z) + fabsf(c.w);
        float sq = c.x*c.x + c.y*c.y + c.z*c.z + c.w*c.w;
        #pragma unroll
        for (int o = 16; o; o >>= 1) sq += __shfl_down_sync(0xffffffffu, sq, o);
        if ((threadIdx.x & 31) == 0) {
            int t0 = (i * 4) % T_SIG;              // warp-uniform segment
            atomicAdd(&segsum[t0 / 16000], sq);
        }
    }
    float bd = block_reduce(dry, scr);
    float br = block_reduce(rir, scr);
    float bs = block_reduce(spa, scr);
    __syncthreads();
    if (threadIdx.x == 0) {
        atomicAdd(&g_acc[3], (double)bd);
        atomicAdd(&g_acc[4], (double)br);
        atomicAdd(&g_acc[5], (double)bs);
    }
    if (threadIdx.x < 4) atomicAdd(&g_acc[6 + threadIdx.x], (double)segsum[threadIdx.x]);
}

// ---------------------------------------------------------------- consistency
// 2^17-pt four-step FFT. n = n1 + 1024*n2, k = k2 + 128*k1. Spectra stored
// permuted at p = k2*1024 + k1. dry packed as real, rir as imag (forward);
// two Hermitian product spectra packed per inverse FFT.

// Column FFT with radix-4 stage 0 fused into the global load: the upper half
// of every column (n2 >= 63) is structurally zero (n >= T_SIG), so stage 0
// degenerates to a0 +/- a1 and a0 -/+ i*a1 with only two loads. Output store
// vectorized to float4 (2 consecutive n1 per thread); the paired transposed
// smem reads stay conflict-free under the g0 swizzle.
__global__ __launch_bounds__(TPB, 6) void conv_fwdA(const float* __restrict__ dry,
                                                    const float* __restrict__ rir) {
    __shared__ __align__(16) float2 sA[16 * CRS], sB[16 * CRS];
    int n1_0 = blockIdx.x * 16;
    int sig  = blockIdx.y;
    const float* d = dry + (size_t)sig * T_SIG;
    const float* r = rir + (size_t)sig * T_SIG;
    #pragma unroll
    for (int l = 0; l < 2; ++l) {                 // 512 stage-0 butterflies
        int idx = threadIdx.x + TPB * l;
        int n1l = idx & 15, p = idx >> 4;          // p in [0,32)
        int n1 = n1_0 + n1l;
        float2 a0 = make_float2(d[n1 + (p << 10)], r[n1 + (p << 10)]);
        int nb = n1 + ((p + 32) << 10);
        float2 a1 = make_float2(0.f, 0.f);
        if (nb < T_SIG) { a1.x = d[nb]; a1.y = r[nb]; }
        // SIGN=-1 stage 0 with a2=a3=0
        float b0x = a0.x + a1.x, b0y = a0.y + a1.y;
        float b2x = a0.x - a1.x, b2y = a0.y - a1.y;
        float b1x = a0.x + a1.y, b1y = a0.y - a1.x;   // a0 - i a1
        float b3x = a0.x - a1.y, b3y = a0.y + a1.x;   // a0 + i a1
        float2 w = __ldg(&g_tw128[p]);
        float c1 = w.x, s1 = -w.y;
        float c2 = c1 * c1 - s1 * s1, s2 = 2.f * c1 * s1;
        float c3 = c2 * c1 - s2 * s1, s3 = c2 * s1 + s2 * c1;
        int ob = n1l * CRS + (p << 2);
        sA[swz(ob, 0)]     = make_float2(b0x, b0y);
        sA[swz(ob + 1, 0)] = make_float2(b1x * c1 - b1y * s1, b1x * s1 + b1y * c1);
        sA[swz(ob + 2, 0)] = make_float2(b2x * c2 - b2y * s2, b2x * s2 + b2y * c2);
        sA[swz(ob + 3, 0)] = make_float2(b3x * c3 - b3y * s3, b3x * s3 + b3y * c3);
    }
    __syncthreads();
    float2* res = smem_fft4<-1, 128, 16, CRS, 0, 0, 1>(sA, sB, g_tw128);
    float4* out4 = (float4*)(g_bufA + (size_t)sig * CN);
    #pragma unroll
    for (int l = 0; l < 4; ++l) {                  // 1024 float4 stores total
        int idx = threadIdx.x + TPB * l;
        int n1h = idx & 7, k2 = idx >> 3;
        int n1a = n1_0 + 2 * n1h;
        float2 y0 = res[swz((2 * n1h) * CRS + k2, 0)];
        float2 y1 = res[swz((2 * n1h + 1) * CRS + k2, 0)];
        float c0, s0, c1, s1;
        __sincosf(-(6.2831853071795864f / 131072.0f) * (float)(n1a * k2), &s0, &c0);
        __sincosf(-(6.2831853071795864f / 131072.0f) * (float)((n1a + 1) * k2), &s1, &c1);
        out4[(k2 << 9) + ((n1_0 >> 1) + n1h)] =
            make_float4(y0.x * c0 - y0.y * s0, y0.x * s0 + y0.y * c0,
                        y1.x * c1 - y1.y * s1, y1.x * s1 + y1.y * c1);
    }
}

// Fused: forward 1024-pt row FFTs (4 rows) + Hermitian pointwise product
// (packed pairs) + inverse 1024-pt row FFTs + inter-pass twiddle.
// Block x handles conjugate row pair (r0, r1); x==0 handles the self-paired
// rows 0 and 64. y = product-pair index (signals 2y, 2y+1 -> Pa + i*Pb).
// Global loads/stores are float4-vectorized.
__global__ __launch_bounds__(TPB) void conv_prodrow_inv1() {
    __shared__ __align__(16) float2 S[6144];
    int x = blockIdx.x, pr = blockIdx.y;
    int r0 = x;
    int r1 = x ? (128 - x) : 64;
    const float2* Xa = g_bufA + (size_t)(2 * pr) * CN;
    const float2* Xb = Xa + CN;
    int tid = threadIdx.x;
    {
        const float4* Xa0 = (const float4*)(Xa + r0 * 1024);
        const float4* Xa1 = (const float4*)(Xa + r1 * 1024);
        const float4* Xb0 = (const float4*)(Xb + r0 * 1024);
        const float4* Xb1 = (const float4*)(Xb + r1 * 1024);
        float4* S4 = (float4*)S;
        #pragma unroll
        for (int l = 0; l < 2; ++l) {
            int i = tid + TPB * l;                 // 0..511 float4 per row
            S4[i]        = Xa0[i];
            S4[512 + i]  = Xa1[i];
            S4[1024 + i] = Xb0[i];
            S4[1536 + i] = Xb1[i];
        }
    }
    __syncthreads();
    float2* aF = smem_fft4<-1, 1024, 2, 1024, 2, 2>(S, S + 4096, g_tw1024);       // = S+4096
    float2* bF = smem_fft4<-1, 1024, 2, 1024, 2, 2>(S + 2048, S, g_tw1024);       // = S
    float2* P = S + 2048;
    if (x) {
        // cross pair: (r0, k1) <-> (r1, 1023-k1)
        #pragma unroll
        for (int l = 0; l < 4; ++l) {
            int k1 = tid + TPB * l;
            int jm = 1023 - k1;
            float2 Q1, Q2;
            packprod(aF[k1], aF[1024 + jm], bF[k1], bF[1024 + jm], Q1, Q2);
            P[k1] = Q1;
            P[1024 + jm] = Q2;
        }
    } else {
        // row 0: self pairs (k1, (1024-k1)&1023), k1 in [0,512]
        // row 64: self pairs (k1, 1023-k1), k1 in [0,511]
        #pragma unroll
        for (int l = 0; l < 4; ++l) {
            int k1 = tid + TPB * l;
            if (k1 <= 512) {
                int jm = (1024 - k1) & 1023;
                float2 Q1, Q2;
                packprod(aF[k1], aF[jm], bF[k1], bF[jm], Q1, Q2);
                P[k1] = Q1; P[jm] = Q2;
            }
            if (k1 < 512) {
                int jm = 1023 - k1;
                float2 Q1, Q2;
                packprod(aF[1024 + k1], aF[1024 + jm], bF[1024 + k1], bF[1024 + jm], Q1, Q2);
                P[1024 + k1] = Q1; P[1024 + jm] = Q2;
            }
        }
    }
    __syncthreads();
    float2* res = smem_fft4<1, 1024, 2, 1024, 2, 2>(S + 2048, S, g_tw1024);       // = S
    float4* out4 = (float4*)(g_bufB + (size_t)pr * CN);
    const float4* res4 = (const float4*)res;
    #pragma unroll
    for (int l = 0; l < 4; ++l) {                  // 1024 float4 stores total
        int idx = tid + TPB * l;                   // 0..1023
        int row = idx >> 9;
        int jp = idx & 511;                        // n1 pair index
        int n1 = jp << 1;
        int k2v = row ? r1 : r0;
        float4 v = res4[(row << 9) + jp];
        float c0, s0, c1, s1;
        __sincosf((6.2831853071795864f / 131072.0f) * (float)(n1 * k2v), &s0, &c0);
        __sincosf((6.2831853071795864f / 131072.0f) * (float)((n1 + 1) * k2v), &s1, &c1);
        out4[(k2v << 9) + jp] =
            make_float4(v.x * c0 - v.y * s0, v.x * s0 + v.y * c0,
                        v.z * c1 - v.w * s1, v.z * s1 + v.w * c1);
    }
}

__global__ __launch_bounds__(TPB, 6) void conv_inv2(const float* __restrict__ mix) {
    __shared__ __align__(16) float2 sA[16 * CRS], sB[16 * CRS];
    __shared__ float scr[8];
    int n1_0 = blockIdx.x * 16;
    int pr   = blockIdx.y;
    const float4* inb4 = (const float4*)(g_bufB + (size_t)pr * CN);
    #pragma unroll
    for (int l = 0; l < 4; ++l) {                  // 1024 float4 loads total
        int idx = threadIdx.x + TPB * l;
        int n1h = idx & 7, k2 = idx >> 3;
        float4 v = inb4[(k2 << 9) + ((n1_0 >> 1) + n1h)];
        sA[swz((2 * n1h) * CRS + k2, 0)]     = make_float2(v.x, v.y);
        sA[swz((2 * n1h + 1) * CRS + k2, 0)] = make_float2(v.z, v.w);
    }
    __syncthreads();
    // HALF=1: only the low half of each inverse column is needed (n2 <= 62).
    float2* res = smem_fft4<1, 128, 16, CRS, 0, 0, 0, 1>(sA, sB, g_tw128);
    const float* ma = mix + (size_t)(2 * pr) * T_SIG;
    const float* mb = ma + T_SIG;
    float acc = 0.f;
    const float INVN = 1.0f / 131072.0f;
    #pragma unroll
    for (int l = 0; l < 8; ++l) {
        int idx = threadIdx.x + TPB * l;
        int n1l = idx & 15, n2 = idx >> 4;
        int n = n1_0 + n1l + (n2 << 10);
        if (n < T_SIG) {
            float2 v = res[swz(n1l * CRS + n2, 0)];
            acc += fabsf(v.x * INVN - ma[n]) + fabsf(v.y * INVN - mb[n]);
        }
    }
    float b = block_reduce(acc, scr);
    if (threadIdx.x == 0) atomicAdd(&g_acc[10], (double)b);
}

// ---------------------------------------------------------------- finalize

__global__ void finalize_kernel(float* out) {
    const double NT   = 4096000.0;                 // 64 * 64000
    const double CNT  = 64.0 * 513.0 * 251.0;
    const double MELC = 64.0 * 80.0 * 251.0;
    const double SEGC = 1024000.0;                 // 64 * 16000
    double dry_time = g_acc[3] / NT;
    double mag   = g_acc[0] / CNT;
    double phase = 1.0 - g_acc[1] / CNT;
    double freqL = mag + 0.1 * phase;
    double mel   = g_acc[2] / MELC;
    double total_dry = dry_time + 0.5 * freqL + 0.3 * mel;
    double rir_time = g_acc[4] / NT;
    double spars    = g_acc[5] / NT;
    double e0 = g_acc[6] / SEGC, e1 = g_acc[7] / SEGC;
    double e2 = g_acc[8] / SEGC, e3 = g_acc[9] / SEGC;
    double decay = fmax(0.0, e1 - 0.8 * e0) + fmax(0.0, e2 - 0.8 * e1)
                 + fmax(0.0, e3 - 0.8 * e2);
    double total_rir = rir_time + 0.1 * (spars + decay);
    double consist = g_acc[10] / NT;
    out[0] = (float)(3.0 * total_dry + total_rir + 0.2 * consist);
}

// ---------------------------------------------------------------- launch
// Graph fork-join: after init, three independent branches run concurrently —
// stft (s1), time_loss (s2), conv chain (capture stream) — joined via events
// before finalize.

extern "C" void kernel_launch(void* const* d_in, const int* in_sizes, int n_in,
                              void* d_out, int out_size) {
    const float* pd  = (const float*)d_in[0];   // pred_dry
    const float* pr  = (const float*)d_in[1];   // pred_rir
    const float* td  = (const float*)d_in[2];   // target_dry
    const float* tr  = (const float*)d_in[3];   // target_rir
    const float* mix = (const float*)d_in[4];   // mix
    float* out = (float*)d_out;

    init_kernel<<<3, TPB>>>();
    init2_kernel<<<1, 128>>>();

    cudaEventRecord(g_eF, 0);
    cudaStreamWaitEvent(g_s1, g_eF, 0);
    cudaStreamWaitEvent(g_s2, g_eF, 0);

    stft_loss_kernel<<<NSIG * NFRAMES, TPB, 0, g_s1>>>(pd, td);
    time_loss_kernel<<<1024, TPB, 0, g_s2>>>((const float4*)pd, (const float4*)pr,
                                             (const float4*)td, (const float4*)tr);
    conv_fwdA<<<dim3(64, NSIG), TPB>>>(pd, pr);
    conv_prodrow_inv1<<<dim3(64, 32), TPB>>>();
    conv_inv2<<<dim3(64, 32), TPB>>>(mix);

    cudaEventRecord(g_eJ1, g_s1);
    cudaEventRecord(g_eJ2, g_s2);
    cudaStreamWaitEvent(0, g_eJ1, 0);
    cudaStreamWaitEvent(0, g_eJ2, 0);

    finalize_kernel<<<1, 1>>>(out);
}

// round 13
// speedup vs baseline: 1.0810x; 1.0810x over previous
#include <cuda_runtime.h>

#define TPB 256
#define T_SIG 64000
#define NSIG 64
#define NFFT 1024
#define HOP 256
#define NFRAMES 251
#define NPAIR 126   // ceil(NFRAMES/2) frame pairs per signal
#define NFREQ 513
#define NMEL 80
#define CN 131072   // conv FFT length = 2^17 >= 2*T-1 (exact linear convolution)
#define CRS 144     // conv smem row stride; 144>>4=9 odd => g0 swizzle fixes transpose

// global accumulators (double):
// 0 mag, 1 cos, 2 mel, 3 dryL1, 4 rirL1, 5 sparsity, 6..9 e0..e3, 10 consist
__device__ double g_acc[12];
__device__ int    g_mel_i0[NFREQ];
__device__ float  g_mel_w0[NFREQ];
__device__ int    g_mel_i1[NFREQ];
__device__ float  g_mel_w1[NFREQ];
__device__ int4   g_mel_rng[NMEL];             // per-mel gather ranges
__device__ float2 g_tw1024[341];               // radix-4 twiddles, L=1024 (all stages)
__device__ float2 g_tw128[42];                 // radix-4 twiddles, L=128
__device__ __align__(16) float2 g_bufA[(size_t)NSIG * CN];   // 64 MB scratch
__device__ __align__(16) float2 g_bufB[(size_t)NSIG * CN];   // 64 MB scratch

// Streams/events for graph fork-join (created at program init, before the
// harness's memory checkpoints; NonBlocking so the legacy capture stream
// doesn't implicitly serialize them).
static cudaStream_t g_s1, g_s2;
static cudaEvent_t  g_eF, g_eJ1, g_eJ2;
static struct StreamInit {
    StreamInit() {
        cudaStreamCreateWithFlags(&g_s1, cudaStreamNonBlocking);
        cudaStreamCreateWithFlags(&g_s2, cudaStreamNonBlocking);
        cudaEventCreateWithFlags(&g_eF,  cudaEventDisableTiming);
        cudaEventCreateWithFlags(&g_eJ1, cudaEventDisableTiming);
        cudaEventCreateWithFlags(&g_eJ2, cudaEventDisableTiming);
    }
} g_stream_init;

// ---------------------------------------------------------------- utilities

__host__ __device__ constexpr int ilog2c(int n) { return n <= 1 ? 0 : 1 + ilog2c(n / 2); }

// Bank swizzle per buffer generation (bits [0:4) XOR-keyed from upper bits).
// g=0 fixes stage-0 write pattern (4bf+j) AND stride-144 transpose accesses;
// g=1 fixes stage-1 pattern (q | j<<2 | p<<4); g=2 identity.
__device__ __forceinline__ int swz(int a, int g) {
    if (g == 0) return a ^ ((a >> 4) & 0xF);
    if (g == 1) return a ^ ((a >> 2) & 0xC);
    return a;
}

__device__ __forceinline__ float block_reduce(float v, float* scr) {
    #pragma unroll
    for (int o = 16; o; o >>= 1) v += __shfl_down_sync(0xffffffffu, v, o);
    __syncthreads();
    if ((threadIdx.x & 31) == 0) scr[threadIdx.x >> 5] = v;
    __syncthreads();
    if (threadIdx.x < 32) {
        v = (threadIdx.x < (TPB / 32)) ? scr[threadIdx.x] : 0.f;
        #pragma unroll
        for (int o = 4; o; o >>= 1) v += __shfl_down_sync(0xffffffffu, v, o);
    }
    return v;  // valid on thread 0
}

// Mixed radix-4/2 Stockham DIF FFT over R rows of length L (power of 2) in
// shared memory, row stride RS (float2, 16-aligned). The caller writes the
// input through swz(.,GIN) and reads the natural-order result through
// swz(.,GOUT). SKIP=1: caller already performed radix-4 stage 0 (input must
// be in generation-0 layout). HALF=1: radix-2 tail stores only the low half
// (A+B) of each output pair.
template<int SIGN, int L, int R, int RS, int GIN, int GOUT, int SKIP = 0, int HALF = 0>
__device__ __forceinline__ float2* smem_fft4(float2* a, float2* b,
                                             const float2* __restrict__ tw) {
    constexpr int LOG2L = ilog2c(L);
    constexpr int NS4 = LOG2L >> 1;
    float2 *src = a, *dst = b;
    int ncur = L >> (2 * SKIP), logs = 2 * SKIP, toff = SKIP ? (L >> 2) : 0;
    #pragma unroll
    for (int s = SKIP; s < NS4; ++s) {
        const int rg = (s == 0) ? GIN : (s == 1) ? 0 : (s == 2) ? 1 : 2;
        const int wg = ((s == NS4 - 1) && !(LOG2L & 1)) ? GOUT
                       : (s == 0) ? 0 : (s == 1) ? 1 : 2;
        const int m = ncur >> 2;
        const int Ls = 1 << logs;
        constexpr int NB = R * (L >> 2);
        #pragma unroll
        for (int l = 0; l < NB / TPB; ++l) {
            const int it = threadIdx.x + TPB * l;
            const int row = it >> (LOG2L - 2);
            const int bf  = it & ((L >> 2) - 1);
            const int p = bf >> logs;
            const int q = bf - (p << logs);
            const int base = row * RS + q;
            float2 a0 = src[swz(base + p * Ls, rg)];
            float2 a1 = src[swz(base + (p + m) * Ls, rg)];
            float2 a2 = src[swz(base + (p + 2 * m) * Ls, rg)];
            float2 a3 = src[swz(base + (p + 3 * m) * Ls, rg)];
            float t0x = a0.x + a2.x, t0y = a0.y + a2.y;
            float t1x = a0.x - a2.x, t1y = a0.y - a2.y;
            float t2x = a1.x + a3.x, t2y = a1.y + a3.y;
            float t3x = a1.x - a3.x, t3y = a1.y - a3.y;
            float b0x = t0x + t2x, b0y = t0y + t2y;
            float b2x = t0x - t2x, b2y = t0y - t2y;
            float b1x, b1y, b3x, b3y;
            if (SIGN < 0) {           // b1 = t1 - i t3, b3 = t1 + i t3
                b1x = t1x + t3y; b1y = t1y - t3x;
                b3x = t1x - t3y; b3y = t1y + t3x;
            } else {                  // b1 = t1 + i t3, b3 = t1 - i t3
                b1x = t1x - t3y; b1y = t1y + t3x;
                b3x = t1x + t3y; b3y = t1y - t3x;
            }
            float2 w = __ldg(&tw[toff + p]);
            float c1 = w.x;
            float s1 = (SIGN < 0) ? -w.y : w.y;
            float c2 = c1 * c1 - s1 * s1, s2 = 2.f * c1 * s1;
            float c3 = c2 * c1 - s2 * s1, s3 = c2 * s1 + s2 * c1;
            const int ob = base + ((p << 2) << logs);
            dst[swz(ob, wg)]          = make_float2(b0x, b0y);
            dst[swz(ob + Ls, wg)]     = make_float2(b1x * c1 - b1y * s1, b1x * s1 + b1y * c1);
            dst[swz(ob + 2 * Ls, wg)] = make_float2(b2x * c2 - b2y * s2, b2x * s2 + b2y * c2);
            dst[swz(ob + 3 * Ls, wg)] = make_float2(b3x * c3 - b3y * s3, b3x * s3 + b3y * c3);
        }
        __syncthreads();
        float2* t = src; src = dst; dst = t;
        ncur >>= 2; logs += 2; toff += m;
    }
    if constexpr (LOG2L & 1) {        // final radix-2 stage (twiddle-free, p=0)
        const int rg = (NS4 == 1) ? 0 : (NS4 == 2) ? 1 : 2;
        constexpr int Ls = L >> 1;
        constexpr int NB = R * (L >> 1);
        #pragma unroll
        for (int l = 0; l < NB / TPB; ++l) {
            const int it = threadIdx.x + TPB * l;
            const int row = it >> (LOG2L - 1);
            const int q   = it & ((L >> 1) - 1);
            const int base = row * RS + q;
            float2 A = src[swz(base, rg)];
            float2 B = src[swz(base + Ls, rg)];
            dst[swz(base, GOUT)]      = make_float2(A.x + B.x, A.y + B.y);
            if constexpr (!HALF)
                dst[swz(base + Ls, GOUT)] = make_float2(A.x - B.x, A.y - B.y);
        }
        __syncthreads();
        float2* t = src; src = dst; dst = t;
    }
    return src;
}

// Hermitian unpack of two packed spectra (dry real, rir imag) + complex
// product, producing packed product pair Q1 (at p1) / Q2 (at p2=conj pos).
__device__ __forceinline__ void packprod(float2 A1, float2 A2, float2 B1, float2 B2,
                                         float2& Q1, float2& Q2) {
    float Dar = 0.5f * (A1.x + A2.x), Dai = 0.5f * (A1.y - A2.y);
    float Rar = 0.5f * (A1.y + A2.y), Rai = 0.5f * (A2.x - A1.x);
    float Par = Dar * Rar - Dai * Rai, Pai = Dar * Rai + Dai * Rar;
    float Dbr = 0.5f * (B1.x + B2.x), Dbi = 0.5f * (B1.y - B2.y);
    float Rbr = 0.5f * (B1.y + B2.y), Rbi = 0.5f * (B2.x - B1.x);
    float Pbr = Dbr * Rbr - Dbi * Rbi, Pbi = Dbr * Rbi + Dbi * Rbr;
    Q1 = make_float2(Par - Pbi, Pai + Pbr);   // Pa + i*Pb
    Q2 = make_float2(Par + Pbi, Pbr - Pai);   // conj(Pa) + i*conj(Pb)
}

// ---------------------------------------------------------------- init

__global__ void init_kernel() {
    int t = blockIdx.x * blockDim.x + threadIdx.x;
    if (t < 12) g_acc[t] = 0.0;
    if (t < 341) {                                // L=1024 twiddles (all 5 stages)
        int ncur = 1024, p = t;
        while (p >= (ncur >> 2)) { p -= (ncur >> 2); ncur >>= 2; }
        double ang = 6.283185307179586476925286766559 * (double)p / (double)ncur;
        g_tw1024[t] = make_float2((float)cos(ang), (float)sin(ang));
    }
    if (t < 42) {                                 // L=128 twiddles (3 radix-4 stages)
        int ncur = 128, p = t;
        while (p >= (ncur >> 2)) { p -= (ncur >> 2); ncur >>= 2; }
        double ang = 6.283185307179586476925286766559 * (double)p / (double)ncur;
        g_tw128[t] = make_float2((float)cos(ang), (float)sin(ang));
    }
    if (t < NFREQ) {
        double freq   = (double)t * (8000.0 / 512.0);
        double melmax = 2595.0 * log10(1.0 + 8000.0 / 700.0);
        double mstep  = melmax / 81.0;
        double mval   = 2595.0 * log10(1.0 + freq / 700.0);
        int i = (int)floor(mval / mstep);
        if (i < 0) i = 0;
        if (i > 81) i = 81;
        double f_lo = 700.0 * (pow(10.0, ((double)i * mstep) / 2595.0) - 1.0);
        double f_hi = 700.0 * (pow(10.0, ((double)(i + 1) * mstep) / 2595.0) - 1.0);
        double inv  = 1.0 / (f_hi - f_lo);
        int i0 = -1, i1 = -1; float w0 = 0.f, w1 = 0.f;
        if (i <= 79)           { i0 = i;     w0 = (float)fmax(0.0, (freq - f_lo) * inv); }
        if (i >= 1 && i <= 80) { i1 = i - 1; w1 = (float)fmax(0.0, (f_hi - freq) * inv); }
        g_mel_i0[t] = i0; g_mel_w0[t] = w0;
        g_mel_i1[t] = i1; g_mel_w1[t] = w1;
    }
}

// Second init pass: per-mel contiguous gather ranges (i0[k], i1[k] are
// monotone in k, so each mel's membership is a contiguous bin range).
__global__ void init2_kernel() {
    int m = threadIdx.x;
    if (m >= NMEL) return;
    int s0 = NFREQ, e0 = 0, s1 = NFREQ, e1 = 0;
    for (int k = 0; k < NFREQ; ++k) {
        if (g_mel_i0[k] == m) { if (k < s0) s0 = k; if (k + 1 > e0) e0 = k + 1; }
        if (g_mel_i1[k] == m) { if (k < s1) s1 = k; if (k + 1 > e1) e1 = k + 1; }
    }
    g_mel_rng[m] = make_int4(s0, e0, s1, e1);
}

// ---------------------------------------------------------------- STFT losses
// One block per (signal, frame PAIR): two 1024-pt FFTs batched (R=2) share
// all barriers / reductions / atomics. pred packed as real, target as imag;
// Hermitian unpack recovers both spectra. The last pair's second frame (251)
// is zero-filled and contributes exactly 0 to every loss term.

__global__ __launch_bounds__(TPB, 5) void stft_loss_kernel(const float* __restrict__ pd,
                                                           const float* __restrict__ td) {
    __shared__ float2 sA[2 * NFFT], sB[2 * NFFT];
    __shared__ float s_mel;
    __shared__ float scr[8];
    int f0  = blockIdx.x * 2;
    int sig = blockIdx.y;
    const float* p = pd + (size_t)sig * T_SIG;
    const float* q = td + (size_t)sig * T_SIG;
    int tid = threadIdx.x;

    #pragma unroll
    for (int l = 0; l < (2 * NFFT) / TPB; ++l) {
        int j = tid + TPB * l;
        int fr = j >> 10, jj = j & (NFFT - 1);
        int f = f0 + fr;
        float2 v = make_float2(0.f, 0.f);
        if (f < NFRAMES) {
            int t0 = f * HOP - 512 + jj;           // reflect padding (center=True)
            if (t0 < 0) t0 = -t0;
            else if (t0 >= T_SIG) t0 = 2 * T_SIG - 2 - t0;
            float w = 0.5f - 0.5f * cospif((float)jj * (1.0f / 512.0f));  // hann
            v = make_float2(p[t0] * w, q[t0] * w);
        }
        sA[j] = v;
    }
    if (tid == 0) s_mel = 0.f;
    __syncthreads();

    // L=1024 has 5 radix-4 stages (odd count) -> result lands in sB; sA free.
    float2* res = smem_fft4<-1, NFFT, 2, NFFT, 2, 2>(sA, sB, g_tw1024);

    const float SCL2 = 0.0026041666666666665f;     // 1/(sum hann^2) = 1/384
    float magacc = 0.f, cosacc = 0.f;
    #pragma unroll
    for (int fr = 0; fr < 2; ++fr) {
        float2* rf = res + fr * NFFT;
        float2* cache = sA + fr * NFFT;
        for (int k = tid; k < NFREQ; k += TPB) {
            float2 Xk = rf[k];
            float2 Xm = rf[(NFFT - k) & (NFFT - 1)];
            float Pr = 0.5f * (Xk.x + Xm.x);
            float Pi = 0.5f * (Xk.y - Xm.y);
            float Tr = 0.5f * (Xk.y + Xm.y);
            float Ti = 0.5f * (Xm.x - Xk.x);
            float pp = (Pr * Pr + Pi * Pi) * SCL2;
            float tp = (Tr * Tr + Ti * Ti) * SCL2;
            magacc += fabsf(sqrtf(pp) - sqrtf(tp));
            float dot = (Pr * Tr + Pi * Ti) * SCL2;
            cosacc += dot * rsqrtf(fmaxf(pp * tp, 1e-36f));  // cos(dphi)
            cache[k] = make_float2(pp, tp);        // cache powers for mel gather
        }
    }
    __syncthreads();
    if (tid < 2 * NMEL) {                          // gather: (frame, mel) per thread
        int fr = tid / NMEL;
        int m  = tid - fr * NMEL;
        const float2* cache = sA + fr * NFFT;
        int4 r = g_mel_rng[m];
        float mp_ = 0.f, mt_ = 0.f;
        for (int k = r.x; k < r.y; ++k) {
            float w = g_mel_w0[k]; float2 v = cache[k];
            mp_ += v.x * w; mt_ += v.y * w;
        }
        for (int k = r.z; k < r.w; ++k) {
            float w = g_mel_w1[k]; float2 v = cache[k];
            mp_ += v.x * w; mt_ += v.y * w;
        }
        float d = fabsf(logf(mp_ + 1e-8f) - logf(mt_ + 1e-8f));
        atomicAdd(&s_mel, d);
    }
    float bm = block_reduce(magacc, scr);
    float bc = block_reduce(cosacc, scr);
    if (tid == 0) {
        atomicAdd(&g_acc[0], (double)bm);
        atomicAdd(&g_acc[1], (double)bc);
        atomicAdd(&g_acc[2], (double)s_mel);
    }
}

// ---------------------------------------------------------------- time-domain

__global__ __launch_bounds__(TPB) void time_loss_kernel(const float4* __restrict__ pd,
                                                        const float4* __restrict__ pr,
                                                        const float4* __restrict__ td,
                                                        const float4* __restrict__ tr) {
    __shared__ float segsum[4];
    __shared__ float scr[8];
    if (threadIdx.x < 4) segsum[threadIdx.x] = 0.f;
    __syncthreads();
    float dry = 0.f, rir = 0.f, spa = 0.f;
    const int N4 = (NSIG * T_SIG) / 4;             // 1,024,000
    int stride = gridDim.x * TPB;
    for (int i = blockIdx.x * TPB + threadIdx.x; i < N4; i += stride) {
        float4 a = pd[i], b = td[i], c = pr[i], d = tr[i];
        dry += fabsf(a.x-b.x) + fabsf(a.y-b.y) + fabsf(a.z-b.z) + fabsf(a.w-b.w);
        rir += fabsf(c.x-d.x) + fabsf(c.y-d.y) + fabsf(c.z-d.z) + fabsf(c.w-d.w);
        spa += fabsf(c.x) + fabsf(c.y) + fabsf(c.z) + fabsf(c.w);
        float sq = c.x*c.x + c.y*c.y + c.z*c.z + c.w*c.w;
        #pragma unroll
        for (int o = 16; o; o >>= 1) sq += __shfl_down_sync(0xffffffffu, sq, o);
        if ((threadIdx.x & 31) == 0) {
            int t0 = (i * 4) % T_SIG;              // warp-uniform segment
            atomicAdd(&segsum[t0 / 16000], sq);
        }
    }
    float bd = block_reduce(dry, scr);
    float br = block_reduce(rir, scr);
    float bs = block_reduce(spa, scr);
    __syncthreads();
    if (threadIdx.x == 0) {
        atomicAdd(&g_acc[3], (double)bd);
        atomicAdd(&g_acc[4], (double)br);
        atomicAdd(&g_acc[5], (double)bs);
    }
    if (threadIdx.x < 4) atomicAdd(&g_acc[6 + threadIdx.x], (double)segsum[threadIdx.x]);
}

// ---------------------------------------------------------------- consistency
// 2^17-pt four-step FFT. n = n1 + 1024*n2, k = k2 + 128*k1. Spectra stored
// permuted at p = k2*1024 + k1. dry packed as real, rir as imag (forward);
// two Hermitian product spectra packed per inverse FFT.

// Column FFT with radix-4 stage 0 fused into the global load: the upper half
// of every column (n2 >= 63) is structurally zero (n >= T_SIG), so stage 0
// degenerates to a0 +/- a1 and a0 -/+ i*a1 with only two loads. Output store
// vectorized to float4 (2 consecutive n1 per thread); the paired transposed
// smem reads stay conflict-free under the g0 swizzle.
__global__ __launch_bounds__(TPB, 6) void conv_fwdA(const float* __restrict__ dry,
                                                    const float* __restrict__ rir) {
    __shared__ __align__(16) float2 sA[16 * CRS], sB[16 * CRS];
    int n1_0 = blockIdx.x * 16;
    int sig  = blockIdx.y;
    const float* d = dry + (size_t)sig * T_SIG;
    const float* r = rir + (size_t)sig * T_SIG;
    #pragma unroll
    for (int l = 0; l < 2; ++l) {                 // 512 stage-0 butterflies
        int idx = threadIdx.x + TPB * l;
        int n1l = idx & 15, p = idx >> 4;          // p in [0,32)
        int n1 = n1_0 + n1l;
        float2 a0 = make_float2(d[n1 + (p << 10)], r[n1 + (p << 10)]);
        int nb = n1 + ((p + 32) << 10);
        float2 a1 = make_float2(0.f, 0.f);
        if (nb < T_SIG) { a1.x = d[nb]; a1.y = r[nb]; }
        // SIGN=-1 stage 0 with a2=a3=0
        float b0x = a0.x + a1.x, b0y = a0.y + a1.y;
        float b2x = a0.x - a1.x, b2y = a0.y - a1.y;
        float b1x = a0.x + a1.y, b1y = a0.y - a1.x;   // a0 - i a1
        float b3x = a0.x - a1.y, b3y = a0.y + a1.x;   // a0 + i a1
        float2 w = __ldg(&g_tw128[p]);
        float c1 = w.x, s1 = -w.y;
        float c2 = c1 * c1 - s1 * s1, s2 = 2.f * c1 * s1;
        float c3 = c2 * c1 - s2 * s1, s3 = c2 * s1 + s2 * c1;
        int ob = n1l * CRS + (p << 2);
        sA[swz(ob, 0)]     = make_float2(b0x, b0y);
        sA[swz(ob + 1, 0)] = make_float2(b1x * c1 - b1y * s1, b1x * s1 + b1y * c1);
        sA[swz(ob + 2, 0)] = make_float2(b2x * c2 - b2y * s2, b2x * s2 + b2y * c2);
        sA[swz(ob + 3, 0)] = make_float2(b3x * c3 - b3y * s3, b3x * s3 + b3y * c3);
    }
    __syncthreads();
    float2* res = smem_fft4<-1, 128, 16, CRS, 0, 0, 1>(sA, sB, g_tw128);
    float4* out4 = (float4*)(g_bufA + (size_t)sig * CN);
    #pragma unroll
    for (int l = 0; l < 4; ++l) {                  // 1024 float4 stores total
        int idx = threadIdx.x + TPB * l;
        int n1h = idx & 7, k2 = idx >> 3;
        int n1a = n1_0 + 2 * n1h;
        float2 y0 = res[swz((2 * n1h) * CRS + k2, 0)];
        float2 y1 = res[swz((2 * n1h + 1) * CRS + k2, 0)];
        float c0, s0, c1, s1;
        __sincosf(-(6.2831853071795864f / 131072.0f) * (float)(n1a * k2), &s0, &c0);
        __sincosf(-(6.2831853071795864f / 131072.0f) * (float)((n1a + 1) * k2), &s1, &c1);
        out4[(k2 << 9) + ((n1_0 >> 1) + n1h)] =
            make_float4(y0.x * c0 - y0.y * s0, y0.x * s0 + y0.y * c0,
                        y1.x * c1 - y1.y * s1, y1.x * s1 + y1.y * c1);
    }
}

// Fused: forward 1024-pt row FFTs (4 rows) + Hermitian pointwise product
// (packed pairs) + inverse 1024-pt row FFTs + inter-pass twiddle.
// Block x handles conjugate row pair (r0, r1); x==0 handles the self-paired
// rows 0 and 64. y = product-pair index (signals 2y, 2y+1 -> Pa + i*Pb).
// Global loads/stores are float4-vectorized.
__global__ __launch_bounds__(TPB) void conv_prodrow_inv1() {
    __shared__ __align__(16) float2 S[6144];
    int x = blockIdx.x, pr = blockIdx.y;
    int r0 = x;
    int r1 = x ? (128 - x) : 64;
    const float2* Xa = g_bufA + (size_t)(2 * pr) * CN;
    const float2* Xb = Xa + CN;
    int tid = threadIdx.x;
    {
        const float4* Xa0 = (const float4*)(Xa + r0 * 1024);
        const float4* Xa1 = (const float4*)(Xa + r1 * 1024);
        const float4* Xb0 = (const float4*)(Xb + r0 * 1024);
        const float4* Xb1 = (const float4*)(Xb + r1 * 1024);
        float4* S4 = (float4*)S;
        #pragma unroll
        for (int l = 0; l < 2; ++l) {
            int i = tid + TPB * l;                 // 0..511 float4 per row
            S4[i]        = Xa0[i];
            S4[512 + i]  = Xa1[i];
            S4[1024 + i] = Xb0[i];
            S4[1536 + i] = Xb1[i];
        }
    }
    __syncthreads();
    float2* aF = smem_fft4<-1, 1024, 2, 1024, 2, 2>(S, S + 4096, g_tw1024);       // = S+4096
    float2* bF = smem_fft4<-1, 1024, 2, 1024, 2, 2>(S + 2048, S, g_tw1024);       // = S
    float2* P = S + 2048;
    if (x) {
        // cross pair: (r0, k1) <-> (r1, 1023-k1)
        #pragma unroll
        for (int l = 0; l < 4; ++l) {
            int k1 = tid + TPB * l;
            int jm = 1023 - k1;
            float2 Q1, Q2;
            packprod(aF[k1], aF[1024 + jm], bF[k1], bF[1024 + jm], Q1, Q2);
            P[k1] = Q1;
            P[1024 + jm] = Q2;
        }
    } else {
        // row 0: self pairs (k1, (1024-k1)&1023), k1 in [0,512]
        // row 64: self pairs (k1, 1023-k1), k1 in [0,511]
        #pragma unroll
        for (int l = 0; l < 4; ++l) {
            int k1 = tid + TPB * l;
            if (k1 <= 512) {
                int jm = (1024 - k1) & 1023;
                float2 Q1, Q2;
                packprod(aF[k1], aF[jm], bF[k1], bF[jm], Q1, Q2);
                P[k1] = Q1; P[jm] = Q2;
            }
            if (k1 < 512) {
                int jm = 1023 - k1;
                float2 Q1, Q2;
                packprod(aF[1024 + k1], aF[1024 + jm], bF[1024 + k1], bF[1024 + jm], Q1, Q2);
                P[1024 + k1] = Q1; P[1024 + jm] = Q2;
            }
        }
    }
    __syncthreads();
    float2* res = smem_fft4<1, 1024, 2, 1024, 2, 2>(S + 2048, S, g_tw1024);       // = S
    float4* out4 = (float4*)(g_bufB + (size_t)pr * CN);
    const float4* res4 = (const float4*)res;
    #pragma unroll
    for (int l = 0; l < 4; ++l) {                  // 1024 float4 stores total
        int idx = tid + TPB * l;                   // 0..1023
        int row = idx >> 9;
        int jp = idx & 511;                        // n1 pair index
        int n1 = jp << 1;
        int k2v = row ? r1 : r0;
        float4 v = res4[(row << 9) + jp];
        float c0, s0, c1, s1;
        __sincosf((6.2831853071795864f / 131072.0f) * (float)(n1 * k2v), &s0, &c0);
        __sincosf((6.2831853071795864f / 131072.0f) * (float)((n1 + 1) * k2v), &s1, &c1);
        out4[(k2v << 9) + jp] =
            make_float4(v.x * c0 - v.y * s0, v.x * s0 + v.y * c0,
                        v.z * c1 - v.w * s1, v.z * s1 + v.w * c1);
    }
}

__global__ __launch_bounds__(TPB, 6) void conv_inv2(const float* __restrict__ mix) {
    __shared__ __align__(16) float2 sA[16 * CRS], sB[16 * CRS];
    __shared__ float scr[8];
    int n1_0 = blockIdx.x * 16;
    int pr   = blockIdx.y;
    const float4* inb4 = (const float4*)(g_bufB + (size_t)pr * CN);
    #pragma unroll
    for (int l = 0; l < 4; ++l) {                  // 1024 float4 loads total
        int idx = threadIdx.x + TPB * l;
        int n1h = idx & 7, k2 = idx >> 3;
        float4 v = inb4[(k2 << 9) + ((n1_0 >> 1) + n1h)];
        sA[swz((2 * n1h) * CRS + k2, 0)]     = make_float2(v.x, v.y);
        sA[swz((2 * n1h + 1) * CRS + k2, 0)] = make_float2(v.z, v.w);
    }
    __syncthreads();
    // HALF=1: only the low half of each inverse column is needed (n2 <= 62).
    float2* res = smem_fft4<1, 128, 16, CRS, 0, 0, 0, 1>(sA, sB, g_tw128);
    const float* ma = mix + (size_t)(2 * pr) * T_SIG;
    const float* mb = ma + T_SIG;
    float acc = 0.f;
    const float INVN = 1.0f / 131072.0f;
    #pragma unroll
    for (int l = 0; l < 8; ++l) {
        int idx = threadIdx.x + TPB * l;
        int n1l = idx & 15, n2 = idx >> 4;
        int n = n1_0 + n1l + (n2 << 10);
        if (n < T_SIG) {
            float2 v = res[swz(n1l * CRS + n2, 0)];
            acc += fabsf(v.x * INVN - ma[n]) + fabsf(v.y * INVN - mb[n]);
        }
    }
    float b = block_reduce(acc, scr);
    if (threadIdx.x == 0) atomicAdd(&g_acc[10], (double)b);
}

// ---------------------------------------------------------------- finalize

__global__ void finalize_kernel(float* out) {
    const double NT   = 4096000.0;                 // 64 * 64000
    const double CNT  = 64.0 * 513.0 * 251.0;
    const double MELC = 64.0 * 80.0 * 251.0;
    const double SEGC = 1024000.0;                 // 64 * 16000
    double dry_time = g_acc[3] / NT;
    double mag   = g_acc[0] / CNT;
    double phase = 1.0 - g_acc[1] / CNT;
    double freqL = mag + 0.1 * phase;
    double mel   = g_acc[2] / MELC;
    double total_dry = dry_time + 0.5 * freqL + 0.3 * mel;
    double rir_time = g_acc[4] / NT;
    double spars    = g_acc[5] / NT;
    double e0 = g_acc[6] / SEGC, e1 = g_acc[7] / SEGC;
    double e2 = g_acc[8] / SEGC, e3 = g_acc[9] / SEGC;
    double decay = fmax(0.0, e1 - 0.8 * e0) + fmax(0.0, e2 - 0.8 * e1)
                 + fmax(0.0, e3 - 0.8 * e2);
    double total_rir = rir_time + 0.1 * (spars + decay);
    double consist = g_acc[10] / NT;
    out[0] = (float)(3.0 * total_dry + total_rir + 0.2 * consist);
}

// ---------------------------------------------------------------- launch
// Graph fork-join: after init, three independent branches run concurrently —
// stft (s1), time_loss (s2), conv chain (capture stream) — joined via events
// before finalize.

extern "C" void kernel_launch(void* const* d_in, const int* in_sizes, int n_in,
                              void* d_out, int out_size) {
    const float* pd  = (const float*)d_in[0];   // pred_dry
    const float* pr  = (const float*)d_in[1];   // pred_rir
    const float* td  = (const float*)d_in[2];   // target_dry
    const float* tr  = (const float*)d_in[3];   // target_rir
    const float* mix = (const float*)d_in[4];   // mix
    float* out = (float*)d_out;

    init_kernel<<<3, TPB>>>();
    init2_kernel<<<1, 128>>>();

    cudaEventRecord(g_eF, 0);
    cudaStreamWaitEvent(g_s1, g_eF, 0);
    cudaStreamWaitEvent(g_s2, g_eF, 0);

    stft_loss_kernel<<<dim3(NPAIR, NSIG), TPB, 0, g_s1>>>(pd, td);
    time_loss_kernel<<<1024, TPB, 0, g_s2>>>((const float4*)pd, (const float4*)pr,
                                             (const float4*)td, (const float4*)tr);
    conv_fwdA<<<dim3(64, NSIG), TPB>>>(pd, pr);
    conv_prodrow_inv1<<<dim3(64, 32), TPB>>>();
    conv_inv2<<<dim3(64, 32), TPB>>>(mix);

    cudaEventRecord(g_eJ1, g_s1);
    cudaEventRecord(g_eJ2, g_s2);
    cudaStreamWaitEvent(0, g_eJ1, 0);
    cudaStreamWaitEvent(0, g_eJ2, 0);

    finalize_kernel<<<1, 1>>>(out);
}

// round 14
// speedup vs baseline: 1.1342x; 1.0493x over previous
#include <cuda_runtime.h>

#define TPB 256
#define T_SIG 64000
#define NSIG 64
#define NFFT 1024
#define HOP 256
#define NFRAMES 251
#define NPAIR 126   // ceil(NFRAMES/2) frame pairs per signal
#define NFREQ 513
#define NMEL 80
#define CN 131072   // conv FFT length = 2^17 >= 2*T-1 (exact linear convolution)
#define CRS 144     // conv smem row stride; 144>>4=9 odd => g0 swizzle fixes transpose

// global accumulators (double):
// 0 mag, 1 cos, 2 mel, 3 dryL1, 4 rirL1, 5 sparsity, 6..9 e0..e3, 10 consist
__device__ double g_acc[12];
__device__ int    g_mel_i0[NFREQ];
__device__ float  g_mel_w0[NFREQ];
__device__ int    g_mel_i1[NFREQ];
__device__ float  g_mel_w1[NFREQ];
__device__ int4   g_mel_rng[NMEL];             // per-mel gather ranges
__device__ float2 g_tw1024[341];               // radix-4 twiddles, L=1024 (all stages)
__device__ float2 g_tw128[42];                 // radix-4 twiddles, L=128
__device__ __align__(16) float2 g_bufA[(size_t)NSIG * CN];   // 64 MB scratch
__device__ __align__(16) float2 g_bufB[(size_t)NSIG * CN];   // 64 MB scratch

// Streams/events for graph fork-join (created at program init, before the
// harness's memory checkpoints; NonBlocking so the legacy capture stream
// doesn't implicitly serialize them).
static cudaStream_t g_s1, g_s2;
static cudaEvent_t  g_eF, g_eJ1, g_eJ2;
static struct StreamInit {
    StreamInit() {
        cudaStreamCreateWithFlags(&g_s1, cudaStreamNonBlocking);
        cudaStreamCreateWithFlags(&g_s2, cudaStreamNonBlocking);
        cudaEventCreateWithFlags(&g_eF,  cudaEventDisableTiming);
        cudaEventCreateWithFlags(&g_eJ1, cudaEventDisableTiming);
        cudaEventCreateWithFlags(&g_eJ2, cudaEventDisableTiming);
    }
} g_stream_init;

// ---------------------------------------------------------------- utilities

__host__ __device__ constexpr int ilog2c(int n) { return n <= 1 ? 0 : 1 + ilog2c(n / 2); }

// Bank swizzle per buffer generation (bits [0:4) XOR-keyed from upper bits).
// g=0 fixes stage-0 write pattern (4bf+j) AND stride-144 transpose accesses;
// g=1 fixes stage-1 pattern (q | j<<2 | p<<4); g=2 identity.
__device__ __forceinline__ int swz(int a, int g) {
    if (g == 0) return a ^ ((a >> 4) & 0xF);
    if (g == 1) return a ^ ((a >> 2) & 0xC);
    return a;
}

__device__ __forceinline__ float block_reduce(float v, float* scr) {
    #pragma unroll
    for (int o = 16; o; o >>= 1) v += __shfl_down_sync(0xffffffffu, v, o);
    __syncthreads();
    if ((threadIdx.x & 31) == 0) scr[threadIdx.x >> 5] = v;
    __syncthreads();
    if (threadIdx.x < 32) {
        v = (threadIdx.x < (TPB / 32)) ? scr[threadIdx.x] : 0.f;
        #pragma unroll
        for (int o = 4; o; o >>= 1) v += __shfl_down_sync(0xffffffffu, v, o);
    }
    return v;  // valid on thread 0
}

// Mixed radix-4/2 Stockham DIF FFT over R rows of length L (power of 2) in
// shared memory, row stride RS (float2, 16-aligned). The caller writes the
// input through swz(.,GIN) and reads the natural-order result through
// swz(.,GOUT). SKIP=1: caller already performed radix-4 stage 0 (input must
// be in generation-0 layout). HALF=1: radix-2 tail stores only the low half
// (A+B) of each output pair.
template<int SIGN, int L, int R, int RS, int GIN, int GOUT, int SKIP = 0, int HALF = 0>
__device__ __forceinline__ float2* smem_fft4(float2* a, float2* b,
                                             const float2* __restrict__ tw) {
    constexpr int LOG2L = ilog2c(L);
    constexpr int NS4 = LOG2L >> 1;
    float2 *src = a, *dst = b;
    int ncur = L >> (2 * SKIP), logs = 2 * SKIP, toff = SKIP ? (L >> 2) : 0;
    #pragma unroll
    for (int s = SKIP; s < NS4; ++s) {
        const int rg = (s == 0) ? GIN : (s == 1) ? 0 : (s == 2) ? 1 : 2;
        const int wg = ((s == NS4 - 1) && !(LOG2L & 1)) ? GOUT
                       : (s == 0) ? 0 : (s == 1) ? 1 : 2;
        const int m = ncur >> 2;
        const int Ls = 1 << logs;
        constexpr int NB = R * (L >> 2);
        #pragma unroll
        for (int l = 0; l < NB / TPB; ++l) {
            const int it = threadIdx.x + TPB * l;
            const int row = it >> (LOG2L - 2);
            const int bf  = it & ((L >> 2) - 1);
            const int p = bf >> logs;
            const int q = bf - (p << logs);
            const int base = row * RS + q;
            float2 a0 = src[swz(base + p * Ls, rg)];
            float2 a1 = src[swz(base + (p + m) * Ls, rg)];
            float2 a2 = src[swz(base + (p + 2 * m) * Ls, rg)];
            float2 a3 = src[swz(base + (p + 3 * m) * Ls, rg)];
            float t0x = a0.x + a2.x, t0y = a0.y + a2.y;
            float t1x = a0.x - a2.x, t1y = a0.y - a2.y;
            float t2x = a1.x + a3.x, t2y = a1.y + a3.y;
            float t3x = a1.x - a3.x, t3y = a1.y - a3.y;
            float b0x = t0x + t2x, b0y = t0y + t2y;
            float b2x = t0x - t2x, b2y = t0y - t2y;
            float b1x, b1y, b3x, b3y;
            if (SIGN < 0) {           // b1 = t1 - i t3, b3 = t1 + i t3
                b1x = t1x + t3y; b1y = t1y - t3x;
                b3x = t1x - t3y; b3y = t1y + t3x;
            } else {                  // b1 = t1 + i t3, b3 = t1 - i t3
                b1x = t1x - t3y; b1y = t1y + t3x;
                b3x = t1x + t3y; b3y = t1y - t3x;
            }
            float2 w = __ldg(&tw[toff + p]);
            float c1 = w.x;
            float s1 = (SIGN < 0) ? -w.y : w.y;
            float c2 = c1 * c1 - s1 * s1, s2 = 2.f * c1 * s1;
            float c3 = c2 * c1 - s2 * s1, s3 = c2 * s1 + s2 * c1;
            const int ob = base + ((p << 2) << logs);
            dst[swz(ob, wg)]          = make_float2(b0x, b0y);
            dst[swz(ob + Ls, wg)]     = make_float2(b1x * c1 - b1y * s1, b1x * s1 + b1y * c1);
            dst[swz(ob + 2 * Ls, wg)] = make_float2(b2x * c2 - b2y * s2, b2x * s2 + b2y * c2);
            dst[swz(ob + 3 * Ls, wg)] = make_float2(b3x * c3 - b3y * s3, b3x * s3 + b3y * c3);
        }
        __syncthreads();
        float2* t = src; src = dst; dst = t;
        ncur >>= 2; logs += 2; toff += m;
    }
    if constexpr (LOG2L & 1) {        // final radix-2 stage (twiddle-free, p=0)
        const int rg = (NS4 == 1) ? 0 : (NS4 == 2) ? 1 : 2;
        constexpr int Ls = L >> 1;
        constexpr int NB = R * (L >> 1);
        #pragma unroll
        for (int l = 0; l < NB / TPB; ++l) {
            const int it = threadIdx.x + TPB * l;
            const int row = it >> (LOG2L - 1);
            const int q   = it & ((L >> 1) - 1);
            const int base = row * RS + q;
            float2 A = src[swz(base, rg)];
            float2 B = src[swz(base + Ls, rg)];
            dst[swz(base, GOUT)]      = make_float2(A.x + B.x, A.y + B.y);
            if constexpr (!HALF)
                dst[swz(base + Ls, GOUT)] = make_float2(A.x - B.x, A.y - B.y);
        }
        __syncthreads();
        float2* t = src; src = dst; dst = t;
    }
    return src;
}

// Hermitian unpack of two packed spectra (dry real, rir imag) + complex
// product, producing packed product pair Q1 (at p1) / Q2 (at p2=conj pos).
__device__ __forceinline__ void packprod(float2 A1, float2 A2, float2 B1, float2 B2,
                                         float2& Q1, float2& Q2) {
    float Dar = 0.5f * (A1.x + A2.x), Dai = 0.5f * (A1.y - A2.y);
    float Rar = 0.5f * (A1.y + A2.y), Rai = 0.5f * (A2.x - A1.x);
    float Par = Dar * Rar - Dai * Rai, Pai = Dar * Rai + Dai * Rar;
    float Dbr = 0.5f * (B1.x + B2.x), Dbi = 0.5f * (B1.y - B2.y);
    float Rbr = 0.5f * (B1.y + B2.y), Rbi = 0.5f * (B2.x - B1.x);
    float Pbr = Dbr * Rbr - Dbi * Rbi, Pbi = Dbr * Rbi + Dbi * Rbr;
    Q1 = make_float2(Par - Pbi, Pai + Pbr);   // Pa + i*Pb
    Q2 = make_float2(Par + Pbi, Pbr - Pai);   // conj(Pa) + i*conj(Pb)
}

// ---------------------------------------------------------------- init

__global__ void init_kernel() {
    int t = blockIdx.x * blockDim.x + threadIdx.x;
    if (t < 12) g_acc[t] = 0.0;
    if (t < 341) {                                // L=1024 twiddles (all 5 stages)
        int ncur = 1024, p = t;
        while (p >= (ncur >> 2)) { p -= (ncur >> 2); ncur >>= 2; }
        double ang = 6.283185307179586476925286766559 * (double)p / (double)ncur;
        g_tw1024[t] = make_float2((float)cos(ang), (float)sin(ang));
    }
    if (t < 42) {                                 // L=128 twiddles (3 radix-4 stages)
        int ncur = 128, p = t;
        while (p >= (ncur >> 2)) { p -= (ncur >> 2); ncur >>= 2; }
        double ang = 6.283185307179586476925286766559 * (double)p / (double)ncur;
        g_tw128[t] = make_float2((float)cos(ang), (float)sin(ang));
    }
    if (t < NFREQ) {
        double freq   = (double)t * (8000.0 / 512.0);
        double melmax = 2595.0 * log10(1.0 + 8000.0 / 700.0);
        double mstep  = melmax / 81.0;
        double mval   = 2595.0 * log10(1.0 + freq / 700.0);
        int i = (int)floor(mval / mstep);
        if (i < 0) i = 0;
        if (i > 81) i = 81;
        double f_lo = 700.0 * (pow(10.0, ((double)i * mstep) / 2595.0) - 1.0);
        double f_hi = 700.0 * (pow(10.0, ((double)(i + 1) * mstep) / 2595.0) - 1.0);
        double inv  = 1.0 / (f_hi - f_lo);
        int i0 = -1, i1 = -1; float w0 = 0.f, w1 = 0.f;
        if (i <= 79)           { i0 = i;     w0 = (float)fmax(0.0, (freq - f_lo) * inv); }
        if (i >= 1 && i <= 80) { i1 = i - 1; w1 = (float)fmax(0.0, (f_hi - freq) * inv); }
        g_mel_i0[t] = i0; g_mel_w0[t] = w0;
        g_mel_i1[t] = i1; g_mel_w1[t] = w1;
    }
}

// Second init pass: per-mel contiguous gather ranges (i0[k], i1[k] are
// monotone in k, so each mel's membership is a contiguous bin range).
__global__ void init2_kernel() {
    int m = threadIdx.x;
    if (m >= NMEL) return;
    int s0 = NFREQ, e0 = 0, s1 = NFREQ, e1 = 0;
    for (int k = 0; k < NFREQ; ++k) {
        if (g_mel_i0[k] == m) { if (k < s0) s0 = k; if (k + 1 > e0) e0 = k + 1; }
        if (g_mel_i1[k] == m) { if (k < s1) s1 = k; if (k + 1 > e1) e1 = k + 1; }
    }
    g_mel_rng[m] = make_int4(s0, e0, s1, e1);
}

// ---------------------------------------------------------------- STFT losses
// One block per (signal, frame PAIR): two 1024-pt FFTs batched (R=2) share
// all barriers / reductions / atomics. Radix-4 stage 0 is FUSED into the
// windowed global load (SKIP=1): each thread loads the 4 stride-256 samples
// of one butterfly, windows, butterflies in registers, writes g0 layout —
// saving a full smem round trip. The last pair's second frame (251) is
// zero-filled and contributes exactly 0 to every loss term.

__global__ __launch_bounds__(TPB, 5) void stft_loss_kernel(const float* __restrict__ pd,
                                                           const float* __restrict__ td) {
    __shared__ float2 sA[2 * NFFT], sB[2 * NFFT];
    __shared__ float s_mel;
    __shared__ float scr[8];
    int f0  = blockIdx.x * 2;
    int sig = blockIdx.y;
    const float* p = pd + (size_t)sig * T_SIG;
    const float* q = td + (size_t)sig * T_SIG;
    int tid = threadIdx.x;

    if (tid == 0) s_mel = 0.f;
    #pragma unroll
    for (int l = 0; l < 2; ++l) {                  // 512 fused stage-0 butterflies
        int idx = tid + TPB * l;
        int fr = idx >> 8, pb = idx & 255;         // frame-of-pair, butterfly index
        int f = f0 + fr;
        float2 a0, a1, a2, a3;
        if (f < NFRAMES) {
            int base_t = f * HOP - 512;
            #pragma unroll
            for (int j = 0; j < 4; ++j) {
                int jj = pb + (j << 8);
                int t0 = base_t + jj;              // reflect padding (center=True)
                if (t0 < 0) t0 = -t0;
                else if (t0 >= T_SIG) t0 = 2 * T_SIG - 2 - t0;
                float w = 0.5f - 0.5f * cospif((float)jj * (1.0f / 512.0f));  // hann
                float2 v = make_float2(p[t0] * w, q[t0] * w);
                if (j == 0) a0 = v; else if (j == 1) a1 = v;
                else if (j == 2) a2 = v; else a3 = v;
            }
        } else {
            a0 = a1 = a2 = a3 = make_float2(0.f, 0.f);
        }
        // SIGN=-1 radix-4 stage 0
        float t0x = a0.x + a2.x, t0y = a0.y + a2.y;
        float t1x = a0.x - a2.x, t1y = a0.y - a2.y;
        float t2x = a1.x + a3.x, t2y = a1.y + a3.y;
        float t3x = a1.x - a3.x, t3y = a1.y - a3.y;
        float b0x = t0x + t2x, b0y = t0y + t2y;
        float b2x = t0x - t2x, b2y = t0y - t2y;
        float b1x = t1x + t3y, b1y = t1y - t3x;    // t1 - i t3
        float b3x = t1x - t3y, b3y = t1y + t3x;    // t1 + i t3
        float2 w = __ldg(&g_tw1024[pb]);
        float c1 = w.x, s1 = -w.y;
        float c2 = c1 * c1 - s1 * s1, s2 = 2.f * c1 * s1;
        float c3 = c2 * c1 - s2 * s1, s3 = c2 * s1 + s2 * c1;
        int ob = fr * NFFT + (pb << 2);
        sA[swz(ob, 0)]     = make_float2(b0x, b0y);
        sA[swz(ob + 1, 0)] = make_float2(b1x * c1 - b1y * s1, b1x * s1 + b1y * c1);
        sA[swz(ob + 2, 0)] = make_float2(b2x * c2 - b2y * s2, b2x * s2 + b2y * c2);
        sA[swz(ob + 3, 0)] = make_float2(b3x * c3 - b3y * s3, b3x * s3 + b3y * c3);
    }
    __syncthreads();

    // 4 remaining radix-4 stages (SKIP=1); result parity: back in sA.
    float2* res = smem_fft4<-1, NFFT, 2, NFFT, 0, 2, 1>(sA, sB, g_tw1024);
    float2* cache = (res == sA) ? sB : sA;         // free buffer for power cache

    const float SCL2 = 0.0026041666666666665f;     // 1/(sum hann^2) = 1/384
    float magacc = 0.f, cosacc = 0.f;
    #pragma unroll
    for (int fr = 0; fr < 2; ++fr) {
        float2* rf = res + fr * NFFT;
        float2* cf = cache + fr * NFFT;
        for (int k = tid; k < NFREQ; k += TPB) {
            float2 Xk = rf[k];
            float2 Xm = rf[(NFFT - k) & (NFFT - 1)];
            float Pr = 0.5f * (Xk.x + Xm.x);
            float Pi = 0.5f * (Xk.y - Xm.y);
            float Tr = 0.5f * (Xk.y + Xm.y);
            float Ti = 0.5f * (Xm.x - Xk.x);
            float pp = (Pr * Pr + Pi * Pi) * SCL2;
            float tp = (Tr * Tr + Ti * Ti) * SCL2;
            magacc += fabsf(sqrtf(pp) - sqrtf(tp));
            float dot = (Pr * Tr + Pi * Ti) * SCL2;
            cosacc += dot * rsqrtf(fmaxf(pp * tp, 1e-36f));  // cos(dphi)
            cf[k] = make_float2(pp, tp);           // cache powers for mel gather
        }
    }
    __syncthreads();
    if (tid < 2 * NMEL) {                          // gather: (frame, mel) per thread
        int fr = tid / NMEL;
        int m  = tid - fr * NMEL;
        const float2* cf = cache + fr * NFFT;
        int4 r = g_mel_rng[m];
        float mp_ = 0.f, mt_ = 0.f;
        for (int k = r.x; k < r.y; ++k) {
            float w = g_mel_w0[k]; float2 v = cf[k];
            mp_ += v.x * w; mt_ += v.y * w;
        }
        for (int k = r.z; k < r.w; ++k) {
            float w = g_mel_w1[k]; float2 v = cf[k];
            mp_ += v.x * w; mt_ += v.y * w;
        }
        float d = fabsf(logf(mp_ + 1e-8f) - logf(mt_ + 1e-8f));
        atomicAdd(&s_mel, d);
    }
    float bm = block_reduce(magacc, scr);
    float bc = block_reduce(cosacc, scr);
    if (tid == 0) {
        atomicAdd(&g_acc[0], (double)bm);
        atomicAdd(&g_acc[1], (double)bc);
        atomicAdd(&g_acc[2], (double)s_mel);
    }
}

// ---------------------------------------------------------------- time-domain

__global__ __launch_bounds__(TPB) void time_loss_kernel(const float4* __restrict__ pd,
                                                        const float4* __restrict__ pr,
                                                        const float4* __restrict__ td,
                                                        const float4* __restrict__ tr) {
    __shared__ float segsum[4];
    __shared__ float scr[8];
    if (threadIdx.x < 4) segsum[threadIdx.x] = 0.f;
    __syncthreads();
    float dry = 0.f, rir = 0.f, spa = 0.f;
    const int N4 = (NSIG * T_SIG) / 4;             // 1,024,000
    int stride = gridDim.x * TPB;
    for (int i = blockIdx.x * TPB + threadIdx.x; i < N4; i += stride) {
        float4 a = pd[i], b = td[i], c = pr[i], d = tr[i];
        dry += fabsf(a.x-b.x) + fabsf(a.y-b.y) + fabsf(a.z-b.z) + fabsf(a.w-b.w);
        rir += fabsf(c.x-d.x) + fabsf(c.y-d.y) + fabsf(c.z-d.z) + fabsf(c.w-d.w);
        spa += fabsf(c.x) + fabsf(c.y) + fabsf(c.z) + fabsf(c.w);
        float sq = c.x*c.x + c.y*c.y + c.z*c.z + c.w*c.w;
        #pragma unroll
        for (int o = 16; o; o >>= 1) sq += __shfl_down_sync(0xffffffffu, sq, o);
        if ((threadIdx.x & 31) == 0) {
            int t0 = (i * 4) % T_SIG;              // warp-uniform segment
            atomicAdd(&segsum[t0 / 16000], sq);
        }
    }
    float bd = block_reduce(dry, scr);
    float br = block_reduce(rir, scr);
    float bs = block_reduce(spa, scr);
    __syncthreads();
    if (threadIdx.x == 0) {
        atomicAdd(&g_acc[3], (double)bd);
        atomicAdd(&g_acc[4], (double)br);
        atomicAdd(&g_acc[5], (double)bs);
    }
    if (threadIdx.x < 4) atomicAdd(&g_acc[6 + threadIdx.x], (double)segsum[threadIdx.x]);
}

// ---------------------------------------------------------------- consistency
// 2^17-pt four-step FFT. n = n1 + 1024*n2, k = k2 + 128*k1. Spectra stored
// permuted at p = k2*1024 + k1. dry packed as real, rir as imag (forward);
// two Hermitian product spectra packed per inverse FFT.

// Column FFT with radix-4 stage 0 fused into the global load: the upper half
// of every column (n2 >= 63) is structurally zero (n >= T_SIG), so stage 0
// degenerates to a0 +/- a1 and a0 -/+ i*a1 with only two loads. Output store
// vectorized to float4 (2 consecutive n1 per thread); the paired transposed
// smem reads stay conflict-free under the g0 swizzle.
__global__ __launch_bounds__(TPB, 6) void conv_fwdA(const float* __restrict__ dry,
                                                    const float* __restrict__ rir) {
    __shared__ __align__(16) float2 sA[16 * CRS], sB[16 * CRS];
    int n1_0 = blockIdx.x * 16;
    int sig  = blockIdx.y;
    const float* d = dry + (size_t)sig * T_SIG;
    const float* r = rir + (size_t)sig * T_SIG;
    #pragma unroll
    for (int l = 0; l < 2; ++l) {                 // 512 stage-0 butterflies
        int idx = threadIdx.x + TPB * l;
        int n1l = idx & 15, p = idx >> 4;          // p in [0,32)
        int n1 = n1_0 + n1l;
        float2 a0 = make_float2(d[n1 + (p << 10)], r[n1 + (p << 10)]);
        int nb = n1 + ((p + 32) << 10);
        float2 a1 = make_float2(0.f, 0.f);
        if (nb < T_SIG) { a1.x = d[nb]; a1.y = r[nb]; }
        // SIGN=-1 stage 0 with a2=a3=0
        float b0x = a0.x + a1.x, b0y = a0.y + a1.y;
        float b2x = a0.x - a1.x, b2y = a0.y - a1.y;
        float b1x = a0.x + a1.y, b1y = a0.y - a1.x;   // a0 - i a1
        float b3x = a0.x - a1.y, b3y = a0.y + a1.x;   // a0 + i a1
        float2 w = __ldg(&g_tw128[p]);
        float c1 = w.x, s1 = -w.y;
        float c2 = c1 * c1 - s1 * s1, s2 = 2.f * c1 * s1;
        float c3 = c2 * c1 - s2 * s1, s3 = c2 * s1 + s2 * c1;
        int ob = n1l * CRS + (p << 2);
        sA[swz(ob, 0)]     = make_float2(b0x, b0y);
        sA[swz(ob + 1, 0)] = make_float2(b1x * c1 - b1y * s1, b1x * s1 + b1y * c1);
        sA[swz(ob + 2, 0)] = make_float2(b2x * c2 - b2y * s2, b2x * s2 + b2y * c2);
        sA[swz(ob + 3, 0)] = make_float2(b3x * c3 - b3y * s3, b3x * s3 + b3y * c3);
    }
    __syncthreads();
    float2* res = smem_fft4<-1, 128, 16, CRS, 0, 0, 1>(sA, sB, g_tw128);
    float4* out4 = (float4*)(g_bufA + (size_t)sig * CN);
    #pragma unroll
    for (int l = 0; l < 4; ++l) {                  // 1024 float4 stores total
        int idx = threadIdx.x + TPB * l;
        int n1h = idx & 7, k2 = idx >> 3;
        int n1a = n1_0 + 2 * n1h;
        float2 y0 = res[swz((2 * n1h) * CRS + k2, 0)];
        float2 y1 = res[swz((2 * n1h + 1) * CRS + k2, 0)];
        float c0, s0, c1, s1;
        __sincosf(-(6.2831853071795864f / 131072.0f) * (float)(n1a * k2), &s0, &c0);
        __sincosf(-(6.2831853071795864f / 131072.0f) * (float)((n1a + 1) * k2), &s1, &c1);
        out4[(k2 << 9) + ((n1_0 >> 1) + n1h)] =
            make_float4(y0.x * c0 - y0.y * s0, y0.x * s0 + y0.y * c0,
                        y1.x * c1 - y1.y * s1, y1.x * s1 + y1.y * c1);
    }
}

// Fused: forward 1024-pt row FFTs (4 rows) + Hermitian pointwise product
// (packed pairs) + inverse 1024-pt row FFTs + inter-pass twiddle.
// Block x handles conjugate row pair (r0, r1); x==0 handles the self-paired
// rows 0 and 64. y = product-pair index (signals 2y, 2y+1 -> Pa + i*Pb).
// Global loads/stores are float4-vectorized.
__global__ __launch_bounds__(TPB) void conv_prodrow_inv1() {
    __shared__ __align__(16) float2 S[6144];
    int x = blockIdx.x, pr = blockIdx.y;
    int r0 = x;
    int r1 = x ? (128 - x) : 64;
    const float2* Xa = g_bufA + (size_t)(2 * pr) * CN;
    const float2* Xb = Xa + CN;
    int tid = threadIdx.x;
    {
        const float4* Xa0 = (const float4*)(Xa + r0 * 1024);
        const float4* Xa1 = (const float4*)(Xa + r1 * 1024);
        const float4* Xb0 = (const float4*)(Xb + r0 * 1024);
        const float4* Xb1 = (const float4*)(Xb + r1 * 1024);
        float4* S4 = (float4*)S;
        #pragma unroll
        for (int l = 0; l < 2; ++l) {
            int i = tid + TPB * l;                 // 0..511 float4 per row
            S4[i]        = Xa0[i];
            S4[512 + i]  = Xa1[i];
            S4[1024 + i] = Xb0[i];
            S4[1536 + i] = Xb1[i];
        }
    }
    __syncthreads();
    float2* aF = smem_fft4<-1, 1024, 2, 1024, 2, 2>(S, S + 4096, g_tw1024);       // = S+4096
    float2* bF = smem_fft4<-1, 1024, 2, 1024, 2, 2>(S + 2048, S, g_tw1024);       // = S
    float2* P = S + 2048;
    if (x) {
        // cross pair: (r0, k1) <-> (r1, 1023-k1)
        #pragma unroll
        for (int l = 0; l < 4; ++l) {
            int k1 = tid + TPB * l;
            int jm = 1023 - k1;
            float2 Q1, Q2;
            packprod(aF[k1], aF[1024 + jm], bF[k1], bF[1024 + jm], Q1, Q2);
            P[k1] = Q1;
            P[1024 + jm] = Q2;
        }
    } else {
        // row 0: self pairs (k1, (1024-k1)&1023), k1 in [0,512]
        // row 64: self pairs (k1, 1023-k1), k1 in [0,511]
        #pragma unroll
        for (int l = 0; l < 4; ++l) {
            int k1 = tid + TPB * l;
            if (k1 <= 512) {
                int jm = (1024 - k1) & 1023;
                float2 Q1, Q2;
                packprod(aF[k1], aF[jm], bF[k1], bF[jm], Q1, Q2);
                P[k1] = Q1; P[jm] = Q2;
            }
            if (k1 < 512) {
                int jm = 1023 - k1;
                float2 Q1, Q2;
                packprod(aF[1024 + k1], aF[1024 + jm], bF[1024 + k1], bF[1024 + jm], Q1, Q2);
                P[1024 + k1] = Q1; P[1024 + jm] = Q2;
            }
        }
    }
    __syncthreads();
    float2* res = smem_fft4<1, 1024, 2, 1024, 2, 2>(S + 2048, S, g_tw1024);       // = S
    float4* out4 = (float4*)(g_bufB + (size_t)pr * CN);
    const float4* res4 = (const float4*)res;
    #pragma unroll
    for (int l = 0; l < 4; ++l) {                  // 1024 float4 stores total
        int idx = tid + TPB * l;                   // 0..1023
        int row = idx >> 9;
        int jp = idx & 511;                        // n1 pair index
        int n1 = jp << 1;
        int k2v = row ? r1 : r0;
        float4 v = res4[(row << 9) + jp];
        float c0, s0, c1, s1;
        __sincosf((6.2831853071795864f / 131072.0f) * (float)(n1 * k2v), &s0, &c0);
        __sincosf((6.2831853071795864f / 131072.0f) * (float)((n1 + 1) * k2v), &s1, &c1);
        out4[(k2v << 9) + jp] =
            make_float4(v.x * c0 - v.y * s0, v.x * s0 + v.y * c0,
                        v.z * c1 - v.w * s1, v.z * s1 + v.w * c1);
    }
}

__global__ __launch_bounds__(TPB, 6) void conv_inv2(const float* __restrict__ mix) {
    __shared__ __align__(16) float2 sA[16 * CRS], sB[16 * CRS];
    __shared__ float scr[8];
    int n1_0 = blockIdx.x * 16;
    int pr   = blockIdx.y;
    const float4* inb4 = (const float4*)(g_bufB + (size_t)pr * CN);
    #pragma unroll
    for (int l = 0; l < 4; ++l) {                  // 1024 float4 loads total
        int idx = threadIdx.x + TPB * l;
        int n1h = idx & 7, k2 = idx >> 3;
        float4 v = inb4[(k2 << 9) + ((n1_0 >> 1) + n1h)];
        sA[swz((2 * n1h) * CRS + k2, 0)]     = make_float2(v.x, v.y);
        sA[swz((2 * n1h + 1) * CRS + k2, 0)] = make_float2(v.z, v.w);
    }
    __syncthreads();
    // HALF=1: only the low half of each inverse column is needed (n2 <= 62).
    float2* res = smem_fft4<1, 128, 16, CRS, 0, 0, 0, 1>(sA, sB, g_tw128);
    const float* ma = mix + (size_t)(2 * pr) * T_SIG;
    const float* mb = ma + T_SIG;
    float acc = 0.f;
    const float INVN = 1.0f / 131072.0f;
    #pragma unroll
    for (int l = 0; l < 8; ++l) {
        int idx = threadIdx.x + TPB * l;
        int n1l = idx & 15, n2 = idx >> 4;
        int n = n1_0 + n1l + (n2 << 10);
        if (n < T_SIG) {
            float2 v = res[swz(n1l * CRS + n2, 0)];
            acc += fabsf(v.x * INVN - ma[n]) + fabsf(v.y * INVN - mb[n]);
        }
    }
    float b = block_reduce(acc, scr);
    if (threadIdx.x == 0) atomicAdd(&g_acc[10], (double)b);
}

// ---------------------------------------------------------------- finalize

__global__ void finalize_kernel(float* out) {
    const double NT   = 4096000.0;                 // 64 * 64000
    const double CNT  = 64.0 * 513.0 * 251.0;
    const double MELC = 64.0 * 80.0 * 251.0;
    const double SEGC = 1024000.0;                 // 64 * 16000
    double dry_time = g_acc[3] / NT;
    double mag   = g_acc[0] / CNT;
    double phase = 1.0 - g_acc[1] / CNT;
    double freqL = mag + 0.1 * phase;
    double mel   = g_acc[2] / MELC;
    double total_dry = dry_time + 0.5 * freqL + 0.3 * mel;
    double rir_time = g_acc[4] / NT;
    double spars    = g_acc[5] / NT;
    double e0 = g_acc[6] / SEGC, e1 = g_acc[7] / SEGC;
    double e2 = g_acc[8] / SEGC, e3 = g_acc[9] / SEGC;
    double decay = fmax(0.0, e1 - 0.8 * e0) + fmax(0.0, e2 - 0.8 * e1)
                 + fmax(0.0, e3 - 0.8 * e2);
    double total_rir = rir_time + 0.1 * (spars + decay);
    double consist = g_acc[10] / NT;
    out[0] = (float)(3.0 * total_dry + total_rir + 0.2 * consist);
}

// ---------------------------------------------------------------- launch
// Graph fork-join: after init, three independent branches run concurrently —
// stft (s1), time_loss (s2), conv chain (capture stream) — joined via events
// before finalize.

extern "C" void kernel_launch(void* const* d_in, const int* in_sizes, int n_in,
                              void* d_out, int out_size) {
    const float* pd  = (const float*)d_in[0];   // pred_dry
    const float* pr  = (const float*)d_in[1];   // pred_rir
    const float* td  = (const float*)d_in[2];   // target_dry
    const float* tr  = (const float*)d_in[3];   // target_rir
    const float* mix = (const float*)d_in[4];   // mix
    float* out = (float*)d_out;

    init_kernel<<<3, TPB>>>();
    init2_kernel<<<1, 128>>>();

    cudaEventRecord(g_eF, 0);
    cudaStreamWaitEvent(g_s1, g_eF, 0);
    cudaStreamWaitEvent(g_s2, g_eF, 0);

    stft_loss_kernel<<<dim3(NPAIR, NSIG), TPB, 0, g_s1>>>(pd, td);
    time_loss_kernel<<<1024, TPB, 0, g_s2>>>((const float4*)pd, (const float4*)pr,
                                             (const float4*)td, (const float4*)tr);
    conv_fwdA<<<dim3(64, NSIG), TPB>>>(pd, pr);
    conv_prodrow_inv1<<<dim3(64, 32), TPB>>>();
    conv_inv2<<<dim3(64, 32), TPB>>>(mix);

    cudaEventRecord(g_eJ1, g_s1);
    cudaEventRecord(g_eJ2, g_s2);
    cudaStreamWaitEvent(0, g_eJ1, 0);
    cudaStreamWaitEvent(0, g_eJ2, 0);

    finalize_kernel<<<1, 1>>>(out);
}

// round 15
// speedup vs baseline: 1.1474x; 1.0116x over previous
#include <cuda_runtime.h>

#define TPB 256
#define T_SIG 64000
#define NSIG 64
#define NFFT 1024
#define HOP 256
#define NFRAMES 251
#define NPAIR 126   // ceil(NFRAMES/2) frame pairs per signal
#define NFREQ 513
#define NMEL 80
#define CN 131072   // conv FFT length = 2^17 >= 2*T-1 (exact linear convolution)
#define CRS 144     // conv smem row stride; 144>>4=9 odd => g0 swizzle fixes transpose

// global accumulators (double):
// 0 mag, 1 cos, 2 mel, 3 dryL1, 4 rirL1, 5 sparsity, 6..9 e0..e3, 10 consist
__device__ double g_acc[12];
__device__ int    g_mel_i0[NFREQ];
__device__ float  g_mel_w0[NFREQ];
__device__ int    g_mel_i1[NFREQ];
__device__ float  g_mel_w1[NFREQ];
__device__ int4   g_mel_rng[NMEL];             // per-mel gather ranges
__device__ float  g_hann[NFFT];                // hann window (periodic, double init)
__device__ float2 g_tw1024[341];               // radix-4 twiddles, L=1024 (all stages)
__device__ float2 g_tw128[42];                 // radix-4 twiddles, L=128
__device__ __align__(16) float2 g_bufA[(size_t)NSIG * CN];   // 64 MB scratch
__device__ __align__(16) float2 g_bufB[(size_t)NSIG * CN];   // 64 MB scratch

// Streams/events for graph fork-join (created at program init, before the
// harness's memory checkpoints; NonBlocking so the legacy capture stream
// doesn't implicitly serialize them).
static cudaStream_t g_s1, g_s2;
static cudaEvent_t  g_eF, g_eJ1, g_eJ2;
static struct StreamInit {
    StreamInit() {
        cudaStreamCreateWithFlags(&g_s1, cudaStreamNonBlocking);
        cudaStreamCreateWithFlags(&g_s2, cudaStreamNonBlocking);
        cudaEventCreateWithFlags(&g_eF,  cudaEventDisableTiming);
        cudaEventCreateWithFlags(&g_eJ1, cudaEventDisableTiming);
        cudaEventCreateWithFlags(&g_eJ2, cudaEventDisableTiming);
    }
} g_stream_init;

// ---------------------------------------------------------------- utilities

__host__ __device__ constexpr int ilog2c(int n) { return n <= 1 ? 0 : 1 + ilog2c(n / 2); }

__device__ __forceinline__ float fsqrt_approx(float x) {
    float r; asm("sqrt.approx.f32 %0, %1;" : "=f"(r) : "f"(x)); return r;
}

// Bank swizzle per buffer generation (bits [0:4) XOR-keyed from upper bits).
// g=0 fixes stage-0 write pattern (4bf+j) AND stride-144 transpose accesses;
// g=1 fixes stage-1 pattern (q | j<<2 | p<<4); g=2 identity.
__device__ __forceinline__ int swz(int a, int g) {
    if (g == 0) return a ^ ((a >> 4) & 0xF);
    if (g == 1) return a ^ ((a >> 2) & 0xC);
    return a;
}

__device__ __forceinline__ float block_reduce(float v, float* scr) {
    #pragma unroll
    for (int o = 16; o; o >>= 1) v += __shfl_down_sync(0xffffffffu, v, o);
    __syncthreads();
    if ((threadIdx.x & 31) == 0) scr[threadIdx.x >> 5] = v;
    __syncthreads();
    if (threadIdx.x < 32) {
        v = (threadIdx.x < (TPB / 32)) ? scr[threadIdx.x] : 0.f;
        #pragma unroll
        for (int o = 4; o; o >>= 1) v += __shfl_down_sync(0xffffffffu, v, o);
    }
    return v;  // valid on thread 0
}

// Mixed radix-4/2 Stockham DIF FFT over R rows of length L (power of 2) in
// shared memory, row stride RS (float2, 16-aligned). The caller writes the
// input through swz(.,GIN) and reads the natural-order result through
// swz(.,GOUT). SKIP=1: caller already performed radix-4 stage 0 (input must
// be in generation-0 layout). HALF=1: radix-2 tail stores only the low half
// (A+B) of each output pair.
template<int SIGN, int L, int R, int RS, int GIN, int GOUT, int SKIP = 0, int HALF = 0>
__device__ __forceinline__ float2* smem_fft4(float2* a, float2* b,
                                             const float2* __restrict__ tw) {
    constexpr int LOG2L = ilog2c(L);
    constexpr int NS4 = LOG2L >> 1;
    float2 *src = a, *dst = b;
    int ncur = L >> (2 * SKIP), logs = 2 * SKIP, toff = SKIP ? (L >> 2) : 0;
    #pragma unroll
    for (int s = SKIP; s < NS4; ++s) {
        const int rg = (s == 0) ? GIN : (s == 1) ? 0 : (s == 2) ? 1 : 2;
        const int wg = ((s == NS4 - 1) && !(LOG2L & 1)) ? GOUT
                       : (s == 0) ? 0 : (s == 1) ? 1 : 2;
        const int m = ncur >> 2;
        const int Ls = 1 << logs;
        constexpr int NB = R * (L >> 2);
        #pragma unroll
        for (int l = 0; l < NB / TPB; ++l) {
            const int it = threadIdx.x + TPB * l;
            const int row = it >> (LOG2L - 2);
            const int bf  = it & ((L >> 2) - 1);
            const int p = bf >> logs;
            const int q = bf - (p << logs);
            const int base = row * RS + q;
            float2 a0 = src[swz(base + p * Ls, rg)];
            float2 a1 = src[swz(base + (p + m) * Ls, rg)];
            float2 a2 = src[swz(base + (p + 2 * m) * Ls, rg)];
            float2 a3 = src[swz(base + (p + 3 * m) * Ls, rg)];
            float t0x = a0.x + a2.x, t0y = a0.y + a2.y;
            float t1x = a0.x - a2.x, t1y = a0.y - a2.y;
            float t2x = a1.x + a3.x, t2y = a1.y + a3.y;
            float t3x = a1.x - a3.x, t3y = a1.y - a3.y;
            float b0x = t0x + t2x, b0y = t0y + t2y;
            float b2x = t0x - t2x, b2y = t0y - t2y;
            float b1x, b1y, b3x, b3y;
            if (SIGN < 0) {           // b1 = t1 - i t3, b3 = t1 + i t3
                b1x = t1x + t3y; b1y = t1y - t3x;
                b3x = t1x - t3y; b3y = t1y + t3x;
            } else {                  // b1 = t1 + i t3, b3 = t1 - i t3
                b1x = t1x - t3y; b1y = t1y + t3x;
                b3x = t1x + t3y; b3y = t1y - t3x;
            }
            float2 w = __ldg(&tw[toff + p]);
            float c1 = w.x;
            float s1 = (SIGN < 0) ? -w.y : w.y;
            float c2 = c1 * c1 - s1 * s1, s2 = 2.f * c1 * s1;
            float c3 = c2 * c1 - s2 * s1, s3 = c2 * s1 + s2 * c1;
            const int ob = base + ((p << 2) << logs);
            dst[swz(ob, wg)]          = make_float2(b0x, b0y);
            dst[swz(ob + Ls, wg)]     = make_float2(b1x * c1 - b1y * s1, b1x * s1 + b1y * c1);
            dst[swz(ob + 2 * Ls, wg)] = make_float2(b2x * c2 - b2y * s2, b2x * s2 + b2y * c2);
            dst[swz(ob + 3 * Ls, wg)] = make_float2(b3x * c3 - b3y * s3, b3x * s3 + b3y * c3);
        }
        __syncthreads();
        float2* t = src; src = dst; dst = t;
        ncur >>= 2; logs += 2; toff += m;
    }
    if constexpr (LOG2L & 1) {        // final radix-2 stage (twiddle-free, p=0)
        const int rg = (NS4 == 1) ? 0 : (NS4 == 2) ? 1 : 2;
        constexpr int Ls = L >> 1;
        constexpr int NB = R * (L >> 1);
        #pragma unroll
        for (int l = 0; l < NB / TPB; ++l) {
            const int it = threadIdx.x + TPB * l;
            const int row = it >> (LOG2L - 1);
            const int q   = it & ((L >> 1) - 1);
            const int base = row * RS + q;
            float2 A = src[swz(base, rg)];
            float2 B = src[swz(base + Ls, rg)];
            dst[swz(base, GOUT)]      = make_float2(A.x + B.x, A.y + B.y);
            if constexpr (!HALF)
                dst[swz(base + Ls, GOUT)] = make_float2(A.x - B.x, A.y - B.y);
        }
        __syncthreads();
        float2* t = src; src = dst; dst = t;
    }
    return src;
}

// Hermitian unpack of two packed spectra (dry real, rir imag) + complex
// product, producing packed product pair Q1 (at p1) / Q2 (at p2=conj pos).
__device__ __forceinline__ void packprod(float2 A1, float2 A2, float2 B1, float2 B2,
                                         float2& Q1, float2& Q2) {
    float Dar = 0.5f * (A1.x + A2.x), Dai = 0.5f * (A1.y - A2.y);
    float Rar = 0.5f * (A1.y + A2.y), Rai = 0.5f * (A2.x - A1.x);
    float Par = Dar * Rar - Dai * Rai, Pai = Dar * Rai + Dai * Rar;
    float Dbr = 0.5f * (B1.x + B2.x), Dbi = 0.5f * (B1.y - B2.y);
    float Rbr = 0.5f * (B1.y + B2.y), Rbi = 0.5f * (B2.x - B1.x);
    float Pbr = Dbr * Rbr - Dbi * Rbi, Pbi = Dbr * Rbi + Dbi * Rbr;
    Q1 = make_float2(Par - Pbi, Pai + Pbr);   // Pa + i*Pb
    Q2 = make_float2(Par + Pbi, Pbr - Pai);   // conj(Pa) + i*conj(Pb)
}

// ---------------------------------------------------------------- init

__global__ void init_kernel() {
    int t = blockIdx.x * blockDim.x + threadIdx.x;
    if (t < 12) g_acc[t] = 0.0;
    if (t < 341) {                                // L=1024 twiddles (all 5 stages)
        int ncur = 1024, p = t;
        while (p >= (ncur >> 2)) { p -= (ncur >> 2); ncur >>= 2; }
        double ang = 6.283185307179586476925286766559 * (double)p / (double)ncur;
        g_tw1024[t] = make_float2((float)cos(ang), (float)sin(ang));
    }
    if (t < 42) {                                 // L=128 twiddles (3 radix-4 stages)
        int ncur = 128, p = t;
        while (p >= (ncur >> 2)) { p -= (ncur >> 2); ncur >>= 2; }
        double ang = 6.283185307179586476925286766559 * (double)p / (double)ncur;
        g_tw128[t] = make_float2((float)cos(ang), (float)sin(ang));
    }
    if (t < NFFT) {                               // hann window (periodic)
        double wa = 0.5 - 0.5 * cos(6.283185307179586476925286766559 * (double)t / 1024.0);
        g_hann[t] = (float)wa;
    }
    if (t < NFREQ) {
        double freq   = (double)t * (8000.0 / 512.0);
        double melmax = 2595.0 * log10(1.0 + 8000.0 / 700.0);
        double mstep  = melmax / 81.0;
        double mval   = 2595.0 * log10(1.0 + freq / 700.0);
        int i = (int)floor(mval / mstep);
        if (i < 0) i = 0;
        if (i > 81) i = 81;
        double f_lo = 700.0 * (pow(10.0, ((double)i * mstep) / 2595.0) - 1.0);
        double f_hi = 700.0 * (pow(10.0, ((double)(i + 1) * mstep) / 2595.0) - 1.0);
        double inv  = 1.0 / (f_hi - f_lo);
        int i0 = -1, i1 = -1; float w0 = 0.f, w1 = 0.f;
        if (i <= 79)           { i0 = i;     w0 = (float)fmax(0.0, (freq - f_lo) * inv); }
        if (i >= 1 && i <= 80) { i1 = i - 1; w1 = (float)fmax(0.0, (f_hi - freq) * inv); }
        g_mel_i0[t] = i0; g_mel_w0[t] = w0;
        g_mel_i1[t] = i1; g_mel_w1[t] = w1;
    }
}

// Second init pass: per-mel contiguous gather ranges (i0[k], i1[k] are
// monotone in k, so each mel's membership is a contiguous bin range).
__global__ void init2_kernel() {
    int m = threadIdx.x;
    if (m >= NMEL) return;
    int s0 = NFREQ, e0 = 0, s1 = NFREQ, e1 = 0;
    for (int k = 0; k < NFREQ; ++k) {
        if (g_mel_i0[k] == m) { if (k < s0) s0 = k; if (k + 1 > e0) e0 = k + 1; }
        if (g_mel_i1[k] == m) { if (k < s1) s1 = k; if (k + 1 > e1) e1 = k + 1; }
    }
    g_mel_rng[m] = make_int4(s0, e0, s1, e1);
}

// ---------------------------------------------------------------- STFT losses
// One block per (signal, frame PAIR): two 1024-pt FFTs batched (R=2) share
// all barriers / reductions / atomics. Radix-4 stage 0 is FUSED into the
// windowed global load (SKIP=1). Hann comes from a table; sqrt/log use
// single-MUFU approximations (rel err ~1e-7 vs 1e-3 budget). The last pair's
// second frame (251) is zero-filled and contributes exactly 0.

__global__ __launch_bounds__(TPB, 5) void stft_loss_kernel(const float* __restrict__ pd,
                                                           const float* __restrict__ td) {
    __shared__ float2 sA[2 * NFFT], sB[2 * NFFT];
    __shared__ float s_mel;
    __shared__ float scr[8];
    int f0  = blockIdx.x * 2;
    int sig = blockIdx.y;
    const float* p = pd + (size_t)sig * T_SIG;
    const float* q = td + (size_t)sig * T_SIG;
    int tid = threadIdx.x;

    if (tid == 0) s_mel = 0.f;
    #pragma unroll
    for (int l = 0; l < 2; ++l) {                  // 512 fused stage-0 butterflies
        int idx = tid + TPB * l;
        int fr = idx >> 8, pb = idx & 255;         // frame-of-pair, butterfly index
        int f = f0 + fr;
        float2 a0, a1, a2, a3;
        if (f < NFRAMES) {
            int base_t = f * HOP - 512;
            #pragma unroll
            for (int j = 0; j < 4; ++j) {
                int jj = pb + (j << 8);
                int t0 = base_t + jj;              // reflect padding (center=True)
                if (t0 < 0) t0 = -t0;
                else if (t0 >= T_SIG) t0 = 2 * T_SIG - 2 - t0;
                float w = g_hann[jj];
                float2 v = make_float2(p[t0] * w, q[t0] * w);
                if (j == 0) a0 = v; else if (j == 1) a1 = v;
                else if (j == 2) a2 = v; else a3 = v;
            }
        } else {
            a0 = a1 = a2 = a3 = make_float2(0.f, 0.f);
        }
        // SIGN=-1 radix-4 stage 0
        float t0x = a0.x + a2.x, t0y = a0.y + a2.y;
        float t1x = a0.x - a2.x, t1y = a0.y - a2.y;
        float t2x = a1.x + a3.x, t2y = a1.y + a3.y;
        float t3x = a1.x - a3.x, t3y = a1.y - a3.y;
        float b0x = t0x + t2x, b0y = t0y + t2y;
        float b2x = t0x - t2x, b2y = t0y - t2y;
        float b1x = t1x + t3y, b1y = t1y - t3x;    // t1 - i t3
        float b3x = t1x - t3y, b3y = t1y + t3x;    // t1 + i t3
        float2 w = __ldg(&g_tw1024[pb]);
        float c1 = w.x, s1 = -w.y;
        float c2 = c1 * c1 - s1 * s1, s2 = 2.f * c1 * s1;
        float c3 = c2 * c1 - s2 * s1, s3 = c2 * s1 + s2 * c1;
        int ob = fr * NFFT + (pb << 2);
        sA[swz(ob, 0)]     = make_float2(b0x, b0y);
        sA[swz(ob + 1, 0)] = make_float2(b1x * c1 - b1y * s1, b1x * s1 + b1y * c1);
        sA[swz(ob + 2, 0)] = make_float2(b2x * c2 - b2y * s2, b2x * s2 + b2y * c2);
        sA[swz(ob + 3, 0)] = make_float2(b3x * c3 - b3y * s3, b3x * s3 + b3y * c3);
    }
    __syncthreads();

    // 4 remaining radix-4 stages (SKIP=1); result parity: back in sA.
    float2* res = smem_fft4<-1, NFFT, 2, NFFT, 0, 2, 1>(sA, sB, g_tw1024);
    float2* cache = (res == sA) ? sB : sA;         // free buffer for power cache

    const float SCL2 = 0.0026041666666666665f;     // 1/(sum hann^2) = 1/384
    float magacc = 0.f, cosacc = 0.f;
    #pragma unroll
    for (int fr = 0; fr < 2; ++fr) {
        float2* rf = res + fr * NFFT;
        float2* cf = cache + fr * NFFT;
        for (int k = tid; k < NFREQ; k += TPB) {
            float2 Xk = rf[k];
            float2 Xm = rf[(NFFT - k) & (NFFT - 1)];
            float Pr = 0.5f * (Xk.x + Xm.x);
            float Pi = 0.5f * (Xk.y - Xm.y);
            float Tr = 0.5f * (Xk.y + Xm.y);
            float Ti = 0.5f * (Xm.x - Xk.x);
            float pp = (Pr * Pr + Pi * Pi) * SCL2;
            float tp = (Tr * Tr + Ti * Ti) * SCL2;
            magacc += fabsf(fsqrt_approx(pp) - fsqrt_approx(tp));
            float dot = (Pr * Tr + Pi * Ti) * SCL2;
            cosacc += dot * rsqrtf(fmaxf(pp * tp, 1e-36f));  // cos(dphi)
            cf[k] = make_float2(pp, tp);           // cache powers for mel gather
        }
    }
    __syncthreads();
    if (tid < 2 * NMEL) {                          // gather: (frame, mel) per thread
        int fr = tid / NMEL;
        int m  = tid - fr * NMEL;
        const float2* cf = cache + fr * NFFT;
        int4 r = g_mel_rng[m];
        float mp_ = 0.f, mt_ = 0.f;
        for (int k = r.x; k < r.y; ++k) {
            float w = g_mel_w0[k]; float2 v = cf[k];
            mp_ += v.x * w; mt_ += v.y * w;
        }
        for (int k = r.z; k < r.w; ++k) {
            float w = g_mel_w1[k]; float2 v = cf[k];
            mp_ += v.x * w; mt_ += v.y * w;
        }
        float d = fabsf(__logf(mp_ + 1e-8f) - __logf(mt_ + 1e-8f));
        atomicAdd(&s_mel, d);
    }
    float bm = block_reduce(magacc, scr);
    float bc = block_reduce(cosacc, scr);
    if (tid == 0) {
        atomicAdd(&g_acc[0], (double)bm);
        atomicAdd(&g_acc[1], (double)bc);
        atomicAdd(&g_acc[2], (double)s_mel);
    }
}

// ---------------------------------------------------------------- time-domain

__global__ __launch_bounds__(TPB) void time_loss_kernel(const float4* __restrict__ pd,
                                                        const float4* __restrict__ pr,
                                                        const float4* __restrict__ td,
                                                        const float4* __restrict__ tr) {
    __shared__ float segsum[4];
    __shared__ float scr[8];
    if (threadIdx.x < 4) segsum[threadIdx.x] = 0.f;
    __syncthreads();
    float dry = 0.f, rir = 0.f, spa = 0.f;
    const int N4 = (NSIG * T_SIG) / 4;             // 1,024,000
    int stride = gridDim.x * TPB;
    for (int i = blockIdx.x * TPB + threadIdx.x; i < N4; i += stride) {
        float4 a = pd[i], b = td[i], c = pr[i], d = tr[i];
        dry += fabsf(a.x-b.x) + fabsf(a.y-b.y) + fabsf(a.z-b.z) + fabsf(a.w-b.w);
        rir += fabsf(c.x-d.x) + fabsf(c.y-d.y) + fabsf(c.z-d.z) + fabsf(c.w-d.w);
        spa += fabsf(c.x) + fabsf(c.y) + fabsf(c.z) + fabsf(c.w);
        float sq = c.x*c.x + c.y*c.y + c.z*c.z + c.w*c.w;
        #pragma unroll
        for (int o = 16; o; o >>= 1) sq += __shfl_down_sync(0xffffffffu, sq, o);
        if ((threadIdx.x & 31) == 0) {
            int t0 = (i * 4) % T_SIG;              // warp-uniform segment
            atomicAdd(&segsum[t0 / 16000], sq);
        }
    }
    float bd = block_reduce(dry, scr);
    float br = block_reduce(rir, scr);
    float bs = block_reduce(spa, scr);
    __syncthreads();
    if (threadIdx.x == 0) {
        atomicAdd(&g_acc[3], (double)bd);
        atomicAdd(&g_acc[4], (double)br);
        atomicAdd(&g_acc[5], (double)bs);
    }
    if (threadIdx.x < 4) atomicAdd(&g_acc[6 + threadIdx.x], (double)segsum[threadIdx.x]);
}

// ---------------------------------------------------------------- consistency
// 2^17-pt four-step FFT. n = n1 + 1024*n2, k = k2 + 128*k1. Spectra stored
// permuted at p = k2*1024 + k1. dry packed as real, rir as imag (forward);
// two Hermitian product spectra packed per inverse FFT.

// Column FFT with radix-4 stage 0 fused into the global load: the upper half
// of every column (n2 >= 63) is structurally zero (n >= T_SIG), so stage 0
// degenerates to a0 +/- a1 and a0 -/+ i*a1 with only two loads. Output store
// vectorized to float4 (2 consecutive n1 per thread); the paired transposed
// smem reads stay conflict-free under the g0 swizzle.
__global__ __launch_bounds__(TPB, 6) void conv_fwdA(const float* __restrict__ dry,
                                                    const float* __restrict__ rir) {
    __shared__ __align__(16) float2 sA[16 * CRS], sB[16 * CRS];
    int n1_0 = blockIdx.x * 16;
    int sig  = blockIdx.y;
    const float* d = dry + (size_t)sig * T_SIG;
    const float* r = rir + (size_t)sig * T_SIG;
    #pragma unroll
    for (int l = 0; l < 2; ++l) {                 // 512 stage-0 butterflies
        int idx = threadIdx.x + TPB * l;
        int n1l = idx & 15, p = idx >> 4;          // p in [0,32)
        int n1 = n1_0 + n1l;
        float2 a0 = make_float2(d[n1 + (p << 10)], r[n1 + (p << 10)]);
        int nb = n1 + ((p + 32) << 10);
        float2 a1 = make_float2(0.f, 0.f);
        if (nb < T_SIG) { a1.x = d[nb]; a1.y = r[nb]; }
        // SIGN=-1 stage 0 with a2=a3=0
        float b0x = a0.x + a1.x, b0y = a0.y + a1.y;
        float b2x = a0.x - a1.x, b2y = a0.y - a1.y;
        float b1x = a0.x + a1.y, b1y = a0.y - a1.x;   // a0 - i a1
        float b3x = a0.x - a1.y, b3y = a0.y + a1.x;   // a0 + i a1
        float2 w = __ldg(&g_tw128[p]);
        float c1 = w.x, s1 = -w.y;
        float c2 = c1 * c1 - s1 * s1, s2 = 2.f * c1 * s1;
        float c3 = c2 * c1 - s2 * s1, s3 = c2 * s1 + s2 * c1;
        int ob = n1l * CRS + (p << 2);
        sA[swz(ob, 0)]     = make_float2(b0x, b0y);
        sA[swz(ob + 1, 0)] = make_float2(b1x * c1 - b1y * s1, b1x * s1 + b1y * c1);
        sA[swz(ob + 2, 0)] = make_float2(b2x * c2 - b2y * s2, b2x * s2 + b2y * c2);
        sA[swz(ob + 3, 0)] = make_float2(b3x * c3 - b3y * s3, b3x * s3 + b3y * c3);
    }
    __syncthreads();
    float2* res = smem_fft4<-1, 128, 16, CRS, 0, 0, 1>(sA, sB, g_tw128);
    float4* out4 = (float4*)(g_bufA + (size_t)sig * CN);
    #pragma unroll
    for (int l = 0; l < 4; ++l) {                  // 1024 float4 stores total
        int idx = threadIdx.x + TPB * l;
        int n1h = idx & 7, k2 = idx >> 3;
        int n1a = n1_0 + 2 * n1h;
        float2 y0 = res[swz((2 * n1h) * CRS + k2, 0)];
        float2 y1 = res[swz((2 * n1h + 1) * CRS + k2, 0)];
        float c0, s0, c1, s1;
        __sincosf(-(6.2831853071795864f / 131072.0f) * (float)(n1a * k2), &s0, &c0);
        __sincosf(-(6.2831853071795864f / 131072.0f) * (float)((n1a + 1) * k2), &s1, &c1);
        out4[(k2 << 9) + ((n1_0 >> 1) + n1h)] =
            make_float4(y0.x * c0 - y0.y * s0, y0.x * s0 + y0.y * c0,
                        y1.x * c1 - y1.y * s1, y1.x * s1 + y1.y * c1);
    }
}

// Fused: forward 1024-pt row FFTs (4 rows) + Hermitian pointwise product
// (packed pairs) + inverse 1024-pt row FFTs + inter-pass twiddle.
// Block x handles conjugate row pair (r0, r1); x==0 handles the self-paired
// rows 0 and 64. y = product-pair index (signals 2y, 2y+1 -> Pa + i*Pb).
// Global loads/stores are float4-vectorized.
__global__ __launch_bounds__(TPB) void conv_prodrow_inv1() {
    __shared__ __align__(16) float2 S[6144];
    int x = blockIdx.x, pr = blockIdx.y;
    int r0 = x;
    int r1 = x ? (128 - x) : 64;
    const float2* Xa = g_bufA + (size_t)(2 * pr) * CN;
    const float2* Xb = Xa + CN;
    int tid = threadIdx.x;
    {
        const float4* Xa0 = (const float4*)(Xa + r0 * 1024);
        const float4* Xa1 = (const float4*)(Xa + r1 * 1024);
        const float4* Xb0 = (const float4*)(Xb + r0 * 1024);
        const float4* Xb1 = (const float4*)(Xb + r1 * 1024);
        float4* S4 = (float4*)S;
        #pragma unroll
        for (int l = 0; l < 2; ++l) {
            int i = tid + TPB * l;                 // 0..511 float4 per row
            S4[i]        = Xa0[i];
            S4[512 + i]  = Xa1[i];
            S4[1024 + i] = Xb0[i];
            S4[1536 + i] = Xb1[i];
        }
    }
    __syncthreads();
    float2* aF = smem_fft4<-1, 1024, 2, 1024, 2, 2>(S, S + 4096, g_tw1024);       // = S+4096
    float2* bF = smem_fft4<-1, 1024, 2, 1024, 2, 2>(S + 2048, S, g_tw1024);       // = S
    float2* P = S + 2048;
    if (x) {
        // cross pair: (r0, k1) <-> (r1, 1023-k1)
        #pragma unroll
        for (int l = 0; l < 4; ++l) {
            int k1 = tid + TPB * l;
            int jm = 1023 - k1;
            float2 Q1, Q2;
            packprod(aF[k1], aF[1024 + jm], bF[k1], bF[1024 + jm], Q1, Q2);
            P[k1] = Q1;
            P[1024 + jm] = Q2;
        }
    } else {
        // row 0: self pairs (k1, (1024-k1)&1023), k1 in [0,512]
        // row 64: self pairs (k1, 1023-k1), k1 in [0,511]
        #pragma unroll
        for (int l = 0; l < 4; ++l) {
            int k1 = tid + TPB * l;
            if (k1 <= 512) {
                int jm = (1024 - k1) & 1023;
                float2 Q1, Q2;
                packprod(aF[k1], aF[jm], bF[k1], bF[jm], Q1, Q2);
                P[k1] = Q1; P[jm] = Q2;
            }
            if (k1 < 512) {
                int jm = 1023 - k1;
                float2 Q1, Q2;
                packprod(aF[1024 + k1], aF[1024 + jm], bF[1024 + k1], bF[1024 + jm], Q1, Q2);
                P[1024 + k1] = Q1; P[1024 + jm] = Q2;
            }
        }
    }
    __syncthreads();
    float2* res = smem_fft4<1, 1024, 2, 1024, 2, 2>(S + 2048, S, g_tw1024);       // = S
    float4* out4 = (float4*)(g_bufB + (size_t)pr * CN);
    const float4* res4 = (const float4*)res;
    #pragma unroll
    for (int l = 0; l < 4; ++l) {                  // 1024 float4 stores total
        int idx = tid + TPB * l;                   // 0..1023
        int row = idx >> 9;
        int jp = idx & 511;                        // n1 pair index
        int n1 = jp << 1;
        int k2v = row ? r1 : r0;
        float4 v = res4[(row << 9) + jp];
        float c0, s0, c1, s1;
        __sincosf((6.2831853071795864f / 131072.0f) * (float)(n1 * k2v), &s0, &c0);
        __sincosf((6.2831853071795864f / 131072.0f) * (float)((n1 + 1) * k2v), &s1, &c1);
        out4[(k2v << 9) + jp] =
            make_float4(v.x * c0 - v.y * s0, v.x * s0 + v.y * c0,
                        v.z * c1 - v.w * s1, v.z * s1 + v.w * c1);
    }
}

__global__ __launch_bounds__(TPB, 6) void conv_inv2(const float* __restrict__ mix) {
    __shared__ __align__(16) float2 sA[16 * CRS], sB[16 * CRS];
    __shared__ float scr[8];
    int n1_0 = blockIdx.x * 16;
    int pr   = blockIdx.y;
    const float4* inb4 = (const float4*)(g_bufB + (size_t)pr * CN);
    #pragma unroll
    for (int l = 0; l < 4; ++l) {                  // 1024 float4 loads total
        int idx = threadIdx.x + TPB * l;
        int n1h = idx & 7, k2 = idx >> 3;
        float4 v = inb4[(k2 << 9) + ((n1_0 >> 1) + n1h)];
        sA[swz((2 * n1h) * CRS + k2, 0)]     = make_float2(v.x, v.y);
        sA[swz((2 * n1h + 1) * CRS + k2, 0)] = make_float2(v.z, v.w);
    }
    __syncthreads();
    // HALF=1: only the low half of each inverse column is needed (n2 <= 62).
    float2* res = smem_fft4<1, 128, 16, CRS, 0, 0, 0, 1>(sA, sB, g_tw128);
    const float* ma = mix + (size_t)(2 * pr) * T_SIG;
    const float* mb = ma + T_SIG;
    float acc = 0.f;
    const float INVN = 1.0f / 131072.0f;
    #pragma unroll
    for (int l = 0; l < 8; ++l) {
        int idx = threadIdx.x + TPB * l;
        int n1l = idx & 15, n2 = idx >> 4;
        int n = n1_0 + n1l + (n2 << 10);
        if (n < T_SIG) {
            float2 v = res[swz(n1l * CRS + n2, 0)];
            acc += fabsf(v.x * INVN - ma[n]) + fabsf(v.y * INVN - mb[n]);
        }
    }
    float b = block_reduce(acc, scr);
    if (threadIdx.x == 0) atomicAdd(&g_acc[10], (double)b);
}

// ---------------------------------------------------------------- finalize

__global__ void finalize_kernel(float* out) {
    const double NT   = 4096000.0;                 // 64 * 64000
    const double CNT  = 64.0 * 513.0 * 251.0;
    const double MELC = 64.0 * 80.0 * 251.0;
    const double SEGC = 1024000.0;                 // 64 * 16000
    double dry_time = g_acc[3] / NT;
    double mag   = g_acc[0] / CNT;
    double phase = 1.0 - g_acc[1] / CNT;
    double freqL = mag + 0.1 * phase;
    double mel   = g_acc[2] / MELC;
    double total_dry = dry_time + 0.5 * freqL + 0.3 * mel;
    double rir_time = g_acc[4] / NT;
    double spars    = g_acc[5] / NT;
    double e0 = g_acc[6] / SEGC, e1 = g_acc[7] / SEGC;
    double e2 = g_acc[8] / SEGC, e3 = g_acc[9] / SEGC;
    double decay = fmax(0.0, e1 - 0.8 * e0) + fmax(0.0, e2 - 0.8 * e1)
                 + fmax(0.0, e3 - 0.8 * e2);
    double total_rir = rir_time + 0.1 * (spars + decay);
    double consist = g_acc[10] / NT;
    out[0] = (float)(3.0 * total_dry + total_rir + 0.2 * consist);
}

// ---------------------------------------------------------------- launch
// Graph fork-join: after init, three independent branches run concurrently —
// stft (s1), time_loss (s2), conv chain (capture stream) — joined via events
// before finalize.

extern "C" void kernel_launch(void* const* d_in, const int* in_sizes, int n_in,
                              void* d_out, int out_size) {
    const float* pd  = (const float*)d_in[0];   // pred_dry
    const float* pr  = (const float*)d_in[1];   // pred_rir
    const float* td  = (const float*)d_in[2];   // target_dry
    const float* tr  = (const float*)d_in[3];   // target_rir
    const float* mix = (const float*)d_in[4];   // mix
    float* out = (float*)d_out;

    init_kernel<<<4, TPB>>>();
    init2_kernel<<<1, 128>>>();

    cudaEventRecord(g_eF, 0);
    cudaStreamWaitEvent(g_s1, g_eF, 0);
    cudaStreamWaitEvent(g_s2, g_eF, 0);

    stft_loss_kernel<<<dim3(NPAIR, NSIG), TPB, 0, g_s1>>>(pd, td);
    time_loss_kernel<<<1024, TPB, 0, g_s2>>>((const float4*)pd, (const float4*)pr,
                                             (const float4*)td, (const float4*)tr);
    conv_fwdA<<<dim3(64, NSIG), TPB>>>(pd, pr);
    conv_prodrow_inv1<<<dim3(64, 32), TPB>>>();
    conv_inv2<<<dim3(64, 32), TPB>>>(mix);

    cudaEventRecord(g_eJ1, g_s1);
    cudaEventRecord(g_eJ2, g_s2);
    cudaStreamWaitEvent(0, g_eJ1, 0);
    cudaStreamWaitEvent(0, g_eJ2, 0);

    finalize_kernel<<<1, 1>>>(out);
}

// round 16
// speedup vs baseline: 1.1759x; 1.0249x over previous
#include <cuda_runtime.h>

#define TPB 256
#define T_SIG 64000
#define NSIG 64
#define NFFT 1024
#define HOP 256
#define NFRAMES 251
#define NPAIR 126   // ceil(NFRAMES/2) frame pairs per signal
#define NFREQ 513
#define NMEL 80
#define CN 131072   // conv FFT length = 2^17 >= 2*T-1 (exact linear convolution)
#define CRS 144     // conv smem row stride; 144>>4=9 odd => g0 swizzle fixes transpose

// global accumulators (double):
// 0 mag, 1 cos, 2 mel, 3 dryL1, 4 rirL1, 5 sparsity, 6..9 e0..e3, 10 consist
__device__ double g_acc[12];
__device__ int    g_mel_i0[NFREQ];
__device__ float  g_mel_w0[NFREQ];
__device__ int    g_mel_i1[NFREQ];
__device__ float  g_mel_w1[NFREQ];
__device__ int4   g_mel_rng[NMEL];             // per-mel gather ranges
__device__ float  g_hann[NFFT];                // hann window (periodic, double init)
__device__ float2 g_tw1024[341];               // radix-4 twiddles, L=1024 (all stages)
__device__ float2 g_tw128[42];                 // radix-4 twiddles, L=128
__device__ __align__(16) float2 g_bufA[(size_t)NSIG * CN];   // 64 MB scratch
__device__ __align__(16) float2 g_bufB[(size_t)NSIG * CN];   // 64 MB scratch

// Streams/events for graph fork-join (created at program init, before the
// harness's memory checkpoints; NonBlocking so the legacy capture stream
// doesn't implicitly serialize them).
static cudaStream_t g_s1, g_s2;
static cudaEvent_t  g_eF, g_eJ1, g_eJ2;
static struct StreamInit {
    StreamInit() {
        cudaStreamCreateWithFlags(&g_s1, cudaStreamNonBlocking);
        cudaStreamCreateWithFlags(&g_s2, cudaStreamNonBlocking);
        cudaEventCreateWithFlags(&g_eF,  cudaEventDisableTiming);
        cudaEventCreateWithFlags(&g_eJ1, cudaEventDisableTiming);
        cudaEventCreateWithFlags(&g_eJ2, cudaEventDisableTiming);
    }
} g_stream_init;

// ---------------------------------------------------------------- utilities

__host__ __device__ constexpr int ilog2c(int n) { return n <= 1 ? 0 : 1 + ilog2c(n / 2); }

__device__ __forceinline__ float fsqrt_approx(float x) {
    float r; asm("sqrt.approx.f32 %0, %1;" : "=f"(r) : "f"(x)); return r;
}

// Bank swizzle per buffer generation (bits [0:4) XOR-keyed from upper bits).
// g=0 fixes stage-0 write pattern (4bf+j) AND stride-144 transpose accesses;
// g=1 fixes stage-1 pattern (q | j<<2 | p<<4); g=2 identity.
__device__ __forceinline__ int swz(int a, int g) {
    if (g == 0) return a ^ ((a >> 4) & 0xF);
    if (g == 1) return a ^ ((a >> 2) & 0xC);
    return a;
}

__device__ __forceinline__ float block_reduce(float v, float* scr) {
    #pragma unroll
    for (int o = 16; o; o >>= 1) v += __shfl_down_sync(0xffffffffu, v, o);
    __syncthreads();
    if ((threadIdx.x & 31) == 0) scr[threadIdx.x >> 5] = v;
    __syncthreads();
    if (threadIdx.x < 32) {
        v = (threadIdx.x < (TPB / 32)) ? scr[threadIdx.x] : 0.f;
        #pragma unroll
        for (int o = 4; o; o >>= 1) v += __shfl_down_sync(0xffffffffu, v, o);
    }
    return v;  // valid on thread 0
}

// Mixed radix-4/2 Stockham DIF FFT over R rows of length L (power of 2) in
// shared memory, row stride RS (float2, 16-aligned). The caller writes the
// input through swz(.,GIN) and reads the natural-order result through
// swz(.,GOUT). SKIP=1: caller already performed radix-4 stage 0 (input must
// be in generation-0 layout). HALF=1: radix-2 tail stores only the low half
// (A+B) of each output pair.
template<int SIGN, int L, int R, int RS, int GIN, int GOUT, int SKIP = 0, int HALF = 0>
__device__ __forceinline__ float2* smem_fft4(float2* a, float2* b,
                                             const float2* __restrict__ tw) {
    constexpr int LOG2L = ilog2c(L);
    constexpr int NS4 = LOG2L >> 1;
    float2 *src = a, *dst = b;
    int ncur = L >> (2 * SKIP), logs = 2 * SKIP, toff = SKIP ? (L >> 2) : 0;
    #pragma unroll
    for (int s = SKIP; s < NS4; ++s) {
        const int rg = (s == 0) ? GIN : (s == 1) ? 0 : (s == 2) ? 1 : 2;
        const int wg = ((s == NS4 - 1) && !(LOG2L & 1)) ? GOUT
                       : (s == 0) ? 0 : (s == 1) ? 1 : 2;
        const int m = ncur >> 2;
        const int Ls = 1 << logs;
        constexpr int NB = R * (L >> 2);
        #pragma unroll
        for (int l = 0; l < NB / TPB; ++l) {
            const int it = threadIdx.x + TPB * l;
            const int row = it >> (LOG2L - 2);
            const int bf  = it & ((L >> 2) - 1);
            const int p = bf >> logs;
            const int q = bf - (p << logs);
            const int base = row * RS + q;
            float2 a0 = src[swz(base + p * Ls, rg)];
            float2 a1 = src[swz(base + (p + m) * Ls, rg)];
            float2 a2 = src[swz(base + (p + 2 * m) * Ls, rg)];
            float2 a3 = src[swz(base + (p + 3 * m) * Ls, rg)];
            float t0x = a0.x + a2.x, t0y = a0.y + a2.y;
            float t1x = a0.x - a2.x, t1y = a0.y - a2.y;
            float t2x = a1.x + a3.x, t2y = a1.y + a3.y;
            float t3x = a1.x - a3.x, t3y = a1.y - a3.y;
            float b0x = t0x + t2x, b0y = t0y + t2y;
            float b2x = t0x - t2x, b2y = t0y - t2y;
            float b1x, b1y, b3x, b3y;
            if (SIGN < 0) {           // b1 = t1 - i t3, b3 = t1 + i t3
                b1x = t1x + t3y; b1y = t1y - t3x;
                b3x = t1x - t3y; b3y = t1y + t3x;
            } else {                  // b1 = t1 + i t3, b3 = t1 - i t3
                b1x = t1x - t3y; b1y = t1y + t3x;
                b3x = t1x + t3y; b3y = t1y - t3x;
            }
            float2 w = __ldg(&tw[toff + p]);
            float c1 = w.x;
            float s1 = (SIGN < 0) ? -w.y : w.y;
            float c2 = c1 * c1 - s1 * s1, s2 = 2.f * c1 * s1;
            float c3 = c2 * c1 - s2 * s1, s3 = c2 * s1 + s2 * c1;
            const int ob = base + ((p << 2) << logs);
            dst[swz(ob, wg)]          = make_float2(b0x, b0y);
            dst[swz(ob + Ls, wg)]     = make_float2(b1x * c1 - b1y * s1, b1x * s1 + b1y * c1);
            dst[swz(ob + 2 * Ls, wg)] = make_float2(b2x * c2 - b2y * s2, b2x * s2 + b2y * c2);
            dst[swz(ob + 3 * Ls, wg)] = make_float2(b3x * c3 - b3y * s3, b3x * s3 + b3y * c3);
        }
        __syncthreads();
        float2* t = src; src = dst; dst = t;
        ncur >>= 2; logs += 2; toff += m;
    }
    if constexpr (LOG2L & 1) {        // final radix-2 stage (twiddle-free, p=0)
        const int rg = (NS4 == 1) ? 0 : (NS4 == 2) ? 1 : 2;
        constexpr int Ls = L >> 1;
        constexpr int NB = R * (L >> 1);
        #pragma unroll
        for (int l = 0; l < NB / TPB; ++l) {
            const int it = threadIdx.x + TPB * l;
            const int row = it >> (LOG2L - 1);
            const int q   = it & ((L >> 1) - 1);
            const int base = row * RS + q;
            float2 A = src[swz(base, rg)];
            float2 B = src[swz(base + Ls, rg)];
            dst[swz(base, GOUT)]      = make_float2(A.x + B.x, A.y + B.y);
            if constexpr (!HALF)
                dst[swz(base + Ls, GOUT)] = make_float2(A.x - B.x, A.y - B.y);
        }
        __syncthreads();
        float2* t = src; src = dst; dst = t;
    }
    return src;
}

// Hermitian unpack of two packed spectra (dry real, rir imag) + complex
// product, producing packed product pair Q1 (at p1) / Q2 (at p2=conj pos).
__device__ __forceinline__ void packprod(float2 A1, float2 A2, float2 B1, float2 B2,
                                         float2& Q1, float2& Q2) {
    float Dar = 0.5f * (A1.x + A2.x), Dai = 0.5f * (A1.y - A2.y);
    float Rar = 0.5f * (A1.y + A2.y), Rai = 0.5f * (A2.x - A1.x);
    float Par = Dar * Rar - Dai * Rai, Pai = Dar * Rai + Dai * Rar;
    float Dbr = 0.5f * (B1.x + B2.x), Dbi = 0.5f * (B1.y - B2.y);
    float Rbr = 0.5f * (B1.y + B2.y), Rbi = 0.5f * (B2.x - B1.x);
    float Pbr = Dbr * Rbr - Dbi * Rbi, Pbi = Dbr * Rbi + Dbi * Rbr;
    Q1 = make_float2(Par - Pbi, Pai + Pbr);   // Pa + i*Pb
    Q2 = make_float2(Par + Pbi, Pbr - Pai);   // conj(Pa) + i*conj(Pb)
}

// ---------------------------------------------------------------- init

__global__ void init_kernel() {
    int t = blockIdx.x * blockDim.x + threadIdx.x;
    if (t < 12) g_acc[t] = 0.0;
    if (t < 341) {                                // L=1024 twiddles (all 5 stages)
        int ncur = 1024, p = t;
        while (p >= (ncur >> 2)) { p -= (ncur >> 2); ncur >>= 2; }
        double ang = 6.283185307179586476925286766559 * (double)p / (double)ncur;
        g_tw1024[t] = make_float2((float)cos(ang), (float)sin(ang));
    }
    if (t < 42) {                                 // L=128 twiddles (3 radix-4 stages)
        int ncur = 128, p = t;
        while (p >= (ncur >> 2)) { p -= (ncur >> 2); ncur >>= 2; }
        double ang = 6.283185307179586476925286766559 * (double)p / (double)ncur;
        g_tw128[t] = make_float2((float)cos(ang), (float)sin(ang));
    }
    if (t < NFFT) {                               // hann window (periodic)
        double wa = 0.5 - 0.5 * cos(6.283185307179586476925286766559 * (double)t / 1024.0);
        g_hann[t] = (float)wa;
    }
    if (t < NFREQ) {
        double freq   = (double)t * (8000.0 / 512.0);
        double melmax = 2595.0 * log10(1.0 + 8000.0 / 700.0);
        double mstep  = melmax / 81.0;
        double mval   = 2595.0 * log10(1.0 + freq / 700.0);
        int i = (int)floor(mval / mstep);
        if (i < 0) i = 0;
        if (i > 81) i = 81;
        double f_lo = 700.0 * (pow(10.0, ((double)i * mstep) / 2595.0) - 1.0);
        double f_hi = 700.0 * (pow(10.0, ((double)(i + 1) * mstep) / 2595.0) - 1.0);
        double inv  = 1.0 / (f_hi - f_lo);
        int i0 = -1, i1 = -1; float w0 = 0.f, w1 = 0.f;
        if (i <= 79)           { i0 = i;     w0 = (float)fmax(0.0, (freq - f_lo) * inv); }
        if (i >= 1 && i <= 80) { i1 = i - 1; w1 = (float)fmax(0.0, (f_hi - freq) * inv); }
        g_mel_i0[t] = i0; g_mel_w0[t] = w0;
        g_mel_i1[t] = i1; g_mel_w1[t] = w1;
    }
}

// Second init pass: per-mel contiguous gather ranges (i0[k], i1[k] are
// monotone in k, so each mel's membership is a contiguous bin range).
__global__ void init2_kernel() {
    int m = threadIdx.x;
    if (m >= NMEL) return;
    int s0 = NFREQ, e0 = 0, s1 = NFREQ, e1 = 0;
    for (int k = 0; k < NFREQ; ++k) {
        if (g_mel_i0[k] == m) { if (k < s0) s0 = k; if (k + 1 > e0) e0 = k + 1; }
        if (g_mel_i1[k] == m) { if (k < s1) s1 = k; if (k + 1 > e1) e1 = k + 1; }
    }
    g_mel_rng[m] = make_int4(s0, e0, s1, e1);
}

// ---------------------------------------------------------------- STFT losses
// One block per (signal, frame PAIR): two 1024-pt FFTs batched (R=2) share
// all barriers / reductions / atomics. Radix-4 stage 0 is FUSED into the
// windowed global load (SKIP=1). Hann comes from a table; sqrt/log use
// single-MUFU approximations (rel err ~1e-7 vs 1e-3 budget). The last pair's
// second frame (251) is zero-filled and contributes exactly 0.

__global__ __launch_bounds__(TPB, 5) void stft_loss_kernel(const float* __restrict__ pd,
                                                           const float* __restrict__ td) {
    __shared__ float2 sA[2 * NFFT], sB[2 * NFFT];
    __shared__ float s_mel;
    __shared__ float scr[8];
    int f0  = blockIdx.x * 2;
    int sig = blockIdx.y;
    const float* p = pd + (size_t)sig * T_SIG;
    const float* q = td + (size_t)sig * T_SIG;
    int tid = threadIdx.x;

    if (tid == 0) s_mel = 0.f;
    #pragma unroll
    for (int l = 0; l < 2; ++l) {                  // 512 fused stage-0 butterflies
        int idx = tid + TPB * l;
        int fr = idx >> 8, pb = idx & 255;         // frame-of-pair, butterfly index
        int f = f0 + fr;
        float2 a0, a1, a2, a3;
        if (f < NFRAMES) {
            int base_t = f * HOP - 512;
            #pragma unroll
            for (int j = 0; j < 4; ++j) {
                int jj = pb + (j << 8);
                int t0 = base_t + jj;              // reflect padding (center=True)
                if (t0 < 0) t0 = -t0;
                else if (t0 >= T_SIG) t0 = 2 * T_SIG - 2 - t0;
                float w = g_hann[jj];
                float2 v = make_float2(p[t0] * w, q[t0] * w);
                if (j == 0) a0 = v; else if (j == 1) a1 = v;
                else if (j == 2) a2 = v; else a3 = v;
            }
        } else {
            a0 = a1 = a2 = a3 = make_float2(0.f, 0.f);
        }
        // SIGN=-1 radix-4 stage 0
        float t0x = a0.x + a2.x, t0y = a0.y + a2.y;
        float t1x = a0.x - a2.x, t1y = a0.y - a2.y;
        float t2x = a1.x + a3.x, t2y = a1.y + a3.y;
        float t3x = a1.x - a3.x, t3y = a1.y - a3.y;
        float b0x = t0x + t2x, b0y = t0y + t2y;
        float b2x = t0x - t2x, b2y = t0y - t2y;
        float b1x = t1x + t3y, b1y = t1y - t3x;    // t1 - i t3
        float b3x = t1x - t3y, b3y = t1y + t3x;    // t1 + i t3
        float2 w = __ldg(&g_tw1024[pb]);
        float c1 = w.x, s1 = -w.y;
        float c2 = c1 * c1 - s1 * s1, s2 = 2.f * c1 * s1;
        float c3 = c2 * c1 - s2 * s1, s3 = c2 * s1 + s2 * c1;
        int ob = fr * NFFT + (pb << 2);
        sA[swz(ob, 0)]     = make_float2(b0x, b0y);
        sA[swz(ob + 1, 0)] = make_float2(b1x * c1 - b1y * s1, b1x * s1 + b1y * c1);
        sA[swz(ob + 2, 0)] = make_float2(b2x * c2 - b2y * s2, b2x * s2 + b2y * c2);
        sA[swz(ob + 3, 0)] = make_float2(b3x * c3 - b3y * s3, b3x * s3 + b3y * c3);
    }
    __syncthreads();

    // 4 remaining radix-4 stages (SKIP=1); result parity: back in sA.
    float2* res = smem_fft4<-1, NFFT, 2, NFFT, 0, 2, 1>(sA, sB, g_tw1024);
    float2* cache = (res == sA) ? sB : sA;         // free buffer for power cache

    const float SCL2 = 0.0026041666666666665f;     // 1/(sum hann^2) = 1/384
    float magacc = 0.f, cosacc = 0.f;
    #pragma unroll
    for (int fr = 0; fr < 2; ++fr) {
        float2* rf = res + fr * NFFT;
        float2* cf = cache + fr * NFFT;
        for (int k = tid; k < NFREQ; k += TPB) {
            float2 Xk = rf[k];
            float2 Xm = rf[(NFFT - k) & (NFFT - 1)];
            float Pr = 0.5f * (Xk.x + Xm.x);
            float Pi = 0.5f * (Xk.y - Xm.y);
            float Tr = 0.5f * (Xk.y + Xm.y);
            float Ti = 0.5f * (Xm.x - Xk.x);
            float pp = (Pr * Pr + Pi * Pi) * SCL2;
            float tp = (Tr * Tr + Ti * Ti) * SCL2;
            magacc += fabsf(fsqrt_approx(pp) - fsqrt_approx(tp));
            float dot = (Pr * Tr + Pi * Ti) * SCL2;
            cosacc += dot * rsqrtf(fmaxf(pp * tp, 1e-36f));  // cos(dphi)
            cf[k] = make_float2(pp, tp);           // cache powers for mel gather
        }
    }
    __syncthreads();
    if (tid < 2 * NMEL) {                          // gather: (frame, mel) per thread
        int fr = tid / NMEL;
        int m  = tid - fr * NMEL;
        const float2* cf = cache + fr * NFFT;
        int4 r = g_mel_rng[m];
        float mp_ = 0.f, mt_ = 0.f;
        for (int k = r.x; k < r.y; ++k) {
            float w = g_mel_w0[k]; float2 v = cf[k];
            mp_ += v.x * w; mt_ += v.y * w;
        }
        for (int k = r.z; k < r.w; ++k) {
            float w = g_mel_w1[k]; float2 v = cf[k];
            mp_ += v.x * w; mt_ += v.y * w;
        }
        float d = fabsf(__logf(mp_ + 1e-8f) - __logf(mt_ + 1e-8f));
        atomicAdd(&s_mel, d);
    }
    float bm = block_reduce(magacc, scr);
    float bc = block_reduce(cosacc, scr);
    if (tid == 0) {
        atomicAdd(&g_acc[0], (double)bm);
        atomicAdd(&g_acc[1], (double)bc);
        atomicAdd(&g_acc[2], (double)s_mel);
    }
}

// ---------------------------------------------------------------- time-domain

__global__ __launch_bounds__(TPB) void time_loss_kernel(const float4* __restrict__ pd,
                                                        const float4* __restrict__ pr,
                                                        const float4* __restrict__ td,
                                                        const float4* __restrict__ tr) {
    __shared__ float segsum[4];
    __shared__ float scr[8];
    if (threadIdx.x < 4) segsum[threadIdx.x] = 0.f;
    __syncthreads();
    float dry = 0.f, rir = 0.f, spa = 0.f;
    const int N4 = (NSIG * T_SIG) / 4;             // 1,024,000
    int stride = gridDim.x * TPB;
    for (int i = blockIdx.x * TPB + threadIdx.x; i < N4; i += stride) {
        float4 a = pd[i], b = td[i], c = pr[i], d = tr[i];
        dry += fabsf(a.x-b.x) + fabsf(a.y-b.y) + fabsf(a.z-b.z) + fabsf(a.w-b.w);
        rir += fabsf(c.x-d.x) + fabsf(c.y-d.y) + fabsf(c.z-d.z) + fabsf(c.w-d.w);
        spa += fabsf(c.x) + fabsf(c.y) + fabsf(c.z) + fabsf(c.w);
        float sq = c.x*c.x + c.y*c.y + c.z*c.z + c.w*c.w;
        #pragma unroll
        for (int o = 16; o; o >>= 1) sq += __shfl_down_sync(0xffffffffu, sq, o);
        if ((threadIdx.x & 31) == 0) {
            int t0 = (i * 4) % T_SIG;              // warp-uniform segment
            atomicAdd(&segsum[t0 / 16000], sq);
        }
    }
    float bd = block_reduce(dry, scr);
    float br = block_reduce(rir, scr);
    float bs = block_reduce(spa, scr);
    __syncthreads();
    if (threadIdx.x == 0) {
        atomicAdd(&g_acc[3], (double)bd);
        atomicAdd(&g_acc[4], (double)br);
        atomicAdd(&g_acc[5], (double)bs);
    }
    if (threadIdx.x < 4) atomicAdd(&g_acc[6 + threadIdx.x], (double)segsum[threadIdx.x]);
}

// ---------------------------------------------------------------- consistency
// 2^17-pt four-step FFT. n = n1 + 1024*n2, k = k2 + 128*k1. Spectra stored
// permuted at p = k2*1024 + k1. dry packed as real, rir as imag (forward);
// two Hermitian product spectra packed per inverse FFT.

// Column FFT with radix-4 stage 0 fused into the global load: the upper half
// of every column (n2 >= 63) is structurally zero (n >= T_SIG), so stage 0
// degenerates to a0 +/- a1 and a0 -/+ i*a1 with only two loads. Output store
// vectorized to float4 (2 consecutive n1 per thread); the paired transposed
// smem reads stay conflict-free under the g0 swizzle.
__global__ __launch_bounds__(TPB, 6) void conv_fwdA(const float* __restrict__ dry,
                                                    const float* __restrict__ rir) {
    __shared__ __align__(16) float2 sA[16 * CRS], sB[16 * CRS];
    int n1_0 = blockIdx.x * 16;
    int sig  = blockIdx.y;
    const float* d = dry + (size_t)sig * T_SIG;
    const float* r = rir + (size_t)sig * T_SIG;
    #pragma unroll
    for (int l = 0; l < 2; ++l) {                 // 512 stage-0 butterflies
        int idx = threadIdx.x + TPB * l;
        int n1l = idx & 15, p = idx >> 4;          // p in [0,32)
        int n1 = n1_0 + n1l;
        float2 a0 = make_float2(d[n1 + (p << 10)], r[n1 + (p << 10)]);
        int nb = n1 + ((p + 32) << 10);
        float2 a1 = make_float2(0.f, 0.f);
        if (nb < T_SIG) { a1.x = d[nb]; a1.y = r[nb]; }
        // SIGN=-1 stage 0 with a2=a3=0
        float b0x = a0.x + a1.x, b0y = a0.y + a1.y;
        float b2x = a0.x - a1.x, b2y = a0.y - a1.y;
        float b1x = a0.x + a1.y, b1y = a0.y - a1.x;   // a0 - i a1
        float b3x = a0.x - a1.y, b3y = a0.y + a1.x;   // a0 + i a1
        float2 w = __ldg(&g_tw128[p]);
        float c1 = w.x, s1 = -w.y;
        float c2 = c1 * c1 - s1 * s1, s2 = 2.f * c1 * s1;
        float c3 = c2 * c1 - s2 * s1, s3 = c2 * s1 + s2 * c1;
        int ob = n1l * CRS + (p << 2);
        sA[swz(ob, 0)]     = make_float2(b0x, b0y);
        sA[swz(ob + 1, 0)] = make_float2(b1x * c1 - b1y * s1, b1x * s1 + b1y * c1);
        sA[swz(ob + 2, 0)] = make_float2(b2x * c2 - b2y * s2, b2x * s2 + b2y * c2);
        sA[swz(ob + 3, 0)] = make_float2(b3x * c3 - b3y * s3, b3x * s3 + b3y * c3);
    }
    __syncthreads();
    float2* res = smem_fft4<-1, 128, 16, CRS, 0, 0, 1>(sA, sB, g_tw128);
    float4* out4 = (float4*)(g_bufA + (size_t)sig * CN);
    #pragma unroll
    for (int l = 0; l < 4; ++l) {                  // 1024 float4 stores total
        int idx = threadIdx.x + TPB * l;
        int n1h = idx & 7, k2 = idx >> 3;
        int n1a = n1_0 + 2 * n1h;
        float2 y0 = res[swz((2 * n1h) * CRS + k2, 0)];
        float2 y1 = res[swz((2 * n1h + 1) * CRS + k2, 0)];
        float c0, s0, c1, s1;
        __sincosf(-(6.2831853071795864f / 131072.0f) * (float)(n1a * k2), &s0, &c0);
        __sincosf(-(6.2831853071795864f / 131072.0f) * (float)((n1a + 1) * k2), &s1, &c1);
        out4[(k2 << 9) + ((n1_0 >> 1) + n1h)] =
            make_float4(y0.x * c0 - y0.y * s0, y0.x * s0 + y0.y * c0,
                        y1.x * c1 - y1.y * s1, y1.x * s1 + y1.y * c1);
    }
}

// Fused: forward 1024-pt row FFTs (4 rows, radix-4 stage 0 fused into the
// global load) + Hermitian pointwise product (packed pairs) + inverse
// 1024-pt row FFTs + inter-pass twiddle. Block x handles conjugate row pair
// (r0, r1); x==0 handles the self-paired rows 0 and 64. y = product-pair
// index (signals 2y, 2y+1 -> Pa + i*Pb).
// SMEM plan: fused stage-0 writes aF input to S (g0), bF input to S+2048 (g0).
// aF pass (S, S+4096, SKIP=1, 4 stages) -> result S. bF pass (S+2048, S+4096)
// -> result S+2048. Product -> P = S+4096. Inverse (S+4096, S, 5 stages)
// -> result S.
__global__ __launch_bounds__(TPB) void conv_prodrow_inv1() {
    __shared__ __align__(16) float2 S[6144];
    int x = blockIdx.x, pr = blockIdx.y;
    int r0 = x;
    int r1 = x ? (128 - x) : 64;
    const float2* Xa = g_bufA + (size_t)(2 * pr) * CN;
    const float2* Xb = Xa + CN;
    int tid = threadIdx.x;
    #pragma unroll
    for (int sel = 0; sel < 2; ++sel) {            // 0: signal a, 1: signal b
        const float2* X = sel ? Xb : Xa;
        float2* dst = sel ? (S + 2048) : S;
        #pragma unroll
        for (int l = 0; l < 2; ++l) {              // 512 stage-0 butterflies
            int idx = tid + TPB * l;
            int row = idx >> 8, bf = idx & 255;
            const float2* rowp = X + (row ? r1 : r0) * 1024;
            float2 a0 = rowp[bf];
            float2 a1 = rowp[bf + 256];
            float2 a2 = rowp[bf + 512];
            float2 a3 = rowp[bf + 768];
            float t0x = a0.x + a2.x, t0y = a0.y + a2.y;
            float t1x = a0.x - a2.x, t1y = a0.y - a2.y;
            float t2x = a1.x + a3.x, t2y = a1.y + a3.y;
            float t3x = a1.x - a3.x, t3y = a1.y - a3.y;
            float b0x = t0x + t2x, b0y = t0y + t2y;
            float b2x = t0x - t2x, b2y = t0y - t2y;
            float b1x = t1x + t3y, b1y = t1y - t3x;    // t1 - i t3 (SIGN=-1)
            float b3x = t1x - t3y, b3y = t1y + t3x;    // t1 + i t3
            float2 w = __ldg(&g_tw1024[bf]);
            float c1 = w.x, s1 = -w.y;
            float c2 = c1 * c1 - s1 * s1, s2 = 2.f * c1 * s1;
            float c3 = c2 * c1 - s2 * s1, s3 = c2 * s1 + s2 * c1;
            int ob = row * 1024 + (bf << 2);
            dst[swz(ob, 0)]     = make_float2(b0x, b0y);
            dst[swz(ob + 1, 0)] = make_float2(b1x * c1 - b1y * s1, b1x * s1 + b1y * c1);
            dst[swz(ob + 2, 0)] = make_float2(b2x * c2 - b2y * s2, b2x * s2 + b2y * c2);
            dst[swz(ob + 3, 0)] = make_float2(b3x * c3 - b3y * s3, b3x * s3 + b3y * c3);
        }
    }
    __syncthreads();
    float2* aF = smem_fft4<-1, 1024, 2, 1024, 0, 2, 1>(S, S + 4096, g_tw1024);        // = S
    float2* bF = smem_fft4<-1, 1024, 2, 1024, 0, 2, 1>(S + 2048, S + 4096, g_tw1024); // = S+2048
    float2* P = S + 4096;
    if (x) {
        // cross pair: (r0, k1) <-> (r1, 1023-k1)
        #pragma unroll
        for (int l = 0; l < 4; ++l) {
            int k1 = tid + TPB * l;
            int jm = 1023 - k1;
            float2 Q1, Q2;
            packprod(aF[k1], aF[1024 + jm], bF[k1], bF[1024 + jm], Q1, Q2);
            P[k1] = Q1;
            P[1024 + jm] = Q2;
        }
    } else {
        // row 0: self pairs (k1, (1024-k1)&1023), k1 in [0,512]
        // row 64: self pairs (k1, 1023-k1), k1 in [0,511]
        #pragma unroll
        for (int l = 0; l < 4; ++l) {
            int k1 = tid + TPB * l;
            if (k1 <= 512) {
                int jm = (1024 - k1) & 1023;
                float2 Q1, Q2;
                packprod(aF[k1], aF[jm], bF[k1], bF[jm], Q1, Q2);
                P[k1] = Q1; P[jm] = Q2;
            }
            if (k1 < 512) {
                int jm = 1023 - k1;
                float2 Q1, Q2;
                packprod(aF[1024 + k1], aF[1024 + jm], bF[1024 + k1], bF[1024 + jm], Q1, Q2);
                P[1024 + k1] = Q1; P[1024 + jm] = Q2;
            }
        }
    }
    __syncthreads();
    float2* res = smem_fft4<1, 1024, 2, 1024, 2, 2>(S + 4096, S, g_tw1024);       // = S
    float4* out4 = (float4*)(g_bufB + (size_t)pr * CN);
    const float4* res4 = (const float4*)res;
    #pragma unroll
    for (int l = 0; l < 4; ++l) {                  // 1024 float4 stores total
        int idx = tid + TPB * l;                   // 0..1023
        int row = idx >> 9;
        int jp = idx & 511;                        // n1 pair index
        int n1 = jp << 1;
        int k2v = row ? r1 : r0;
        float4 v = res4[(row << 9) + jp];
        float c0, s0, c1, s1;
        __sincosf((6.2831853071795864f / 131072.0f) * (float)(n1 * k2v), &s0, &c0);
        __sincosf((6.2831853071795864f / 131072.0f) * (float)((n1 + 1) * k2v), &s1, &c1);
        out4[(k2v << 9) + jp] =
            make_float4(v.x * c0 - v.y * s0, v.x * s0 + v.y * c0,
                        v.z * c1 - v.w * s1, v.z * s1 + v.w * c1);
    }
}

// Inverse column FFT with radix-4 stage 0 fused into the float4 gather:
// each thread owns (n1 pair, p) and loads the 4 column positions p+{0,32,64,96},
// butterflies both packed n1 values (SIGN=+1), writes g0 layout.
__global__ __launch_bounds__(TPB, 6) void conv_inv2(const float* __restrict__ mix) {
    __shared__ __align__(16) float2 sA[16 * CRS], sB[16 * CRS];
    __shared__ float scr[8];
    int n1_0 = blockIdx.x * 16;
    int pr   = blockIdx.y;
    const float4* inb4 = (const float4*)(g_bufB + (size_t)pr * CN);
    {
        int n1h = threadIdx.x & 7, p = threadIdx.x >> 3;   // p in [0,32)
        int base4 = (n1_0 >> 1) + n1h;
        float4 v0 = inb4[((p      ) << 9) + base4];
        float4 v1 = inb4[((p + 32) << 9) + base4];
        float4 v2 = inb4[((p + 64) << 9) + base4];
        float4 v3 = inb4[((p + 96) << 9) + base4];
        float2 w = __ldg(&g_tw128[p]);
        #pragma unroll
        for (int h = 0; h < 2; ++h) {              // even/odd n1 of the pair
            float2 a0 = h ? make_float2(v0.z, v0.w) : make_float2(v0.x, v0.y);
            float2 a1 = h ? make_float2(v1.z, v1.w) : make_float2(v1.x, v1.y);
            float2 a2 = h ? make_float2(v2.z, v2.w) : make_float2(v2.x, v2.y);
            float2 a3 = h ? make_float2(v3.z, v3.w) : make_float2(v3.x, v3.y);
            float t0x = a0.x + a2.x, t0y = a0.y + a2.y;
            float t1x = a0.x - a2.x, t1y = a0.y - a2.y;
            float t2x = a1.x + a3.x, t2y = a1.y + a3.y;
            float t3x = a1.x - a3.x, t3y = a1.y - a3.y;
            float b0x = t0x + t2x, b0y = t0y + t2y;
            float b2x = t0x - t2x, b2y = t0y - t2y;
            float b1x = t1x - t3y, b1y = t1y + t3x;    // t1 + i t3 (SIGN=+1)
            float b3x = t1x + t3y, b3y = t1y - t3x;    // t1 - i t3
            float c1 = w.x, s1 = w.y;
            float c2 = c1 * c1 - s1 * s1, s2 = 2.f * c1 * s1;
            float c3 = c2 * c1 - s2 * s1, s3 = c2 * s1 + s2 * c1;
            int ob = (2 * n1h + h) * CRS + (p << 2);
            sA[swz(ob, 0)]     = make_float2(b0x, b0y);
            sA[swz(ob + 1, 0)] = make_float2(b1x * c1 - b1y * s1, b1x * s1 + b1y * c1);
            sA[swz(ob + 2, 0)] = make_float2(b2x * c2 - b2y * s2, b2x * s2 + b2y * c2);
            sA[swz(ob + 3, 0)] = make_float2(b3x * c3 - b3y * s3, b3x * s3 + b3y * c3);
        }
    }
    __syncthreads();
    // SKIP=1 (stage 0 fused), HALF=1 (only low half needed, n2 <= 62).
    float2* res = smem_fft4<1, 128, 16, CRS, 0, 0, 1, 1>(sA, sB, g_tw128);
    const float* ma = mix + (size_t)(2 * pr) * T_SIG;
    const float* mb = ma + T_SIG;
    float acc = 0.f;
    const float INVN = 1.0f / 131072.0f;
    #pragma unroll
    for (int l = 0; l < 8; ++l) {
        int idx = threadIdx.x + TPB * l;
        int n1l = idx & 15, n2 = idx >> 4;
        int n = n1_0 + n1l + (n2 << 10);
        if (n < T_SIG) {
            float2 v = res[swz(n1l * CRS + n2, 0)];
            acc += fabsf(v.x * INVN - ma[n]) + fabsf(v.y * INVN - mb[n]);
        }
    }
    float b = block_reduce(acc, scr);
    if (threadIdx.x == 0) atomicAdd(&g_acc[10], (double)b);
}

// ---------------------------------------------------------------- finalize

__global__ void finalize_kernel(float* out) {
    const double NT   = 4096000.0;                 // 64 * 64000
    const double CNT  = 64.0 * 513.0 * 251.0;
    const double MELC = 64.0 * 80.0 * 251.0;
    const double SEGC = 1024000.0;                 // 64 * 16000
    double dry_time = g_acc[3] / NT;
    double mag   = g_acc[0] / CNT;
    double phase = 1.0 - g_acc[1] / CNT;
    double freqL = mag + 0.1 * phase;
    double mel   = g_acc[2] / MELC;
    double total_dry = dry_time + 0.5 * freqL + 0.3 * mel;
    double rir_time = g_acc[4] / NT;
    double spars    = g_acc[5] / NT;
    double e0 = g_acc[6] / SEGC, e1 = g_acc[7] / SEGC;
    double e2 = g_acc[8] / SEGC, e3 = g_acc[9] / SEGC;
    double decay = fmax(0.0, e1 - 0.8 * e0) + fmax(0.0, e2 - 0.8 * e1)
                 + fmax(0.0, e3 - 0.8 * e2);
    double total_rir = rir_time + 0.1 * (spars + decay);
    double consist = g_acc[10] / NT;
    out[0] = (float)(3.0 * total_dry + total_rir + 0.2 * consist);
}

// ---------------------------------------------------------------- launch
// Graph fork-join: after init, three independent branches run concurrently —
// stft (s1), time_loss (s2), conv chain (capture stream) — joined via events
// before finalize.

extern "C" void kernel_launch(void* const* d_in, const int* in_sizes, int n_in,
                              void* d_out, int out_size) {
    const float* pd  = (const float*)d_in[0];   // pred_dry
    const float* pr  = (const float*)d_in[1];   // pred_rir
    const float* td  = (const float*)d_in[2];   // target_dry
    const float* tr  = (const float*)d_in[3];   // target_rir
    const float* mix = (const float*)d_in[4];   // mix
    float* out = (float*)d_out;

    init_kernel<<<4, TPB>>>();
    init2_kernel<<<1, 128>>>();

    cudaEventRecord(g_eF, 0);
    cudaStreamWaitEvent(g_s1, g_eF, 0);
    cudaStreamWaitEvent(g_s2, g_eF, 0);

    stft_loss_kernel<<<dim3(NPAIR, NSIG), TPB, 0, g_s1>>>(pd, td);
    time_loss_kernel<<<1024, TPB, 0, g_s2>>>((const float4*)pd, (const float4*)pr,
                                             (const float4*)td, (const float4*)tr);
    conv_fwdA<<<dim3(64, NSIG), TPB>>>(pd, pr);
    conv_prodrow_inv1<<<dim3(64, 32), TPB>>>();
    conv_inv2<<<dim3(64, 32), TPB>>>(mix);

    cudaEventRecord(g_eJ1, g_s1);
    cudaEventRecord(g_eJ2, g_s2);
    cudaStreamWaitEvent(0, g_eJ1, 0);
    cudaStreamWaitEvent(0, g_eJ2, 0);

    finalize_kernel<<<1, 1>>>(out);
}

// round 17
// speedup vs baseline: 1.1818x; 1.0050x over previous
#include <cuda_runtime.h>

#define TPB 256
#define T_SIG 64000
#define NSIG 64
#define NFFT 1024
#define HOP 256
#define NFRAMES 251
#define NPAIR 126   // ceil(NFRAMES/2) frame pairs per signal
#define NFREQ 513
#define NMEL 80
#define CN 131072   // conv FFT length = 2^17 >= 2*T-1 (exact linear convolution)
#define CRS 144     // conv smem row stride; 144>>4=9 odd => g0 swizzle fixes transpose

// global accumulators (double):
// 0 mag, 1 cos, 2 mel, 3 dryL1, 4 rirL1, 5 sparsity, 6..9 e0..e3, 10 consist
__device__ double g_acc[12];
__device__ int    g_mel_i0[NFREQ];
__device__ float  g_mel_w0[NFREQ];
__device__ int    g_mel_i1[NFREQ];
__device__ float  g_mel_w1[NFREQ];
__device__ int4   g_mel_rng[NMEL];             // per-mel gather ranges
__device__ float  g_hann[NFFT];                // hann window (periodic, double init)
__device__ float2 g_tw1024[341];               // radix-4 twiddles, L=1024 (all stages)
__device__ float2 g_tw128[42];                 // radix-4 twiddles, L=128
__device__ __align__(16) float2 g_bufA[(size_t)NSIG * CN];   // 64 MB scratch
__device__ __align__(16) float2 g_bufB[(size_t)NSIG * CN];   // 64 MB scratch

// Streams/events for graph fork-join (created at program init, before the
// harness's memory checkpoints; NonBlocking so the legacy capture stream
// doesn't implicitly serialize them).
static cudaStream_t g_s1, g_s2;
static cudaEvent_t  g_eF, g_eJ1, g_eJ2;
static struct StreamInit {
    StreamInit() {
        cudaStreamCreateWithFlags(&g_s1, cudaStreamNonBlocking);
        cudaStreamCreateWithFlags(&g_s2, cudaStreamNonBlocking);
        cudaEventCreateWithFlags(&g_eF,  cudaEventDisableTiming);
        cudaEventCreateWithFlags(&g_eJ1, cudaEventDisableTiming);
        cudaEventCreateWithFlags(&g_eJ2, cudaEventDisableTiming);
    }
} g_stream_init;

// ---------------------------------------------------------------- utilities

__host__ __device__ constexpr int ilog2c(int n) { return n <= 1 ? 0 : 1 + ilog2c(n / 2); }

__device__ __forceinline__ float fsqrt_approx(float x) {
    float r; asm("sqrt.approx.f32 %0, %1;" : "=f"(r) : "f"(x)); return r;
}

// Bank swizzle per buffer generation (bits [0:4) XOR-keyed from upper bits).
// g=0 fixes stage-0 write pattern (4bf+j) AND stride-144 transpose accesses;
// g=1 fixes stage-1 pattern (q | j<<2 | p<<4); g=2 identity.
__device__ __forceinline__ int swz(int a, int g) {
    if (g == 0) return a ^ ((a >> 4) & 0xF);
    if (g == 1) return a ^ ((a >> 2) & 0xC);
    return a;
}

__device__ __forceinline__ float block_reduce(float v, float* scr) {
    #pragma unroll
    for (int o = 16; o; o >>= 1) v += __shfl_down_sync(0xffffffffu, v, o);
    __syncthreads();
    if ((threadIdx.x & 31) == 0) scr[threadIdx.x >> 5] = v;
    __syncthreads();
    if (threadIdx.x < 32) {
        v = (threadIdx.x < (TPB / 32)) ? scr[threadIdx.x] : 0.f;
        #pragma unroll
        for (int o = 4; o; o >>= 1) v += __shfl_down_sync(0xffffffffu, v, o);
    }
    return v;  // valid on thread 0
}

// Mixed radix-4/2 Stockham DIF FFT over R rows of length L (power of 2) in
// shared memory, row stride RS (float2, 16-aligned). The caller writes the
// input through swz(.,GIN) and reads the natural-order result through
// swz(.,GOUT). SKIP=1: caller already performed radix-4 stage 0 (input must
// be in generation-0 layout). HALF=1: radix-2 tail stores only the low half
// (A+B) of each output pair.
template<int SIGN, int L, int R, int RS, int GIN, int GOUT, int SKIP = 0, int HALF = 0>
__device__ __forceinline__ float2* smem_fft4(float2* a, float2* b,
                                             const float2* __restrict__ tw) {
    constexpr int LOG2L = ilog2c(L);
    constexpr int NS4 = LOG2L >> 1;
    float2 *src = a, *dst = b;
    int ncur = L >> (2 * SKIP), logs = 2 * SKIP, toff = SKIP ? (L >> 2) : 0;
    #pragma unroll
    for (int s = SKIP; s < NS4; ++s) {
        const int rg = (s == 0) ? GIN : (s == 1) ? 0 : (s == 2) ? 1 : 2;
        const int wg = ((s == NS4 - 1) && !(LOG2L & 1)) ? GOUT
                       : (s == 0) ? 0 : (s == 1) ? 1 : 2;
        const int m = ncur >> 2;
        const int Ls = 1 << logs;
        constexpr int NB = R * (L >> 2);
        #pragma unroll
        for (int l = 0; l < NB / TPB; ++l) {
            const int it = threadIdx.x + TPB * l;
            const int row = it >> (LOG2L - 2);
            const int bf  = it & ((L >> 2) - 1);
            const int p = bf >> logs;
            const int q = bf - (p << logs);
            const int base = row * RS + q;
            float2 a0 = src[swz(base + p * Ls, rg)];
            float2 a1 = src[swz(base + (p + m) * Ls, rg)];
            float2 a2 = src[swz(base + (p + 2 * m) * Ls, rg)];
            float2 a3 = src[swz(base + (p + 3 * m) * Ls, rg)];
            float t0x = a0.x + a2.x, t0y = a0.y + a2.y;
            float t1x = a0.x - a2.x, t1y = a0.y - a2.y;
            float t2x = a1.x + a3.x, t2y = a1.y + a3.y;
            float t3x = a1.x - a3.x, t3y = a1.y - a3.y;
            float b0x = t0x + t2x, b0y = t0y + t2y;
            float b2x = t0x - t2x, b2y = t0y - t2y;
            float b1x, b1y, b3x, b3y;
            if (SIGN < 0) {           // b1 = t1 - i t3, b3 = t1 + i t3
                b1x = t1x + t3y; b1y = t1y - t3x;
                b3x = t1x - t3y; b3y = t1y + t3x;
            } else {                  // b1 = t1 + i t3, b3 = t1 - i t3
                b1x = t1x - t3y; b1y = t1y + t3x;
                b3x = t1x + t3y; b3y = t1y - t3x;
            }
            float2 w = __ldg(&tw[toff + p]);
            float c1 = w.x;
            float s1 = (SIGN < 0) ? -w.y : w.y;
            float c2 = c1 * c1 - s1 * s1, s2 = 2.f * c1 * s1;
            float c3 = c2 * c1 - s2 * s1, s3 = c2 * s1 + s2 * c1;
            const int ob = base + ((p << 2) << logs);
            dst[swz(ob, wg)]          = make_float2(b0x, b0y);
            dst[swz(ob + Ls, wg)]     = make_float2(b1x * c1 - b1y * s1, b1x * s1 + b1y * c1);
            dst[swz(ob + 2 * Ls, wg)] = make_float2(b2x * c2 - b2y * s2, b2x * s2 + b2y * c2);
            dst[swz(ob + 3 * Ls, wg)] = make_float2(b3x * c3 - b3y * s3, b3x * s3 + b3y * c3);
        }
        __syncthreads();
        float2* t = src; src = dst; dst = t;
        ncur >>= 2; logs += 2; toff += m;
    }
    if constexpr (LOG2L & 1) {        // final radix-2 stage (twiddle-free, p=0)
        const int rg = (NS4 == 1) ? 0 : (NS4 == 2) ? 1 : 2;
        constexpr int Ls = L >> 1;
        constexpr int NB = R * (L >> 1);
        #pragma unroll
        for (int l = 0; l < NB / TPB; ++l) {
            const int it = threadIdx.x + TPB * l;
            const int row = it >> (LOG2L - 1);
            const int q   = it & ((L >> 1) - 1);
            const int base = row * RS + q;
            float2 A = src[swz(base, rg)];
            float2 B = src[swz(base + Ls, rg)];
            dst[swz(base, GOUT)]      = make_float2(A.x + B.x, A.y + B.y);
            if constexpr (!HALF)
                dst[swz(base + Ls, GOUT)] = make_float2(A.x - B.x, A.y - B.y);
        }
        __syncthreads();
        float2* t = src; src = dst; dst = t;
    }
    return src;
}

// Hermitian unpack of two packed spectra (dry real, rir imag) + complex
// product, producing packed product pair Q1 (at p1) / Q2 (at p2=conj pos).
__device__ __forceinline__ void packprod(float2 A1, float2 A2, float2 B1, float2 B2,
                                         float2& Q1, float2& Q2) {
    float Dar = 0.5f * (A1.x + A2.x), Dai = 0.5f * (A1.y - A2.y);
    float Rar = 0.5f * (A1.y + A2.y), Rai = 0.5f * (A2.x - A1.x);
    float Par = Dar * Rar - Dai * Rai, Pai = Dar * Rai + Dai * Rar;
    float Dbr = 0.5f * (B1.x + B2.x), Dbi = 0.5f * (B1.y - B2.y);
    float Rbr = 0.5f * (B1.y + B2.y), Rbi = 0.5f * (B2.x - B1.x);
    float Pbr = Dbr * Rbr - Dbi * Rbi, Pbi = Dbr * Rbi + Dbi * Rbr;
    Q1 = make_float2(Par - Pbi, Pai + Pbr);   // Pa + i*Pb
    Q2 = make_float2(Par + Pbi, Pbr - Pai);   // conj(Pa) + i*conj(Pb)
}

// ---------------------------------------------------------------- init

__global__ void init_kernel() {
    int t = blockIdx.x * blockDim.x + threadIdx.x;
    if (t < 12) g_acc[t] = 0.0;
    if (t < 341) {                                // L=1024 twiddles (all 5 stages)
        int ncur = 1024, p = t;
        while (p >= (ncur >> 2)) { p -= (ncur >> 2); ncur >>= 2; }
        double ang = 6.283185307179586476925286766559 * (double)p / (double)ncur;
        g_tw1024[t] = make_float2((float)cos(ang), (float)sin(ang));
    }
    if (t < 42) {                                 // L=128 twiddles (3 radix-4 stages)
        int ncur = 128, p = t;
        while (p >= (ncur >> 2)) { p -= (ncur >> 2); ncur >>= 2; }
        double ang = 6.283185307179586476925286766559 * (double)p / (double)ncur;
        g_tw128[t] = make_float2((float)cos(ang), (float)sin(ang));
    }
    if (t < NFFT) {                               // hann window (periodic)
        double wa = 0.5 - 0.5 * cos(6.283185307179586476925286766559 * (double)t / 1024.0);
        g_hann[t] = (float)wa;
    }
    if (t < NFREQ) {
        double freq   = (double)t * (8000.0 / 512.0);
        double melmax = 2595.0 * log10(1.0 + 8000.0 / 700.0);
        double mstep  = melmax / 81.0;
        double mval   = 2595.0 * log10(1.0 + freq / 700.0);
        int i = (int)floor(mval / mstep);
        if (i < 0) i = 0;
        if (i > 81) i = 81;
        double f_lo = 700.0 * (pow(10.0, ((double)i * mstep) / 2595.0) - 1.0);
        double f_hi = 700.0 * (pow(10.0, ((double)(i + 1) * mstep) / 2595.0) - 1.0);
        double inv  = 1.0 / (f_hi - f_lo);
        int i0 = -1, i1 = -1; float w0 = 0.f, w1 = 0.f;
        if (i <= 79)           { i0 = i;     w0 = (float)fmax(0.0, (freq - f_lo) * inv); }
        if (i >= 1 && i <= 80) { i1 = i - 1; w1 = (float)fmax(0.0, (f_hi - freq) * inv); }
        g_mel_i0[t] = i0; g_mel_w0[t] = w0;
        g_mel_i1[t] = i1; g_mel_w1[t] = w1;
    }
}

// Second init pass: per-mel contiguous gather ranges (i0[k], i1[k] are
// monotone in k, so each mel's membership is a contiguous bin range).
__global__ void init2_kernel() {
    int m = threadIdx.x;
    if (m >= NMEL) return;
    int s0 = NFREQ, e0 = 0, s1 = NFREQ, e1 = 0;
    for (int k = 0; k < NFREQ; ++k) {
        if (g_mel_i0[k] == m) { if (k < s0) s0 = k; if (k + 1 > e0) e0 = k + 1; }
        if (g_mel_i1[k] == m) { if (k < s1) s1 = k; if (k + 1 > e1) e1 = k + 1; }
    }
    g_mel_rng[m] = make_int4(s0, e0, s1, e1);
}

// ---------------------------------------------------------------- STFT losses
// One block per (signal, frame PAIR): two 1024-pt FFTs batched (R=2) share
// all barriers / reductions / atomics. Radix-4 stage 0 is FUSED into the
// windowed global load (SKIP=1). Hann comes from a table; sqrt/log use
// single-MUFU approximations (rel err ~1e-7 vs 1e-3 budget). The last pair's
// second frame (251) is zero-filled and contributes exactly 0.

__global__ __launch_bounds__(TPB, 5) void stft_loss_kernel(const float* __restrict__ pd,
                                                           const float* __restrict__ td) {
    __shared__ float2 sA[2 * NFFT], sB[2 * NFFT];
    __shared__ float s_mel;
    __shared__ float scr[8];
    int f0  = blockIdx.x * 2;
    int sig = blockIdx.y;
    const float* p = pd + (size_t)sig * T_SIG;
    const float* q = td + (size_t)sig * T_SIG;
    int tid = threadIdx.x;

    if (tid == 0) s_mel = 0.f;
    #pragma unroll
    for (int l = 0; l < 2; ++l) {                  // 512 fused stage-0 butterflies
        int idx = tid + TPB * l;
        int fr = idx >> 8, pb = idx & 255;         // frame-of-pair, butterfly index
        int f = f0 + fr;
        float2 a0, a1, a2, a3;
        if (f < NFRAMES) {
            int base_t = f * HOP - 512;
            #pragma unroll
            for (int j = 0; j < 4; ++j) {
                int jj = pb + (j << 8);
                int t0 = base_t + jj;              // reflect padding (center=True)
                if (t0 < 0) t0 = -t0;
                else if (t0 >= T_SIG) t0 = 2 * T_SIG - 2 - t0;
                float w = g_hann[jj];
                float2 v = make_float2(p[t0] * w, q[t0] * w);
                if (j == 0) a0 = v; else if (j == 1) a1 = v;
                else if (j == 2) a2 = v; else a3 = v;
            }
        } else {
            a0 = a1 = a2 = a3 = make_float2(0.f, 0.f);
        }
        // SIGN=-1 radix-4 stage 0
        float t0x = a0.x + a2.x, t0y = a0.y + a2.y;
        float t1x = a0.x - a2.x, t1y = a0.y - a2.y;
        float t2x = a1.x + a3.x, t2y = a1.y + a3.y;
        float t3x = a1.x - a3.x, t3y = a1.y - a3.y;
        float b0x = t0x + t2x, b0y = t0y + t2y;
        float b2x = t0x - t2x, b2y = t0y - t2y;
        float b1x = t1x + t3y, b1y = t1y - t3x;    // t1 - i t3
        float b3x = t1x - t3y, b3y = t1y + t3x;    // t1 + i t3
        float2 w = __ldg(&g_tw1024[pb]);
        float c1 = w.x, s1 = -w.y;
        float c2 = c1 * c1 - s1 * s1, s2 = 2.f * c1 * s1;
        float c3 = c2 * c1 - s2 * s1, s3 = c2 * s1 + s2 * c1;
        int ob = fr * NFFT + (pb << 2);
        sA[swz(ob, 0)]     = make_float2(b0x, b0y);
        sA[swz(ob + 1, 0)] = make_float2(b1x * c1 - b1y * s1, b1x * s1 + b1y * c1);
        sA[swz(ob + 2, 0)] = make_float2(b2x * c2 - b2y * s2, b2x * s2 + b2y * c2);
        sA[swz(ob + 3, 0)] = make_float2(b3x * c3 - b3y * s3, b3x * s3 + b3y * c3);
    }
    __syncthreads();

    // 4 remaining radix-4 stages (SKIP=1); result parity: back in sA.
    float2* res = smem_fft4<-1, NFFT, 2, NFFT, 0, 2, 1>(sA, sB, g_tw1024);
    float2* cache = (res == sA) ? sB : sA;         // free buffer for power cache

    const float SCL2 = 0.0026041666666666665f;     // 1/(sum hann^2) = 1/384
    float magacc = 0.f, cosacc = 0.f;
    #pragma unroll
    for (int fr = 0; fr < 2; ++fr) {
        float2* rf = res + fr * NFFT;
        float2* cf = cache + fr * NFFT;
        for (int k = tid; k < NFREQ; k += TPB) {
            float2 Xk = rf[k];
            float2 Xm = rf[(NFFT - k) & (NFFT - 1)];
            float Pr = 0.5f * (Xk.x + Xm.x);
            float Pi = 0.5f * (Xk.y - Xm.y);
            float Tr = 0.5f * (Xk.y + Xm.y);
            float Ti = 0.5f * (Xm.x - Xk.x);
            float pp = (Pr * Pr + Pi * Pi) * SCL2;
            float tp = (Tr * Tr + Ti * Ti) * SCL2;
            magacc += fabsf(fsqrt_approx(pp) - fsqrt_approx(tp));
            float dot = (Pr * Tr + Pi * Ti) * SCL2;
            cosacc += dot * rsqrtf(fmaxf(pp * tp, 1e-36f));  // cos(dphi)
            cf[k] = make_float2(pp, tp);           // cache powers for mel gather
        }
    }
    __syncthreads();
    if (tid < 2 * NMEL) {                          // gather: (frame, mel) per thread
        int fr = tid / NMEL;
        int m  = tid - fr * NMEL;
        const float2* cf = cache + fr * NFFT;
        int4 r = g_mel_rng[m];
        float mp_ = 0.f, mt_ = 0.f;
        for (int k = r.x; k < r.y; ++k) {
            float w = g_mel_w0[k]; float2 v = cf[k];
            mp_ += v.x * w; mt_ += v.y * w;
        }
        for (int k = r.z; k < r.w; ++k) {
            float w = g_mel_w1[k]; float2 v = cf[k];
            mp_ += v.x * w; mt_ += v.y * w;
        }
        float d = fabsf(__logf(mp_ + 1e-8f) - __logf(mt_ + 1e-8f));
        atomicAdd(&s_mel, d);
    }
    float bm = block_reduce(magacc, scr);
    float bc = block_reduce(cosacc, scr);
    if (tid == 0) {
        atomicAdd(&g_acc[0], (double)bm);
        atomicAdd(&g_acc[1], (double)bc);
        atomicAdd(&g_acc[2], (double)s_mel);
    }
}

// ---------------------------------------------------------------- time-domain

__global__ __launch_bounds__(TPB) void time_loss_kernel(const float4* __restrict__ pd,
                                                        const float4* __restrict__ pr,
                                                        const float4* __restrict__ td,
                                                        const float4* __restrict__ tr) {
    __shared__ float segsum[4];
    __shared__ float scr[8];
    if (threadIdx.x < 4) segsum[threadIdx.x] = 0.f;
    __syncthreads();
    float dry = 0.f, rir = 0.f, spa = 0.f;
    const int N4 = (NSIG * T_SIG) / 4;             // 1,024,000
    int stride = gridDim.x * TPB;
    for (int i = blockIdx.x * TPB + threadIdx.x; i < N4; i += stride) {
        float4 a = pd[i], b = td[i], c = pr[i], d = tr[i];
        dry += fabsf(a.x-b.x) + fabsf(a.y-b.y) + fabsf(a.z-b.z) + fabsf(a.w-b.w);
        rir += fabsf(c.x-d.x) + fabsf(c.y-d.y) + fabsf(c.z-d.z) + fabsf(c.w-d.w);
        spa += fabsf(c.x) + fabsf(c.y) + fabsf(c.z) + fabsf(c.w);
        float sq = c.x*c.x + c.y*c.y + c.z*c.z + c.w*c.w;
        #pragma unroll
        for (int o = 16; o; o >>= 1) sq += __shfl_down_sync(0xffffffffu, sq, o);
        if ((threadIdx.x & 31) == 0) {
            int t0 = (i * 4) % T_SIG;              // warp-uniform segment
            atomicAdd(&segsum[t0 / 16000], sq);
        }
    }
    float bd = block_reduce(dry, scr);
    float br = block_reduce(rir, scr);
    float bs = block_reduce(spa, scr);
    __syncthreads();
    if (threadIdx.x == 0) {
        atomicAdd(&g_acc[3], (double)bd);
        atomicAdd(&g_acc[4], (double)br);
        atomicAdd(&g_acc[5], (double)bs);
    }
    if (threadIdx.x < 4) atomicAdd(&g_acc[6 + threadIdx.x], (double)segsum[threadIdx.x]);
}

// ---------------------------------------------------------------- consistency
// 2^17-pt four-step FFT. n = n1 + 1024*n2, k = k2 + 128*k1. Spectra stored
// permuted at p = k2*1024 + k1. dry packed as real, rir as imag (forward);
// two Hermitian product spectra packed per inverse FFT.

// Column FFT with radix-4 stage 0 fused into the global load: the upper half
// of every column (n2 >= 63) is structurally zero (n >= T_SIG), so stage 0
// degenerates to a0 +/- a1 and a0 -/+ i*a1 with only two loads. Output store
// vectorized to float4 (2 consecutive n1 per thread); the paired transposed
// smem reads stay conflict-free under the g0 swizzle.
__global__ __launch_bounds__(TPB, 6) void conv_fwdA(const float* __restrict__ dry,
                                                    const float* __restrict__ rir) {
    __shared__ __align__(16) float2 sA[16 * CRS], sB[16 * CRS];
    int n1_0 = blockIdx.x * 16;
    int sig  = blockIdx.y;
    const float* d = dry + (size_t)sig * T_SIG;
    const float* r = rir + (size_t)sig * T_SIG;
    #pragma unroll
    for (int l = 0; l < 2; ++l) {                 // 512 stage-0 butterflies
        int idx = threadIdx.x + TPB * l;
        int n1l = idx & 15, p = idx >> 4;          // p in [0,32)
        int n1 = n1_0 + n1l;
        float2 a0 = make_float2(d[n1 + (p << 10)], r[n1 + (p << 10)]);
        int nb = n1 + ((p + 32) << 10);
        float2 a1 = make_float2(0.f, 0.f);
        if (nb < T_SIG) { a1.x = d[nb]; a1.y = r[nb]; }
        // SIGN=-1 stage 0 with a2=a3=0
        float b0x = a0.x + a1.x, b0y = a0.y + a1.y;
        float b2x = a0.x - a1.x, b2y = a0.y - a1.y;
        float b1x = a0.x + a1.y, b1y = a0.y - a1.x;   // a0 - i a1
        float b3x = a0.x - a1.y, b3y = a0.y + a1.x;   // a0 + i a1
        float2 w = __ldg(&g_tw128[p]);
        float c1 = w.x, s1 = -w.y;
        float c2 = c1 * c1 - s1 * s1, s2 = 2.f * c1 * s1;
        float c3 = c2 * c1 - s2 * s1, s3 = c2 * s1 + s2 * c1;
        int ob = n1l * CRS + (p << 2);
        sA[swz(ob, 0)]     = make_float2(b0x, b0y);
        sA[swz(ob + 1, 0)] = make_float2(b1x * c1 - b1y * s1, b1x * s1 + b1y * c1);
        sA[swz(ob + 2, 0)] = make_float2(b2x * c2 - b2y * s2, b2x * s2 + b2y * c2);
        sA[swz(ob + 3, 0)] = make_float2(b3x * c3 - b3y * s3, b3x * s3 + b3y * c3);
    }
    __syncthreads();
    float2* res = smem_fft4<-1, 128, 16, CRS, 0, 0, 1>(sA, sB, g_tw128);
    float4* out4 = (float4*)(g_bufA + (size_t)sig * CN);
    #pragma unroll
    for (int l = 0; l < 4; ++l) {                  // 1024 float4 stores total
        int idx = threadIdx.x + TPB * l;
        int n1h = idx & 7, k2 = idx >> 3;
        int n1a = n1_0 + 2 * n1h;
        float2 y0 = res[swz((2 * n1h) * CRS + k2, 0)];
        float2 y1 = res[swz((2 * n1h + 1) * CRS + k2, 0)];
        float c0, s0, c1, s1;
        __sincosf(-(6.2831853071795864f / 131072.0f) * (float)(n1a * k2), &s0, &c0);
        __sincosf(-(6.2831853071795864f / 131072.0f) * (float)((n1a + 1) * k2), &s1, &c1);
        out4[(k2 << 9) + ((n1_0 >> 1) + n1h)] =
            make_float4(y0.x * c0 - y0.y * s0, y0.x * s0 + y0.y * c0,
                        y1.x * c1 - y1.y * s1, y1.x * s1 + y1.y * c1);
    }
}

// Fused: forward 1024-pt row FFTs (4 rows, radix-4 stage 0 fused into the
// global load) + Hermitian pointwise product (packed pairs) + inverse
// 1024-pt row FFTs + inter-pass twiddle. Block x handles conjugate row pair
// (r0, r1); x==0 handles the self-paired rows 0 and 64. y = product-pair
// index (signals 2y, 2y+1 -> Pa + i*Pb).
// SMEM plan: fused stage-0 writes aF input to S (g0), bF input to S+2048 (g0).
// aF pass (S, S+4096, SKIP=1, 4 stages) -> result S. bF pass (S+2048, S+4096)
// -> result S+2048. Product -> P = S+4096. Inverse (S+4096, S, 5 stages)
// -> result S.
__global__ __launch_bounds__(TPB) void conv_prodrow_inv1() {
    __shared__ __align__(16) float2 S[6144];
    int x = blockIdx.x, pr = blockIdx.y;
    int r0 = x;
    int r1 = x ? (128 - x) : 64;
    const float2* Xa = g_bufA + (size_t)(2 * pr) * CN;
    const float2* Xb = Xa + CN;
    int tid = threadIdx.x;
    #pragma unroll
    for (int sel = 0; sel < 2; ++sel) {            // 0: signal a, 1: signal b
        const float2* X = sel ? Xb : Xa;
        float2* dst = sel ? (S + 2048) : S;
        #pragma unroll
        for (int l = 0; l < 2; ++l) {              // 512 stage-0 butterflies
            int idx = tid + TPB * l;
            int row = idx >> 8, bf = idx & 255;
            const float2* rowp = X + (row ? r1 : r0) * 1024;
            float2 a0 = rowp[bf];
            float2 a1 = rowp[bf + 256];
            float2 a2 = rowp[bf + 512];
            float2 a3 = rowp[bf + 768];
            float t0x = a0.x + a2.x, t0y = a0.y + a2.y;
            float t1x = a0.x - a2.x, t1y = a0.y - a2.y;
            float t2x = a1.x + a3.x, t2y = a1.y + a3.y;
            float t3x = a1.x - a3.x, t3y = a1.y - a3.y;
            float b0x = t0x + t2x, b0y = t0y + t2y;
            float b2x = t0x - t2x, b2y = t0y - t2y;
            float b1x = t1x + t3y, b1y = t1y - t3x;    // t1 - i t3 (SIGN=-1)
            float b3x = t1x - t3y, b3y = t1y + t3x;    // t1 + i t3
            float2 w = __ldg(&g_tw1024[bf]);
            float c1 = w.x, s1 = -w.y;
            float c2 = c1 * c1 - s1 * s1, s2 = 2.f * c1 * s1;
            float c3 = c2 * c1 - s2 * s1, s3 = c2 * s1 + s2 * c1;
            int ob = row * 1024 + (bf << 2);
            dst[swz(ob, 0)]     = make_float2(b0x, b0y);
            dst[swz(ob + 1, 0)] = make_float2(b1x * c1 - b1y * s1, b1x * s1 + b1y * c1);
            dst[swz(ob + 2, 0)] = make_float2(b2x * c2 - b2y * s2, b2x * s2 + b2y * c2);
            dst[swz(ob + 3, 0)] = make_float2(b3x * c3 - b3y * s3, b3x * s3 + b3y * c3);
        }
    }
    __syncthreads();
    float2* aF = smem_fft4<-1, 1024, 2, 1024, 0, 2, 1>(S, S + 4096, g_tw1024);        // = S
    float2* bF = smem_fft4<-1, 1024, 2, 1024, 0, 2, 1>(S + 2048, S + 4096, g_tw1024); // = S+2048
    float2* P = S + 4096;
    if (x) {
        // cross pair: (r0, k1) <-> (r1, 1023-k1)
        #pragma unroll
        for (int l = 0; l < 4; ++l) {
            int k1 = tid + TPB * l;
            int jm = 1023 - k1;
            float2 Q1, Q2;
            packprod(aF[k1], aF[1024 + jm], bF[k1], bF[1024 + jm], Q1, Q2);
            P[k1] = Q1;
            P[1024 + jm] = Q2;
        }
    } else {
        // row 0: self pairs (k1, (1024-k1)&1023), k1 in [0,512]
        // row 64: self pairs (k1, 1023-k1), k1 in [0,511]
        #pragma unroll
        for (int l = 0; l < 4; ++l) {
            int k1 = tid + TPB * l;
            if (k1 <= 512) {
                int jm = (1024 - k1) & 1023;
                float2 Q1, Q2;
                packprod(aF[k1], aF[jm], bF[k1], bF[jm], Q1, Q2);
                P[k1] = Q1; P[jm] = Q2;
            }
            if (k1 < 512) {
                int jm = 1023 - k1;
                float2 Q1, Q2;
                packprod(aF[1024 + k1], aF[1024 + jm], bF[1024 + k1], bF[1024 + jm], Q1, Q2);
                P[1024 + k1] = Q1; P[1024 + jm] = Q2;
            }
        }
    }
    __syncthreads();
    float2* res = smem_fft4<1, 1024, 2, 1024, 2, 2>(S + 4096, S, g_tw1024);       // = S
    float4* out4 = (float4*)(g_bufB + (size_t)pr * CN);
    const float4* res4 = (const float4*)res;
    #pragma unroll
    for (int l = 0; l < 4; ++l) {                  // 1024 float4 stores total
        int idx = tid + TPB * l;                   // 0..1023
        int row = idx >> 9;
        int jp = idx & 511;                        // n1 pair index
        int n1 = jp << 1;
        int k2v = row ? r1 : r0;
        float4 v = res4[(row << 9) + jp];
        float c0, s0, c1, s1;
        __sincosf((6.2831853071795864f / 131072.0f) * (float)(n1 * k2v), &s0, &c0);
        __sincosf((6.2831853071795864f / 131072.0f) * (float)((n1 + 1) * k2v), &s1, &c1);
        out4[(k2v << 9) + jp] =
            make_float4(v.x * c0 - v.y * s0, v.x * s0 + v.y * c0,
                        v.z * c1 - v.w * s1, v.z * s1 + v.w * c1);
    }
}

// Inverse column FFT with radix-4 stage 0 fused into the float4 gather:
// each thread owns (n1 pair, p) and loads the 4 column positions p+{0,32,64,96},
// butterflies both packed n1 values (SIGN=+1), writes g0 layout.
__global__ __launch_bounds__(TPB, 6) void conv_inv2(const float* __restrict__ mix) {
    __shared__ __align__(16) float2 sA[16 * CRS], sB[16 * CRS];
    __shared__ float scr[8];
    int n1_0 = blockIdx.x * 16;
    int pr   = blockIdx.y;
    const float4* inb4 = (const float4*)(g_bufB + (size_t)pr * CN);
    {
        int n1h = threadIdx.x & 7, p = threadIdx.x >> 3;   // p in [0,32)
        int base4 = (n1_0 >> 1) + n1h;
        float4 v0 = inb4[((p      ) << 9) + base4];
        float4 v1 = inb4[((p + 32) << 9) + base4];
        float4 v2 = inb4[((p + 64) << 9) + base4];
        float4 v3 = inb4[((p + 96) << 9) + base4];
        float2 w = __ldg(&g_tw128[p]);
        #pragma unroll
        for (int h = 0; h < 2; ++h) {              // even/odd n1 of the pair
            float2 a0 = h ? make_float2(v0.z, v0.w) : make_float2(v0.x, v0.y);
            float2 a1 = h ? make_float2(v1.z, v1.w) : make_float2(v1.x, v1.y);
            float2 a2 = h ? make_float2(v2.z, v2.w) : make_float2(v2.x, v2.y);
            float2 a3 = h ? make_float2(v3.z, v3.w) : make_float2(v3.x, v3.y);
            float t0x = a0.x + a2.x, t0y = a0.y + a2.y;
            float t1x = a0.x - a2.x, t1y = a0.y - a2.y;
            float t2x = a1.x + a3.x, t2y = a1.y + a3.y;
            float t3x = a1.x - a3.x, t3y = a1.y - a3.y;
            float b0x = t0x + t2x, b0y = t0y + t2y;
            float b2x = t0x - t2x, b2y = t0y - t2y;
            float b1x = t1x - t3y, b1y = t1y + t3x;    // t1 + i t3 (SIGN=+1)
            float b3x = t1x + t3y, b3y = t1y - t3x;    // t1 - i t3
            float c1 = w.x, s1 = w.y;
            float c2 = c1 * c1 - s1 * s1, s2 = 2.f * c1 * s1;
            float c3 = c2 * c1 - s2 * s1, s3 = c2 * s1 + s2 * c1;
            int ob = (2 * n1h + h) * CRS + (p << 2);
            sA[swz(ob, 0)]     = make_float2(b0x, b0y);
            sA[swz(ob + 1, 0)] = make_float2(b1x * c1 - b1y * s1, b1x * s1 + b1y * c1);
            sA[swz(ob + 2, 0)] = make_float2(b2x * c2 - b2y * s2, b2x * s2 + b2y * c2);
            sA[swz(ob + 3, 0)] = make_float2(b3x * c3 - b3y * s3, b3x * s3 + b3y * c3);
        }
    }
    __syncthreads();
    // SKIP=1 (stage 0 fused), HALF=1 (only low half needed, n2 <= 62).
    float2* res = smem_fft4<1, 128, 16, CRS, 0, 0, 1, 1>(sA, sB, g_tw128);
    const float* ma = mix + (size_t)(2 * pr) * T_SIG;
    const float* mb = ma + T_SIG;
    float acc = 0.f;
    const float INVN = 1.0f / 131072.0f;
    #pragma unroll
    for (int l = 0; l < 8; ++l) {
        int idx = threadIdx.x + TPB * l;
        int n1l = idx & 15, n2 = idx >> 4;
        int n = n1_0 + n1l + (n2 << 10);
        if (n < T_SIG) {
            float2 v = res[swz(n1l * CRS + n2, 0)];
            acc += fabsf(v.x * INVN - ma[n]) + fabsf(v.y * INVN - mb[n]);
        }
    }
    float b = block_reduce(acc, scr);
    if (threadIdx.x == 0) atomicAdd(&g_acc[10], (double)b);
}

// ---------------------------------------------------------------- finalize

__global__ void finalize_kernel(float* out) {
    const double NT   = 4096000.0;                 // 64 * 64000
    const double CNT  = 64.0 * 513.0 * 251.0;
    const double MELC = 64.0 * 80.0 * 251.0;
    const double SEGC = 1024000.0;                 // 64 * 16000
    double dry_time = g_acc[3] / NT;
    double mag   = g_acc[0] / CNT;
    double phase = 1.0 - g_acc[1] / CNT;
    double freqL = mag + 0.1 * phase;
    double mel   = g_acc[2] / MELC;
    double total_dry = dry_time + 0.5 * freqL + 0.3 * mel;
    double rir_time = g_acc[4] / NT;
    double spars    = g_acc[5] / NT;
    double e0 = g_acc[6] / SEGC, e1 = g_acc[7] / SEGC;
    double e2 = g_acc[8] / SEGC, e3 = g_acc[9] / SEGC;
    double decay = fmax(0.0, e1 - 0.8 * e0) + fmax(0.0, e2 - 0.8 * e1)
                 + fmax(0.0, e3 - 0.8 * e2);
    double total_rir = rir_time + 0.1 * (spars + decay);
    double consist = g_acc[10] / NT;
    out[0] = (float)(3.0 * total_dry + total_rir + 0.2 * consist);
}

// ---------------------------------------------------------------- launch
// Graph fork-join: after init, three independent branches run concurrently —
// stft (s1), time_loss (s2), conv chain (capture stream) — joined via events
// before finalize.

extern "C" void kernel_launch(void* const* d_in, const int* in_sizes, int n_in,
                              void* d_out, int out_size) {
    const float* pd  = (const float*)d_in[0];   // pred_dry
    const float* pr  = (const float*)d_in[1];   // pred_rir
    const float* td  = (const float*)d_in[2];   // target_dry
    const float* tr  = (const float*)d_in[3];   // target_rir
    const float* mix = (const float*)d_in[4];   // mix
    float* out = (float*)d_out;

    init_kernel<<<4, TPB>>>();
    init2_kernel<<<1, 128>>>();

    cudaEventRecord(g_eF, 0);
    cudaStreamWaitEvent(g_s1, g_eF, 0);
    cudaStreamWaitEvent(g_s2, g_eF, 0);

    stft_loss_kernel<<<dim3(NPAIR, NSIG), TPB, 0, g_s1>>>(pd, td);
    time_loss_kernel<<<1024, TPB, 0, g_s2>>>((const float4*)pd, (const float4*)pr,
                                             (const float4*)td, (const float4*)tr);
    conv_fwdA<<<dim3(64, NSIG), TPB>>>(pd, pr);
    conv_prodrow_inv1<<<dim3(64, 32), TPB>>>();
    conv_inv2<<<dim3(64, 32), TPB>>>(mix);

    cudaEventRecord(g_eJ1, g_s1);
    cudaEventRecord(g_eJ2, g_s2);
    cudaStreamWaitEvent(0, g_eJ1, 0);
    cudaStreamWaitEvent(0, g_eJ2, 0);

    finalize_kernel<<<1, 1>>>(out);
}